// round 12
// baseline (speedup 1.0000x reference)
#include <cuda_runtime.h>
#include <cuda_bf16.h>
#include <math.h>
#include <stdint.h>

#define Bb   2048
#define NIi  30
#define Hh   2
#define Dd   2
#define HAE  128
#define SZv  1120
#define Lv   30
#define NTRI 528
#define NV   (Lv*HAE)   /* 3840 */

// ---------------- device scratch ----------------
__device__ float g_raw[Bb*SZv];
__device__ float g_xn [Bb*SZv];
__device__ float g_d1[Bb*HAE];
__device__ float g_dh1[Bb*HAE], g_dh2[Bb*HAE];
__device__ float g_accE[Bb*HAE];
__device__ float g_G1[HAE*HAE];
__device__ __nv_bfloat16 g_G1b[HAE*HAE];
__device__ __nv_bfloat16 g_Vb[NV*HAE];
__device__ __nv_bfloat16 g_d2b[Bb*HAE];
__device__ __nv_bfloat16 g_Mbf[(size_t)Bb*NV];
__device__ float g_scalarT[Dd*SZv*Hh];
__device__ float g_zTz[Lv*Lv], g_az[Lv*Lv];
__device__ float g_l2[SZv*Hh];
__device__ float g_scaled[SZv*Hh];
__device__ float g_selh1[2*64];
__device__ float g_buf[Hh*SZv];
__device__ double g_mse, g_jsum, g_comp;
__device__ int g_iu0[NTRI], g_iu1[NTRI];

__device__ __forceinline__ float sp_(float x){ return fmaxf(x,0.f) + log1pf(__expf(-fabsf(x))); }
__device__ __forceinline__ float sig_(float x){ return 1.f/(1.f+__expf(-x)); }

__device__ __forceinline__ float blk_reduce(float v, float* red, int t){
    red[t]=v; __syncthreads();
    for(int st=128;st>0;st>>=1){ if(t<st) red[t]+=red[t+st]; __syncthreads(); }
    float r=red[0]; __syncthreads();
    return r;
}
__device__ __forceinline__ float blk_reduce_max(float v, float* red, int t){
    red[t]=v; __syncthreads();
    for(int st=128;st>0;st>>=1){ if(t<st) red[t]=fmaxf(red[t],red[t+st]); __syncthreads(); }
    float r=red[0]; __syncthreads();
    return r;
}

// ================= HMMA bf16 GEMM (TM / JQ) ==========
#define HS 136
#define HMMA_SMEM (2*128*HS*2)

__device__ __forceinline__ void mma16816(float* c, const uint32_t* a,
                                         uint32_t b0, uint32_t b1){
    asm volatile(
        "mma.sync.aligned.m16n8k16.row.col.f32.bf16.bf16.f32 "
        "{%0,%1,%2,%3}, {%4,%5,%6,%7}, {%8,%9}, {%0,%1,%2,%3};"
        : "+f"(c[0]), "+f"(c[1]), "+f"(c[2]), "+f"(c[3])
        : "r"(a[0]), "r"(a[1]), "r"(a[2]), "r"(a[3]), "r"(b0), "r"(b1));
}
__device__ __forceinline__ void ldsm_x4(uint32_t* r, uint32_t addr){
    asm volatile("ldmatrix.sync.aligned.m8n8.x4.shared.b16 {%0,%1,%2,%3}, [%4];"
        : "=r"(r[0]), "=r"(r[1]), "=r"(r[2]), "=r"(r[3]) : "r"(addr));
}
__device__ __forceinline__ void ldsm_x2(uint32_t& r0, uint32_t& r1, uint32_t addr){
    asm volatile("ldmatrix.sync.aligned.m8n8.x2.shared.b16 {%0,%1}, [%2];"
        : "=r"(r0), "=r"(r1) : "r"(addr));
}

template<int JQ>
__global__ void __launch_bounds__(256)
hmma_gemm(){
    extern __shared__ __nv_bfloat16 dsm[];
    __nv_bfloat16* As = dsm;
    __nv_bfloat16* Bs = dsm + 128*HS;
    __shared__ float red[256];
    const int t = threadIdx.x, wid = t >> 5, lane = t & 31;
    const int g = lane >> 2, ti = lane & 3;
    const int m0 = blockIdx.x * 128;

    const __nv_bfloat16 *Ag, *Bg;
    if (JQ == 0){ Ag = g_d2b + (size_t)m0*HAE; Bg = g_Vb + (size_t)blockIdx.y*128*HAE; }
    else        { Ag = g_Mbf + (size_t)m0*HAE; Bg = g_G1b; }

    for (int i = t; i < 2048; i += 256){
        int row = i >> 4, col = (i & 15) * 8;
        *reinterpret_cast<uint4*>(&As[row*HS + col]) =
            *reinterpret_cast<const uint4*>(&Ag[(size_t)row*HAE + col]);
        *reinterpret_cast<uint4*>(&Bs[row*HS + col]) =
            *reinterpret_cast<const uint4*>(&Bg[(size_t)row*HAE + col]);
    }
    __syncthreads();

    const int wm = wid >> 1, wn = wid & 1;
    const int r0 = wm*32, c0 = wn*64;
    float C[2][8][4];
    #pragma unroll
    for (int mi = 0; mi < 2; mi++)
        #pragma unroll
        for (int ni = 0; ni < 8; ni++)
            #pragma unroll
            for (int q = 0; q < 4; q++) C[mi][ni][q] = 0.f;

    const uint32_t asu = (uint32_t)__cvta_generic_to_shared(As);
    const uint32_t bsu = (uint32_t)__cvta_generic_to_shared(Bs);
    const uint32_t aBase = asu + ((uint32_t)((r0 + (lane & 15))*HS + ((lane >> 4) << 3)) << 1);
    const uint32_t bBase = bsu + ((uint32_t)((c0 + (lane & 7))*HS + ((lane & 8) ? 8 : 0)) << 1);

    #pragma unroll
    for (int kk = 0; kk < 8; kk++){
        uint32_t Af[2][4];
        ldsm_x4(Af[0], aBase + kk*32);
        ldsm_x4(Af[1], aBase + 16*HS*2 + kk*32);
        #pragma unroll
        for (int ni = 0; ni < 8; ni++){
            uint32_t b0, b1;
            ldsm_x2(b0, b1, bBase + ni*(8*HS*2) + kk*32);
            mma16816(C[0][ni], Af[0], b0, b1);
            mma16816(C[1][ni], Af[1], b0, b1);
        }
    }

    if (JQ == 0){
        const int l = blockIdx.y;
        #pragma unroll
        for (int mi = 0; mi < 2; mi++){
            const int r = m0 + r0 + mi*16 + g;
            #pragma unroll
            for (int ni = 0; ni < 8; ni++){
                const int a = c0 + ni*8 + ti*2;
                float2 dA = *reinterpret_cast<const float2*>(&g_d1[(size_t)r*HAE + a]);
                float2 dB = *reinterpret_cast<const float2*>(&g_d1[(size_t)(r+8)*HAE + a]);
                *reinterpret_cast<__nv_bfloat162*>(&g_Mbf[(size_t)r*NV + l*128 + a]) =
                    __floats2bfloat162_rn(C[mi][ni][0]*dA.x, C[mi][ni][1]*dA.y);
                *reinterpret_cast<__nv_bfloat162*>(&g_Mbf[(size_t)(r+8)*NV + l*128 + a]) =
                    __floats2bfloat162_rn(C[mi][ni][2]*dB.x, C[mi][ni][3]*dB.y);
            }
        }
    } else {
        float loc = 0.f;
        #pragma unroll
        for (int mi = 0; mi < 2; mi++){
            const int rl = r0 + mi*16 + g;
            #pragma unroll
            for (int ni = 0; ni < 8; ni++){
                const int a = c0 + ni*8 + ti*2;
                __nv_bfloat162 mA = *reinterpret_cast<const __nv_bfloat162*>(&As[rl*HS + a]);
                __nv_bfloat162 mB = *reinterpret_cast<const __nv_bfloat162*>(&As[(rl+8)*HS + a]);
                loc += C[mi][ni][0]*__bfloat162float(mA.x)
                     + C[mi][ni][1]*__bfloat162float(mA.y)
                     + C[mi][ni][2]*__bfloat162float(mB.x)
                     + C[mi][ni][3]*__bfloat162float(mB.y);
            }
        }
        red[t] = loc; __syncthreads();
        for (int st = 128; st > 0; st >>= 1){ if (t < st) red[t] += red[t+st]; __syncthreads(); }
        if (t == 0) atomicAdd(&g_jsum, (double)red[0]);
    }
}

// ================= TF32 GEMM ==========
// MODE 1: mse accumulate; MODE 5: sp only; MODE 6: split-K atomicAdd
// MODE 8: enc2 mega-kernel — A-staging applies enc1 epilogue
//   (h1=sp(accE+pA), d1=sig -> g_d1), output epilogue computes h2e in smem,
//   d2b (bf16), then z = h2e@ew3^T + eb3, zstats atomics, dh1 = sp(z@dw1^T+db1).
#define TS 20

__device__ __forceinline__ uint32_t to_tf32(float x){
    uint32_t u;
    asm("cvt.rna.tf32.f32 %0, %1;" : "=r"(u) : "f"(x));
    return u;
}
__device__ __forceinline__ void mma1688_tf32(float* c, const uint32_t* a,
                                             uint32_t b0, uint32_t b1){
    asm volatile(
        "mma.sync.aligned.m16n8k8.row.col.f32.tf32.tf32.f32 "
        "{%0,%1,%2,%3}, {%4,%5,%6,%7}, {%8,%9}, {%0,%1,%2,%3};"
        : "+f"(c[0]), "+f"(c[1]), "+f"(c[2]), "+f"(c[3])
        : "r"(a[0]), "r"(a[1]), "r"(a[2]), "r"(a[3]), "r"(b0), "r"(b1));
}

template<int MODE, int PREC>
__global__ void __launch_bounds__(256)
tf32_gemm(const float* __restrict__ A, const float* __restrict__ Bm,
          int N, int K, int Kc,
          const float* __restrict__ bias, float* __restrict__ out0,
          const float* __restrict__ aux, int s_aux, double* accd,
          const float* __restrict__ pA,
          const float* __restrict__ pw3, const float* __restrict__ pb3,
          const float* __restrict__ pdw1, const float* __restrict__ pdb1){
    extern __shared__ float tsm[];
    float* AsH = tsm;
    float* BsH = tsm + 128*TS;
    float* AsL = tsm + 2*128*TS;
    float* BsL = tsm + 3*128*TS;
    __shared__ float red[256];
    const int t = threadIdx.x, wid = t >> 5, lane = t & 31;
    const int g = lane >> 2, ti = lane & 3;
    const int m0 = blockIdx.x * 128, n0 = blockIdx.y * 128;
    const int kBeg = blockIdx.z * Kc, kEnd = min(K, kBeg + Kc);
    const int wm = wid >> 1, wn = wid & 1;
    const int r0 = wm*32, c0 = wn*64;

    float C[2][8][4];
    #pragma unroll
    for (int mi = 0; mi < 2; mi++)
        #pragma unroll
        for (int ni = 0; ni < 8; ni++)
            #pragma unroll
            for (int q = 0; q < 4; q++) C[mi][ni][q] = 0.f;

    for (int k0 = kBeg; k0 < kEnd; k0 += 16){
        #pragma unroll
        for (int i = 0; i < 2; i++){
            int li = t + i*256;
            int row = li >> 2, c = (li & 3) * 4;
            float4 va = *reinterpret_cast<const float4*>(&A[(size_t)(m0+row)*K + k0 + c]);
            float4 vb = make_float4(0.f,0.f,0.f,0.f);
            if (n0 + row < N)
                vb = *reinterpret_cast<const float4*>(&Bm[(size_t)(n0+row)*K + k0 + c]);
            float av[4] = {va.x,va.y,va.z,va.w};
            float bv[4] = {vb.x,vb.y,vb.z,vb.w};
            if (MODE == 8){
                #pragma unroll
                for (int q = 0; q < 4; q++){
                    int col = k0 + c + q;
                    float v = av[q] + pA[col];
                    av[q] = sp_(v);
                    g_d1[(size_t)(m0+row)*HAE + col] = sig_(v);
                }
            }
            #pragma unroll
            for (int q = 0; q < 4; q++){
                uint32_t ah = to_tf32(av[q]);
                uint32_t bh = to_tf32(bv[q]);
                AsH[row*TS + c + q] = __uint_as_float(ah);
                BsH[row*TS + c + q] = __uint_as_float(bh);
                if (PREC){
                    AsL[row*TS + c + q] = __uint_as_float(to_tf32(av[q] - __uint_as_float(ah)));
                    BsL[row*TS + c + q] = __uint_as_float(to_tf32(bv[q] - __uint_as_float(bh)));
                }
            }
        }
        __syncthreads();
        #pragma unroll
        for (int kk = 0; kk < 16; kk += 8){
            uint32_t AfH[2][4], AfL[2][4];
            #pragma unroll
            for (int mi = 0; mi < 2; mi++){
                const int ao = (r0 + mi*16 + g)*TS + kk;
                AfH[mi][0] = __float_as_uint(AsH[ao + ti]);
                AfH[mi][1] = __float_as_uint(AsH[ao + 8*TS + ti]);
                AfH[mi][2] = __float_as_uint(AsH[ao + ti + 4]);
                AfH[mi][3] = __float_as_uint(AsH[ao + 8*TS + ti + 4]);
                if (PREC){
                    AfL[mi][0] = __float_as_uint(AsL[ao + ti]);
                    AfL[mi][1] = __float_as_uint(AsL[ao + 8*TS + ti]);
                    AfL[mi][2] = __float_as_uint(AsL[ao + ti + 4]);
                    AfL[mi][3] = __float_as_uint(AsL[ao + 8*TS + ti + 4]);
                }
            }
            #pragma unroll
            for (int ni = 0; ni < 8; ni++){
                const int bo = (c0 + ni*8 + g)*TS + kk;
                uint32_t bH0 = __float_as_uint(BsH[bo + ti]);
                uint32_t bH1 = __float_as_uint(BsH[bo + ti + 4]);
                mma1688_tf32(C[0][ni], AfH[0], bH0, bH1);
                mma1688_tf32(C[1][ni], AfH[1], bH0, bH1);
                if (PREC){
                    uint32_t bL0 = __float_as_uint(BsL[bo + ti]);
                    uint32_t bL1 = __float_as_uint(BsL[bo + ti + 4]);
                    mma1688_tf32(C[0][ni], AfL[0], bH0, bH1);
                    mma1688_tf32(C[1][ni], AfL[1], bH0, bH1);
                    mma1688_tf32(C[0][ni], AfH[0], bL0, bL1);
                    mma1688_tf32(C[1][ni], AfH[1], bL0, bL1);
                }
            }
        }
        __syncthreads();
    }

    if (MODE == 5){
        #pragma unroll
        for (int mi = 0; mi < 2; mi++){
            const int r = m0 + r0 + mi*16 + g;
            #pragma unroll
            for (int ni = 0; ni < 8; ni++){
                const int gn = n0 + c0 + ni*8 + 2*ti;
                if (gn < N){
                    float b0v = bias[gn], b1v = bias[gn+1];
                    size_t oA = (size_t)r*HAE + gn;
                    size_t oB = (size_t)(r+8)*HAE + gn;
                    out0[oA]   = sp_(C[mi][ni][0] + b0v);
                    out0[oA+1] = sp_(C[mi][ni][1] + b1v);
                    out0[oB]   = sp_(C[mi][ni][2] + b0v);
                    out0[oB+1] = sp_(C[mi][ni][3] + b1v);
                }
            }
        }
    } else if (MODE == 1){
        float loc = 0.f;
        #pragma unroll
        for (int mi = 0; mi < 2; mi++){
            const int r = m0 + r0 + mi*16 + g;
            #pragma unroll
            for (int ni = 0; ni < 8; ni++){
                const int gn = n0 + c0 + ni*8 + 2*ti;
                if (gn < N){
                    float b0v = bias[gn], b1v = bias[gn+1];
                    float d0 = aux[(size_t)r*s_aux + gn]       - (C[mi][ni][0] + b0v);
                    float d1 = aux[(size_t)r*s_aux + gn + 1]   - (C[mi][ni][1] + b1v);
                    float d2 = aux[(size_t)(r+8)*s_aux + gn]   - (C[mi][ni][2] + b0v);
                    float d3 = aux[(size_t)(r+8)*s_aux + gn+1] - (C[mi][ni][3] + b1v);
                    loc += d0*d0 + d1*d1 + d2*d2 + d3*d3;
                }
            }
        }
        red[t] = loc; __syncthreads();
        for (int st = 128; st > 0; st >>= 1){ if (t < st) red[t] += red[t+st]; __syncthreads(); }
        if (t == 0) atomicAdd(accd, (double)red[0]);
    } else if (MODE == 6){
        #pragma unroll
        for (int mi = 0; mi < 2; mi++){
            const int r = m0 + r0 + mi*16 + g;
            #pragma unroll
            for (int ni = 0; ni < 8; ni++){
                const int gn = n0 + c0 + ni*8 + 2*ti;
                if (gn < N){
                    atomicAdd(&out0[(size_t)r*HAE + gn],       C[mi][ni][0]);
                    atomicAdd(&out0[(size_t)r*HAE + gn + 1],   C[mi][ni][1]);
                    atomicAdd(&out0[(size_t)(r+8)*HAE + gn],   C[mi][ni][2]);
                    atomicAdd(&out0[(size_t)(r+8)*HAE + gn+1], C[mi][ni][3]);
                }
            }
        }
    } else if (MODE == 8){
        // h2e tile -> smem; d2b bf16 -> global
        float* hsm = tsm + 4*128*TS;          // [128][132]
        float* w3s = hsm + 128*132;           // [30][132]
        float* zsm = w3s + 30*132;            // [128][31]
        #pragma unroll
        for (int mi = 0; mi < 2; mi++){
            const int rl = r0 + mi*16 + g;
            #pragma unroll
            for (int ni = 0; ni < 8; ni++){
                const int gn = c0 + ni*8 + 2*ti;
                float b0v = bias[gn], b1v = bias[gn+1];
                float v00 = C[mi][ni][0] + b0v, v01 = C[mi][ni][1] + b1v;
                float v10 = C[mi][ni][2] + b0v, v11 = C[mi][ni][3] + b1v;
                hsm[rl*132 + gn]       = sp_(v00);
                hsm[rl*132 + gn + 1]   = sp_(v01);
                hsm[(rl+8)*132 + gn]   = sp_(v10);
                hsm[(rl+8)*132 + gn+1] = sp_(v11);
                *reinterpret_cast<__nv_bfloat162*>(&g_d2b[(size_t)(m0+rl)*HAE + gn]) =
                    __floats2bfloat162_rn(sig_(v00), sig_(v01));
                *reinterpret_cast<__nv_bfloat162*>(&g_d2b[(size_t)(m0+rl+8)*HAE + gn]) =
                    __floats2bfloat162_rn(sig_(v10), sig_(v11));
            }
        }
        for (int i = t; i < 30*HAE; i += 256) w3s[(i>>7)*132 + (i&127)] = pw3[i];
        __syncthreads();
        // z = h2e @ w3^T + b3
        for (int idx = t; idx < 128*30; idx += 256){
            int r = idx / 30, l = idx % 30;
            float s = pb3[l];
            #pragma unroll 8
            for (int k = 0; k < HAE; k++) s += hsm[r*132 + k]*w3s[l*132 + k];
            zsm[r*31 + l] = s;
        }
        __syncthreads();
        // zstats
        for (int idx = t; idx < 900; idx += 256){
            int i = idx / 30, j = idx % 30;
            float a = 0.f, ab = 0.f;
            #pragma unroll 8
            for (int r = 0; r < 128; r++){
                float zi = zsm[r*31 + i], zj = zsm[r*31 + j];
                a  += zi*zj;
                ab += fabsf(zi)*fabsf(zj);
            }
            atomicAdd(&g_zTz[idx], a);
            atomicAdd(&g_az[idx], ab);
        }
        // dec1: dh1 = sp(z @ dw1^T + db1)
        for (int idx = t; idx < 128*HAE; idx += 256){
            int r = idx >> 7, o = idx & 127;
            float s = pdb1[o];
            #pragma unroll
            for (int l = 0; l < 30; l++) s += zsm[r*31 + l]*pdw1[o*30 + l];
            g_dh1[(size_t)(m0+r)*HAE + o] = sp_(s);
        }
    }
}

#define SM1 (2*128*TS*4)
#define SM3 (4*128*TS*4)
#define SMZ ((4*128*TS + 128*132 + 30*132 + 128*31)*4)

// ---------------- setup: V + scalarT + init (one kernel) ----------------
__global__ void setup_k(const float* __restrict__ ew3, const float* __restrict__ ew2,
                        const float* __restrict__ ssc){
    int bid = blockIdx.x, t = threadIdx.x;
    if (bid < 1920){
        int idx = bid*256 + t;
        int bb = idx & 127;
        int n  = idx >> 7;
        int l  = n >> 7;
        int a  = n & 127;
        g_Vb[idx] = __float2bfloat16(ew3[l*HAE + bb] * ew2[bb*HAE + a]);
    } else if (bid < 1984){
        int t2 = (bid - 1920)*256 + t;
        if (t2 < SZv*Hh) g_l2[t2] = 0.5f;
        if (t2 < HAE*HAE) g_G1[t2] = 0.f;
        if (t2 == 0) g_comp = 0.0;
        if (t2 < NTRI){
            int rem = t2, i = 0;
            while (rem >= 32 - i){ rem -= 32 - i; i++; }
            g_iu0[t2] = i; g_iu1[t2] = i + rem;
        }
    } else {
        int gid = (bid - 1984)*256 + t;
        int w = gid >> 5, lane = gid & 31;
        if (w >= Dd*Hh*SZv) return;
        int i = w / (Hh*SZv);
        int rem = w % (Hh*SZv);
        int h = rem / SZv;
        int s = rem % SZv;
        const float* row = &ssc[(((size_t)(i*Hh+h)*SZv)+s)*SZv];
        float a = 0.f;
        for (int k = lane; k < SZv; k += 32) a += row[k];
        #pragma unroll
        for (int o = 16; o > 0; o >>= 1) a += __shfl_down_sync(0xffffffffu, a, o);
        if (lane == 0) g_scalarT[(i*SZv+s)*Hh + h] = a;
    }
}

__global__ void cvt_G1(){
    int t = blockIdx.x*256 + threadIdx.x;
    if (t < HAE*HAE) g_G1b[t] = __float2bfloat16(g_G1[t]);
}

// ---------------- raw / groupnorm (+ per-iter zeroing, + out-dot) --------
__global__ void __launch_bounds__(256)
build_raw_fused(const float* __restrict__ x, const float* __restrict__ ln_g,
                const float* __restrict__ ln_b, int do_out){
    __shared__ float nx[32];
    __shared__ float rw[SZv];
    __shared__ float sc[SZv*2];
    __shared__ float redA[256], redB[256];
    int b = blockIdx.x, t = threadIdx.x;
    int gid = b*256 + t;
    // per-iteration zeroing, spread across the grid
    if (gid < Bb*HAE) g_accE[gid] = 0.f;
    if (gid < Lv*Lv){ g_zTz[gid] = 0.f; g_az[gid] = 0.f; }
    if (gid == Bb*HAE){ g_mse = 0.0; g_jsum = 0.0; }

    float s0 = 0.f, s1 = 0.f;
    if (do_out){
        for (int i = t; i < SZv*2; i += 256) sc[i] = g_scaled[i];
        __syncthreads();
        const float* rwg = &g_raw[(size_t)b*SZv];
        for (int i = t; i < SZv; i += 256){
            float v = rwg[i];
            s0 += v*sc[i*2];
            s1 += v*sc[i*2+1];
        }
        s0 = blk_reduce(s0, redA, t);
        s1 = blk_reduce(s1, redA, t);
    }
    if (t < NIi) nx[t] = x[b*NIi + t];
    else if (t == NIi)   nx[t] = s0;
    else if (t == NIi+1) nx[t] = s1;
    __syncthreads();
    float s = 0.f, ss = 0.f;
    for (int idx = t; idx < SZv; idx += 256){
        float v;
        if (idx < NTRI){
            int i = g_iu0[idx], j = g_iu1[idx];
            v = (i == j) ? nx[i] : nx[i] + nx[j];
        } else if (idx < 2*NTRI){
            int k = idx - NTRI;
            v = nx[g_iu0[k]] * nx[g_iu1[k]];
        } else if (idx < 2*NTRI + 32){
            v = sinf(nx[idx - 2*NTRI]);
        } else {
            v = cosf(nx[idx - 2*NTRI - 32]);
        }
        rw[idx] = v; s += v; ss += v*v;
    }
    redA[t] = s; redB[t] = ss; __syncthreads();
    for (int st = 128; st > 0; st >>= 1){
        if (t < st){ redA[t] += redA[t+st]; redB[t] += redB[t+st]; }
        __syncthreads();
    }
    float mean = redA[0] / SZv;
    float var  = redB[0] / SZv - mean*mean;
    float rstd = rsqrtf(var + 1e-5f);
    for (int idx = t; idx < SZv; idx += 256){
        float v = rw[idx];
        g_raw[(size_t)b*SZv + idx] = v;
        g_xn [(size_t)b*SZv + idx] = (v - mean)*rstd*ln_g[idx] + ln_b[idx];
    }
}

// ---------------- selection chain, phase A (1 block) --------------------
__global__ void __launch_bounds__(256)
sel_A(const float* __restrict__ qw, const float* __restrict__ qb,
      const float* __restrict__ sq,
      const float* __restrict__ sl1, const float* __restrict__ sg1,
      const float* __restrict__ sb1, int iter){
    __shared__ float gsa[900], lsa[900];
    __shared__ float sel[2][30], h1s[2][64];
    __shared__ float sc8[8];
    int t = threadIdx.x;
    qw  += iter*900;  qb  += iter*30;   sq  += iter*60;
    sl1 += iter*2*64*30; sg1 += iter*128; sb1 += iter*128;
    for (int i = t; i < 900; i += 256) gsa[i] = g_zTz[i] / fmaxf(g_az[i], 1e-5f);
    __syncthreads();
    for (int idx = t; idx < 900; idx += 256){
        int i = idx / 30, j = idx % 30;
        float s = qb[j];
        #pragma unroll
        for (int k = 0; k < 30; k++) s += gsa[i*30+k]*qw[j*30+k];
        lsa[idx] = s;
    }
    __syncthreads();
    if (t < 60){
        int h = t / 30, i = t % 30;
        float s = 0.f;
        #pragma unroll
        for (int j = 0; j < 30; j++) s += lsa[i*30+j]*sq[h*30+j];
        sel[h][i] = s;
    }
    __syncthreads();
    if (t < 128){
        int h = t >> 6, o = t & 63;
        float s = 0.f;
        #pragma unroll
        for (int l = 0; l < 30; l++) s += sl1[(h*64+o)*30+l]*sel[h][l];
        h1s[h][o] = s;
    }
    __syncthreads();
    if (t < 2){
        float m = 0.f;
        for (int o = 0; o < 64; o++) m += h1s[t][o];
        m *= (1.f/64.f);
        float v = 0.f;
        for (int o = 0; o < 64; o++){ float d = h1s[t][o]-m; v += d*d; }
        v *= (1.f/64.f);
        sc8[t*2] = m; sc8[t*2+1] = rsqrtf(v + 1e-5f);
    }
    __syncthreads();
    if (t < 128){
        int h = t >> 6, o = t & 63;
        g_selh1[t] = sp_((h1s[h][o]-sc8[h*2])*sc8[h*2+1]*sg1[h*64+o] + sb1[h*64+o]);
    }
}

// ---------------- phase B ----------------
__global__ void __launch_bounds__(256)
sel_B(const float* __restrict__ sl2, int iter){
    __shared__ float h1s[128];
    int t = threadIdx.x;
    if (t < 128) h1s[t] = g_selh1[t];
    __syncthreads();
    int w = blockIdx.x*8 + (t >> 5);
    int lane = t & 31;
    if (w >= Hh*SZv) return;
    int h = w / SZv, s = w % SZv;
    const float* wp = &sl2[((size_t)iter*Hh*SZv + w)*64];
    float a = wp[lane]*h1s[h*64+lane] + wp[lane+32]*h1s[h*64+lane+32];
    #pragma unroll
    for (int o = 16; o > 0; o >>= 1) a += __shfl_down_sync(0xffffffffu, a, o);
    if (lane == 0) g_buf[h*SZv + s] = a;
}

// ---------------- phase C (1 block) ----------------
__global__ void __launch_bounds__(256)
sel_C(const float* __restrict__ sg2, const float* __restrict__ sb2,
      const float* __restrict__ son, int iter){
    __shared__ float buf[2][SZv];
    __shared__ float red[256];
    int t = threadIdx.x;
    sg2 += iter*2*SZv; sb2 += iter*2*SZv;
    son += iter*2*2*SZv;
    for (int i = t; i < 2*SZv; i += 256) buf[i/SZv][i%SZv] = g_buf[i];
    __syncthreads();
    for (int h = 0; h < 2; h++){
        float s = 0.f, ss = 0.f;
        for (int i = t; i < SZv; i += 256){ float v = buf[h][i]; s += v; ss += v*v; }
        s  = blk_reduce(s, red, t);
        ss = blk_reduce(ss, red, t);
        float mean = s*(1.f/SZv);
        float var  = ss*(1.f/SZv) - mean*mean;
        float rstd = rsqrtf(var + 1e-5f);
        float mx = -1e30f;
        for (int i = t; i < SZv; i += 256){
            float v = (buf[h][i]-mean)*rstd*sg2[h*SZv+i] + sb2[h*SZv+i];
            buf[h][i] = v;
            mx = fmaxf(mx, v);
        }
        mx = blk_reduce_max(mx, red, t);
        float se = 0.f;
        for (int i = t; i < SZv; i += 256){
            float e = expf(buf[h][i]-mx);
            buf[h][i] = e;
            se += e;
        }
        se = blk_reduce(se, red, t);
        float inv = 1.f/se;
        for (int i = t; i < SZv; i += 256) buf[h][i] *= inv;
        __syncthreads();
    }
    float d0 = 0.f, d1 = 0.f;
    for (int s = t; s < SZv; s += 256){
        float il = g_l2[s*2]*g_l2[s*2+1];
        d0 += son[s]*il + son[SZv+s]*buf[0][s];
        d1 += son[2*SZv+s]*il + son[2*SZv+SZv+s]*buf[1][s];
    }
    d0 = blk_reduce(d0, red, t);
    d1 = blk_reduce(d1, red, t);
    float on0 = sig_(d0), on1 = sig_(d1);
    float e00 = 0.f, e01 = 0.f, e10 = 0.f, e11 = 0.f;
    for (int s = t; s < SZv; s += 256){
        float o0 = on0*buf[0][s], o1 = on1*buf[1][s];
        float sc0 = o0*g_scalarT[(iter*SZv+s)*2+0];
        float sc1 = o1*g_scalarT[(iter*SZv+s)*2+1];
        if (fabsf(sc0) <= 1e-14f) sc0 = 1e-14f;
        if (fabsf(sc1) <= 1e-14f) sc1 = 1e-14f;
        g_scaled[s*2]   = sc0;
        g_scaled[s*2+1] = sc1;
        float l20 = fmaxf(o0, 1e-14f), l21 = fmaxf(o1, 1e-14f);
        g_l2[s*2] = l20; g_l2[s*2+1] = l21;
        float lg0 = logf(l20 + 1e-5f), lg1 = logf(l21 + 1e-5f);
        e00 += l20*lg0; e01 += l20*lg1;
        e10 += l21*lg0; e11 += l21*lg1;
    }
    e00 = blk_reduce(e00, red, t);
    e01 = blk_reduce(e01, red, t);
    e10 = blk_reduce(e10, red, t);
    e11 = blk_reduce(e11, red, t);
    if (t == 0){
        float g00 = -e00, g01 = -e01, g10 = -e10, g11 = -e11;
        float g = 0.01f*0.5f*(g00+g11) - 0.25f*(g01+g10);
        double cst = g_mse/((double)Bb*SZv) + g_jsum/((double)Lv*(double)Bb*(double)SZv);
        g_comp += (double)g + cst;
    }
}

// ---------------- final: out[b] = dot(raw_b, sc0+sc1); out[Bb] = comp ---
__global__ void __launch_bounds__(256)
finalize_dot(float* __restrict__ out){
    __shared__ float sc[SZv];
    int t = threadIdx.x;
    for (int i = t; i < SZv; i += 256) sc[i] = g_scaled[i*2] + g_scaled[i*2+1];
    __syncthreads();
    int warp = t >> 5, lane = t & 31;
    int b = blockIdx.x*8 + warp;
    const float* rw = &g_raw[(size_t)b*SZv];
    float s = 0.f;
    for (int i = lane; i < SZv; i += 32) s += rw[i]*sc[i];
    #pragma unroll
    for (int o = 16; o > 0; o >>= 1) s += __shfl_down_sync(0xffffffffu, s, o);
    if (lane == 0) out[b] = s;
    if (blockIdx.x == 0 && t == 0) out[Bb] = (float)g_comp;
}

// ---------------- host ----------------
extern "C" void kernel_launch(void* const* d_in, const int* in_sizes, int n_in,
                              void* d_out, int out_size) {
    const float* x    = (const float*)d_in[0];
    const float* ln_g = (const float*)d_in[1];
    const float* ln_b = (const float*)d_in[2];
    const float* ew1  = (const float*)d_in[3];
    const float* eb1  = (const float*)d_in[4];
    const float* ew2  = (const float*)d_in[5];
    const float* eb2  = (const float*)d_in[6];
    const float* ew3  = (const float*)d_in[7];
    const float* eb3  = (const float*)d_in[8];
    const float* dw1  = (const float*)d_in[9];
    const float* db1  = (const float*)d_in[10];
    const float* dw2  = (const float*)d_in[11];
    const float* db2  = (const float*)d_in[12];
    const float* dw3  = (const float*)d_in[13];
    const float* db3  = (const float*)d_in[14];
    const float* qw   = (const float*)d_in[15];
    const float* qb   = (const float*)d_in[16];
    const float* sq   = (const float*)d_in[17];
    const float* sl1  = (const float*)d_in[18];
    const float* sg1  = (const float*)d_in[19];
    const float* sb1  = (const float*)d_in[20];
    const float* sl2  = (const float*)d_in[21];
    const float* sg2  = (const float*)d_in[22];
    const float* sb2  = (const float*)d_in[23];
    const float* ssc  = (const float*)d_in[24];
    const float* son  = (const float*)d_in[25];
    float* out = (float*)d_out;

    float *pXn, *pDh1, *pDh2, *pG1, *pAccE;
    double *pMse;
    cudaGetSymbolAddress((void**)&pXn,  g_xn);
    cudaGetSymbolAddress((void**)&pDh1, g_dh1);
    cudaGetSymbolAddress((void**)&pDh2, g_dh2);
    cudaGetSymbolAddress((void**)&pG1,  g_G1);
    cudaGetSymbolAddress((void**)&pAccE,g_accE);
    cudaGetSymbolAddress((void**)&pMse, g_mse);

    cudaFuncSetAttribute(hmma_gemm<0>, cudaFuncAttributeMaxDynamicSharedMemorySize, HMMA_SMEM);
    cudaFuncSetAttribute(hmma_gemm<1>, cudaFuncAttributeMaxDynamicSharedMemorySize, HMMA_SMEM);
    cudaFuncSetAttribute((const void*)tf32_gemm<8,1>, cudaFuncAttributeMaxDynamicSharedMemorySize, SMZ);

    // setup: V (1920 blocks) + init (64) + scalarT (560)
    setup_k<<<2544,256>>>(ew3, ew2, ssc);
    // G1 = W1 W1^T, tf32 1x split-K
    tf32_gemm<6,0><<<dim3(1,1,35),256,SM1>>>(ew1, ew1, HAE, SZv, 32,
        nullptr, pG1, nullptr, 0, nullptr, nullptr, nullptr, nullptr, nullptr, nullptr);
    cvt_G1<<<64,256>>>();

    for (int iter = 0; iter < Dd; iter++){
        build_raw_fused<<<Bb,256>>>(x, ln_g, ln_b, iter > 0 ? 1 : 0);
        // enc1: xn @ ew1^T -> accE (split-K atomics)
        tf32_gemm<6,1><<<dim3(16,1,7),256,SM3>>>(pXn, ew1, HAE, SZv, 160,
            nullptr, pAccE, nullptr, 0, nullptr, nullptr, nullptr, nullptr, nullptr, nullptr);
        // enc2 mega: A-staging = enc1 epi (h1,d1); epilogue = h2e smem + d2b + z + zstats + dec1
        tf32_gemm<8,1><<<dim3(16,1,1),256,SMZ>>>(pAccE, ew2, HAE, HAE, HAE,
            eb2, nullptr, nullptr, 0, nullptr, eb1, ew3, eb3, dw1, db1);
        // dec2: dh1 @ dw2^T -> dh2 (sp)
        tf32_gemm<5,1><<<dim3(16,1,1),256,SM3>>>(pDh1, dw2, HAE, HAE, HAE,
            db2, pDh2, nullptr, 0, nullptr, nullptr, nullptr, nullptr, nullptr, nullptr);
        // dec3 + fused MSE
        tf32_gemm<1,1><<<dim3(16,9,1),256,SM3>>>(pDh2, dw3, SZv, HAE, HAE,
            db3, nullptr, pXn, SZv, pMse, nullptr, nullptr, nullptr, nullptr, nullptr);
        // TM / JQ (HMMA bf16)
        hmma_gemm<0><<<dim3(16,30), 256, HMMA_SMEM>>>();
        hmma_gemm<1><<<dim3(480,1), 256, HMMA_SMEM>>>();
        // selection chain
        sel_A<<<1,256>>>(qw, qb, sq, sl1, sg1, sb1, iter);
        sel_B<<<(Hh*SZv+7)/8,256>>>(sl2, iter);
        sel_C<<<1,256>>>(sg2, sb2, son, iter);
    }
    finalize_dot<<<Bb/8,256>>>(out);
}

// round 13
// speedup vs baseline: 1.0967x; 1.0967x over previous
#include <cuda_runtime.h>
#include <cuda_bf16.h>
#include <math.h>
#include <stdint.h>

#define Bb   2048
#define NIi  30
#define Hh   2
#define Dd   2
#define HAE  128
#define SZv  1120
#define Lv   30
#define NTRI 528
#define NV   (Lv*HAE)   /* 3840 */

// ---------------- device scratch ----------------
__device__ float g_raw[Bb*SZv];
__device__ float g_xn [Bb*SZv];
__device__ float g_d1[Bb*HAE];
__device__ float g_h2e[Bb*HAE];
__device__ float g_dh1[Bb*HAE], g_dh2[Bb*HAE];
__device__ float g_accE[Bb*HAE];
__device__ float g_G1[HAE*HAE];
__device__ __nv_bfloat16 g_G1b[HAE*HAE];
__device__ __nv_bfloat16 g_Vb[NV*HAE];
__device__ __nv_bfloat16 g_d2b[Bb*HAE];
__device__ __nv_bfloat16 g_Mbf[(size_t)Bb*NV];
__device__ float g_scalarT[Dd*SZv*Hh];
__device__ float g_zTz[Lv*Lv], g_az[Lv*Lv];
__device__ float g_l2[SZv*Hh];
__device__ float g_scaled[SZv*Hh];
__device__ float g_selh1[2*64];
__device__ float g_buf[Hh*SZv];
__device__ double g_mse, g_jsum, g_comp;
__device__ int g_iu0[NTRI], g_iu1[NTRI];

__device__ __forceinline__ float sp_(float x){ return fmaxf(x,0.f) + log1pf(__expf(-fabsf(x))); }
__device__ __forceinline__ float sig_(float x){ return 1.f/(1.f+__expf(-x)); }

__device__ __forceinline__ float blk_reduce(float v, float* red, int t){
    red[t]=v; __syncthreads();
    for(int st=128;st>0;st>>=1){ if(t<st) red[t]+=red[t+st]; __syncthreads(); }
    float r=red[0]; __syncthreads();
    return r;
}
__device__ __forceinline__ float blk_reduce_max(float v, float* red, int t){
    red[t]=v; __syncthreads();
    for(int st=128;st>0;st>>=1){ if(t<st) red[t]=fmaxf(red[t],red[t+st]); __syncthreads(); }
    float r=red[0]; __syncthreads();
    return r;
}

// ================= HMMA bf16 GEMM (TM / JQ) ==========
#define HS 136
#define HMMA_SMEM (2*128*HS*2)

__device__ __forceinline__ void mma16816(float* c, const uint32_t* a,
                                         uint32_t b0, uint32_t b1){
    asm volatile(
        "mma.sync.aligned.m16n8k16.row.col.f32.bf16.bf16.f32 "
        "{%0,%1,%2,%3}, {%4,%5,%6,%7}, {%8,%9}, {%0,%1,%2,%3};"
        : "+f"(c[0]), "+f"(c[1]), "+f"(c[2]), "+f"(c[3])
        : "r"(a[0]), "r"(a[1]), "r"(a[2]), "r"(a[3]), "r"(b0), "r"(b1));
}
__device__ __forceinline__ void ldsm_x4(uint32_t* r, uint32_t addr){
    asm volatile("ldmatrix.sync.aligned.m8n8.x4.shared.b16 {%0,%1,%2,%3}, [%4];"
        : "=r"(r[0]), "=r"(r[1]), "=r"(r[2]), "=r"(r[3]) : "r"(addr));
}
__device__ __forceinline__ void ldsm_x2(uint32_t& r0, uint32_t& r1, uint32_t addr){
    asm volatile("ldmatrix.sync.aligned.m8n8.x2.shared.b16 {%0,%1}, [%2];"
        : "=r"(r0), "=r"(r1) : "r"(addr));
}

template<int JQ>
__global__ void __launch_bounds__(256)
hmma_gemm(){
    extern __shared__ __nv_bfloat16 dsm[];
    __nv_bfloat16* As = dsm;
    __nv_bfloat16* Bs = dsm + 128*HS;
    __shared__ float red[256];
    const int t = threadIdx.x, wid = t >> 5, lane = t & 31;
    const int g = lane >> 2, ti = lane & 3;
    const int m0 = blockIdx.x * 128;

    const __nv_bfloat16 *Ag, *Bg;
    if (JQ == 0){ Ag = g_d2b + (size_t)m0*HAE; Bg = g_Vb + (size_t)blockIdx.y*128*HAE; }
    else        { Ag = g_Mbf + (size_t)m0*HAE; Bg = g_G1b; }

    for (int i = t; i < 2048; i += 256){
        int row = i >> 4, col = (i & 15) * 8;
        *reinterpret_cast<uint4*>(&As[row*HS + col]) =
            *reinterpret_cast<const uint4*>(&Ag[(size_t)row*HAE + col]);
        *reinterpret_cast<uint4*>(&Bs[row*HS + col]) =
            *reinterpret_cast<const uint4*>(&Bg[(size_t)row*HAE + col]);
    }
    __syncthreads();

    const int wm = wid >> 1, wn = wid & 1;
    const int r0 = wm*32, c0 = wn*64;
    float C[2][8][4];
    #pragma unroll
    for (int mi = 0; mi < 2; mi++)
        #pragma unroll
        for (int ni = 0; ni < 8; ni++)
            #pragma unroll
            for (int q = 0; q < 4; q++) C[mi][ni][q] = 0.f;

    const uint32_t asu = (uint32_t)__cvta_generic_to_shared(As);
    const uint32_t bsu = (uint32_t)__cvta_generic_to_shared(Bs);
    const uint32_t aBase = asu + ((uint32_t)((r0 + (lane & 15))*HS + ((lane >> 4) << 3)) << 1);
    const uint32_t bBase = bsu + ((uint32_t)((c0 + (lane & 7))*HS + ((lane & 8) ? 8 : 0)) << 1);

    #pragma unroll
    for (int kk = 0; kk < 8; kk++){
        uint32_t Af[2][4];
        ldsm_x4(Af[0], aBase + kk*32);
        ldsm_x4(Af[1], aBase + 16*HS*2 + kk*32);
        #pragma unroll
        for (int ni = 0; ni < 8; ni++){
            uint32_t b0, b1;
            ldsm_x2(b0, b1, bBase + ni*(8*HS*2) + kk*32);
            mma16816(C[0][ni], Af[0], b0, b1);
            mma16816(C[1][ni], Af[1], b0, b1);
        }
    }

    if (JQ == 0){
        const int l = blockIdx.y;
        #pragma unroll
        for (int mi = 0; mi < 2; mi++){
            const int r = m0 + r0 + mi*16 + g;
            #pragma unroll
            for (int ni = 0; ni < 8; ni++){
                const int a = c0 + ni*8 + ti*2;
                float2 dA = *reinterpret_cast<const float2*>(&g_d1[(size_t)r*HAE + a]);
                float2 dB = *reinterpret_cast<const float2*>(&g_d1[(size_t)(r+8)*HAE + a]);
                *reinterpret_cast<__nv_bfloat162*>(&g_Mbf[(size_t)r*NV + l*128 + a]) =
                    __floats2bfloat162_rn(C[mi][ni][0]*dA.x, C[mi][ni][1]*dA.y);
                *reinterpret_cast<__nv_bfloat162*>(&g_Mbf[(size_t)(r+8)*NV + l*128 + a]) =
                    __floats2bfloat162_rn(C[mi][ni][2]*dB.x, C[mi][ni][3]*dB.y);
            }
        }
    } else {
        float loc = 0.f;
        #pragma unroll
        for (int mi = 0; mi < 2; mi++){
            const int rl = r0 + mi*16 + g;
            #pragma unroll
            for (int ni = 0; ni < 8; ni++){
                const int a = c0 + ni*8 + ti*2;
                __nv_bfloat162 mA = *reinterpret_cast<const __nv_bfloat162*>(&As[rl*HS + a]);
                __nv_bfloat162 mB = *reinterpret_cast<const __nv_bfloat162*>(&As[(rl+8)*HS + a]);
                loc += C[mi][ni][0]*__bfloat162float(mA.x)
                     + C[mi][ni][1]*__bfloat162float(mA.y)
                     + C[mi][ni][2]*__bfloat162float(mB.x)
                     + C[mi][ni][3]*__bfloat162float(mB.y);
            }
        }
        red[t] = loc; __syncthreads();
        for (int st = 128; st > 0; st >>= 1){ if (t < st) red[t] += red[t+st]; __syncthreads(); }
        if (t == 0) atomicAdd(&g_jsum, (double)red[0]);
    }
}

// ================= TF32 GEMM ==========
// MODE 1: mse accumulate; MODE 5: sp only; MODE 6: split-K atomicAdd
// MODE 7: enc2 — A-staging applies enc1 epilogue (h1=sp(accE+pA) staged,
//         d1=sig -> g_d1); epilogue writes h2e=sp (f32) + d2b=sig (bf16).
#define TS 20

__device__ __forceinline__ uint32_t to_tf32(float x){
    uint32_t u;
    asm("cvt.rna.tf32.f32 %0, %1;" : "=r"(u) : "f"(x));
    return u;
}
__device__ __forceinline__ void mma1688_tf32(float* c, const uint32_t* a,
                                             uint32_t b0, uint32_t b1){
    asm volatile(
        "mma.sync.aligned.m16n8k8.row.col.f32.tf32.tf32.f32 "
        "{%0,%1,%2,%3}, {%4,%5,%6,%7}, {%8,%9}, {%0,%1,%2,%3};"
        : "+f"(c[0]), "+f"(c[1]), "+f"(c[2]), "+f"(c[3])
        : "r"(a[0]), "r"(a[1]), "r"(a[2]), "r"(a[3]), "r"(b0), "r"(b1));
}

template<int MODE, int PREC>
__global__ void __launch_bounds__(256)
tf32_gemm(const float* __restrict__ A, const float* __restrict__ Bm,
          int N, int K, int Kc,
          const float* __restrict__ bias, float* __restrict__ out0,
          const float* __restrict__ aux, int s_aux, double* accd,
          const float* __restrict__ pA){
    extern __shared__ float tsm[];
    float* AsH = tsm;
    float* BsH = tsm + 128*TS;
    float* AsL = tsm + 2*128*TS;
    float* BsL = tsm + 3*128*TS;
    __shared__ float red[256];
    const int t = threadIdx.x, wid = t >> 5, lane = t & 31;
    const int g = lane >> 2, ti = lane & 3;
    const int m0 = blockIdx.x * 128, n0 = blockIdx.y * 128;
    const int kBeg = blockIdx.z * Kc, kEnd = min(K, kBeg + Kc);
    const int wm = wid >> 1, wn = wid & 1;
    const int r0 = wm*32, c0 = wn*64;

    float C[2][8][4];
    #pragma unroll
    for (int mi = 0; mi < 2; mi++)
        #pragma unroll
        for (int ni = 0; ni < 8; ni++)
            #pragma unroll
            for (int q = 0; q < 4; q++) C[mi][ni][q] = 0.f;

    for (int k0 = kBeg; k0 < kEnd; k0 += 16){
        #pragma unroll
        for (int i = 0; i < 2; i++){
            int li = t + i*256;
            int row = li >> 2, c = (li & 3) * 4;
            float4 va = *reinterpret_cast<const float4*>(&A[(size_t)(m0+row)*K + k0 + c]);
            float4 vb = make_float4(0.f,0.f,0.f,0.f);
            if (n0 + row < N)
                vb = *reinterpret_cast<const float4*>(&Bm[(size_t)(n0+row)*K + k0 + c]);
            float av[4] = {va.x,va.y,va.z,va.w};
            float bv[4] = {vb.x,vb.y,vb.z,vb.w};
            if (MODE == 7){
                #pragma unroll
                for (int q = 0; q < 4; q++){
                    int col = k0 + c + q;
                    float v = av[q] + pA[col];
                    av[q] = sp_(v);
                    g_d1[(size_t)(m0+row)*HAE + col] = sig_(v);
                }
            }
            #pragma unroll
            for (int q = 0; q < 4; q++){
                uint32_t ah = to_tf32(av[q]);
                uint32_t bh = to_tf32(bv[q]);
                AsH[row*TS + c + q] = __uint_as_float(ah);
                BsH[row*TS + c + q] = __uint_as_float(bh);
                if (PREC){
                    AsL[row*TS + c + q] = __uint_as_float(to_tf32(av[q] - __uint_as_float(ah)));
                    BsL[row*TS + c + q] = __uint_as_float(to_tf32(bv[q] - __uint_as_float(bh)));
                }
            }
        }
        __syncthreads();
        #pragma unroll
        for (int kk = 0; kk < 16; kk += 8){
            uint32_t AfH[2][4], AfL[2][4];
            #pragma unroll
            for (int mi = 0; mi < 2; mi++){
                const int ao = (r0 + mi*16 + g)*TS + kk;
                AfH[mi][0] = __float_as_uint(AsH[ao + ti]);
                AfH[mi][1] = __float_as_uint(AsH[ao + 8*TS + ti]);
                AfH[mi][2] = __float_as_uint(AsH[ao + ti + 4]);
                AfH[mi][3] = __float_as_uint(AsH[ao + 8*TS + ti + 4]);
                if (PREC){
                    AfL[mi][0] = __float_as_uint(AsL[ao + ti]);
                    AfL[mi][1] = __float_as_uint(AsL[ao + 8*TS + ti]);
                    AfL[mi][2] = __float_as_uint(AsL[ao + ti + 4]);
                    AfL[mi][3] = __float_as_uint(AsL[ao + 8*TS + ti + 4]);
                }
            }
            #pragma unroll
            for (int ni = 0; ni < 8; ni++){
                const int bo = (c0 + ni*8 + g)*TS + kk;
                uint32_t bH0 = __float_as_uint(BsH[bo + ti]);
                uint32_t bH1 = __float_as_uint(BsH[bo + ti + 4]);
                mma1688_tf32(C[0][ni], AfH[0], bH0, bH1);
                mma1688_tf32(C[1][ni], AfH[1], bH0, bH1);
                if (PREC){
                    uint32_t bL0 = __float_as_uint(BsL[bo + ti]);
                    uint32_t bL1 = __float_as_uint(BsL[bo + ti + 4]);
                    mma1688_tf32(C[0][ni], AfL[0], bH0, bH1);
                    mma1688_tf32(C[1][ni], AfL[1], bH0, bH1);
                    mma1688_tf32(C[0][ni], AfH[0], bL0, bL1);
                    mma1688_tf32(C[1][ni], AfH[1], bL0, bL1);
                }
            }
        }
        __syncthreads();
    }

    if (MODE == 5){
        #pragma unroll
        for (int mi = 0; mi < 2; mi++){
            const int r = m0 + r0 + mi*16 + g;
            #pragma unroll
            for (int ni = 0; ni < 8; ni++){
                const int gn = n0 + c0 + ni*8 + 2*ti;
                if (gn < N){
                    float b0v = bias[gn], b1v = bias[gn+1];
                    size_t oA = (size_t)r*HAE + gn;
                    size_t oB = (size_t)(r+8)*HAE + gn;
                    out0[oA]   = sp_(C[mi][ni][0] + b0v);
                    out0[oA+1] = sp_(C[mi][ni][1] + b1v);
                    out0[oB]   = sp_(C[mi][ni][2] + b0v);
                    out0[oB+1] = sp_(C[mi][ni][3] + b1v);
                }
            }
        }
    } else if (MODE == 7){
        #pragma unroll
        for (int mi = 0; mi < 2; mi++){
            const int r = m0 + r0 + mi*16 + g;
            #pragma unroll
            for (int ni = 0; ni < 8; ni++){
                const int gn = c0 + ni*8 + 2*ti;
                float b0v = bias[gn], b1v = bias[gn+1];
                float v00 = C[mi][ni][0] + b0v, v01 = C[mi][ni][1] + b1v;
                float v10 = C[mi][ni][2] + b0v, v11 = C[mi][ni][3] + b1v;
                size_t oA = (size_t)r*HAE + gn;
                size_t oB = (size_t)(r+8)*HAE + gn;
                out0[oA]   = sp_(v00); out0[oA+1] = sp_(v01);
                out0[oB]   = sp_(v10); out0[oB+1] = sp_(v11);
                *reinterpret_cast<__nv_bfloat162*>(&g_d2b[oA]) =
                    __floats2bfloat162_rn(sig_(v00), sig_(v01));
                *reinterpret_cast<__nv_bfloat162*>(&g_d2b[oB]) =
                    __floats2bfloat162_rn(sig_(v10), sig_(v11));
            }
        }
    } else if (MODE == 1){
        float loc = 0.f;
        #pragma unroll
        for (int mi = 0; mi < 2; mi++){
            const int r = m0 + r0 + mi*16 + g;
            #pragma unroll
            for (int ni = 0; ni < 8; ni++){
                const int gn = n0 + c0 + ni*8 + 2*ti;
                if (gn < N){
                    float b0v = bias[gn], b1v = bias[gn+1];
                    float d0 = aux[(size_t)r*s_aux + gn]       - (C[mi][ni][0] + b0v);
                    float d1 = aux[(size_t)r*s_aux + gn + 1]   - (C[mi][ni][1] + b1v);
                    float d2 = aux[(size_t)(r+8)*s_aux + gn]   - (C[mi][ni][2] + b0v);
                    float d3 = aux[(size_t)(r+8)*s_aux + gn+1] - (C[mi][ni][3] + b1v);
                    loc += d0*d0 + d1*d1 + d2*d2 + d3*d3;
                }
            }
        }
        red[t] = loc; __syncthreads();
        for (int st = 128; st > 0; st >>= 1){ if (t < st) red[t] += red[t+st]; __syncthreads(); }
        if (t == 0) atomicAdd(accd, (double)red[0]);
    } else { // MODE 6
        #pragma unroll
        for (int mi = 0; mi < 2; mi++){
            const int r = m0 + r0 + mi*16 + g;
            #pragma unroll
            for (int ni = 0; ni < 8; ni++){
                const int gn = n0 + c0 + ni*8 + 2*ti;
                if (gn < N){
                    atomicAdd(&out0[(size_t)r*HAE + gn],       C[mi][ni][0]);
                    atomicAdd(&out0[(size_t)r*HAE + gn + 1],   C[mi][ni][1]);
                    atomicAdd(&out0[(size_t)(r+8)*HAE + gn],   C[mi][ni][2]);
                    atomicAdd(&out0[(size_t)(r+8)*HAE + gn+1], C[mi][ni][3]);
                }
            }
        }
    }
}

#define SM1 (2*128*TS*4)
#define SM3 (4*128*TS*4)

// ---------------- setup: V + scalarT + init (one kernel) ----------------
__global__ void setup_k(const float* __restrict__ ew3, const float* __restrict__ ew2,
                        const float* __restrict__ ssc){
    int bid = blockIdx.x, t = threadIdx.x;
    if (bid < 1920){
        int idx = bid*256 + t;
        int bb = idx & 127;
        int n  = idx >> 7;
        int l  = n >> 7;
        int a  = n & 127;
        g_Vb[idx] = __float2bfloat16(ew3[l*HAE + bb] * ew2[bb*HAE + a]);
    } else if (bid < 1984){
        int t2 = (bid - 1920)*256 + t;
        if (t2 < SZv*Hh) g_l2[t2] = 0.5f;
        if (t2 < HAE*HAE) g_G1[t2] = 0.f;
        if (t2 == 0) g_comp = 0.0;
        if (t2 < NTRI){
            int rem = t2, i = 0;
            while (rem >= 32 - i){ rem -= 32 - i; i++; }
            g_iu0[t2] = i; g_iu1[t2] = i + rem;
        }
    } else {
        int gid = (bid - 1984)*256 + t;
        int w = gid >> 5, lane = gid & 31;
        if (w >= Dd*Hh*SZv) return;
        int i = w / (Hh*SZv);
        int rem = w % (Hh*SZv);
        int h = rem / SZv;
        int s = rem % SZv;
        const float* row = &ssc[(((size_t)(i*Hh+h)*SZv)+s)*SZv];
        float a = 0.f;
        for (int k = lane; k < SZv; k += 32) a += row[k];
        #pragma unroll
        for (int o = 16; o > 0; o >>= 1) a += __shfl_down_sync(0xffffffffu, a, o);
        if (lane == 0) g_scalarT[(i*SZv+s)*Hh + h] = a;
    }
}

__global__ void cvt_G1(){
    int t = blockIdx.x*256 + threadIdx.x;
    if (t < HAE*HAE) g_G1b[t] = __float2bfloat16(g_G1[t]);
}

// ---------------- raw / groupnorm (+ per-iter zeroing, + out-dot) --------
__global__ void __launch_bounds__(256)
build_raw_fused(const float* __restrict__ x, const float* __restrict__ ln_g,
                const float* __restrict__ ln_b, int do_out){
    __shared__ float nx[32];
    __shared__ float rw[SZv];
    __shared__ float sc[SZv*2];
    __shared__ float redA[256], redB[256];
    int b = blockIdx.x, t = threadIdx.x;
    int gid = b*256 + t;
    if (gid < Bb*HAE) g_accE[gid] = 0.f;
    if (gid < Lv*Lv){ g_zTz[gid] = 0.f; g_az[gid] = 0.f; }
    if (gid == Bb*HAE){ g_mse = 0.0; g_jsum = 0.0; }

    float s0 = 0.f, s1 = 0.f;
    if (do_out){
        for (int i = t; i < SZv*2; i += 256) sc[i] = g_scaled[i];
        __syncthreads();
        const float* rwg = &g_raw[(size_t)b*SZv];
        for (int i = t; i < SZv; i += 256){
            float v = rwg[i];
            s0 += v*sc[i*2];
            s1 += v*sc[i*2+1];
        }
        s0 = blk_reduce(s0, redA, t);
        s1 = blk_reduce(s1, redA, t);
    }
    if (t < NIi) nx[t] = x[b*NIi + t];
    else if (t == NIi)   nx[t] = s0;
    else if (t == NIi+1) nx[t] = s1;
    __syncthreads();
    float s = 0.f, ss = 0.f;
    for (int idx = t; idx < SZv; idx += 256){
        float v;
        if (idx < NTRI){
            int i = g_iu0[idx], j = g_iu1[idx];
            v = (i == j) ? nx[i] : nx[i] + nx[j];
        } else if (idx < 2*NTRI){
            int k = idx - NTRI;
            v = nx[g_iu0[k]] * nx[g_iu1[k]];
        } else if (idx < 2*NTRI + 32){
            v = sinf(nx[idx - 2*NTRI]);
        } else {
            v = cosf(nx[idx - 2*NTRI - 32]);
        }
        rw[idx] = v; s += v; ss += v*v;
    }
    redA[t] = s; redB[t] = ss; __syncthreads();
    for (int st = 128; st > 0; st >>= 1){
        if (t < st){ redA[t] += redA[t+st]; redB[t] += redB[t+st]; }
        __syncthreads();
    }
    float mean = redA[0] / SZv;
    float var  = redB[0] / SZv - mean*mean;
    float rstd = rsqrtf(var + 1e-5f);
    for (int idx = t; idx < SZv; idx += 256){
        float v = rw[idx];
        g_raw[(size_t)b*SZv + idx] = v;
        g_xn [(size_t)b*SZv + idx] = (v - mean)*rstd*ln_g[idx] + ln_b[idx];
    }
}

// ---------------- z + zstats + dec1 (16 rows/block, 128 blocks) ---------
#define ZR 16
__global__ void __launch_bounds__(256)
z_dec1(const float* __restrict__ ew3, const float* __restrict__ eb3,
       const float* __restrict__ dw1, const float* __restrict__ db1){
    __shared__ float hs[ZR][129];
    __shared__ float w3[30][129];
    __shared__ float zs[ZR][31];
    int t = threadIdx.x;
    int b0 = blockIdx.x * ZR;
    for (int i = t; i < ZR*HAE; i += 256) hs[i>>7][i&127] = g_h2e[(size_t)b0*HAE + i];
    for (int i = t; i < 30*HAE; i += 256) w3[i>>7][i&127] = ew3[i];
    __syncthreads();
    for (int idx = t; idx < ZR*30; idx += 256){
        int r = idx / 30, l = idx % 30;
        float s = eb3[l];
        #pragma unroll 8
        for (int k = 0; k < HAE; k++) s += hs[r][k]*w3[l][k];
        zs[r][l] = s;
    }
    __syncthreads();
    for (int idx = t; idx < 900; idx += 256){
        int i = idx / 30, j = idx % 30;
        float a = 0.f, ab = 0.f;
        #pragma unroll
        for (int r = 0; r < ZR; r++){
            float zi = zs[r][i], zj = zs[r][j];
            a  += zi*zj;
            ab += fabsf(zi)*fabsf(zj);
        }
        atomicAdd(&g_zTz[idx], a);
        atomicAdd(&g_az[idx], ab);
    }
    for (int idx = t; idx < ZR*HAE; idx += 256){
        int r = idx >> 7, o = idx & 127;
        float s = db1[o];
        #pragma unroll
        for (int l = 0; l < 30; l++) s += zs[r][l]*dw1[o*30 + l];
        g_dh1[(size_t)(b0+r)*HAE + o] = sp_(s);
    }
}

// ---------------- selection chain, phase A (1 block) --------------------
__global__ void __launch_bounds__(256)
sel_A(const float* __restrict__ qw, const float* __restrict__ qb,
      const float* __restrict__ sq,
      const float* __restrict__ sl1, const float* __restrict__ sg1,
      const float* __restrict__ sb1, int iter){
    __shared__ float gsa[900], lsa[900];
    __shared__ float sel[2][30], h1s[2][64];
    __shared__ float sc8[8];
    int t = threadIdx.x;
    qw  += iter*900;  qb  += iter*30;   sq  += iter*60;
    sl1 += iter*2*64*30; sg1 += iter*128; sb1 += iter*128;
    for (int i = t; i < 900; i += 256) gsa[i] = g_zTz[i] / fmaxf(g_az[i], 1e-5f);
    __syncthreads();
    for (int idx = t; idx < 900; idx += 256){
        int i = idx / 30, j = idx % 30;
        float s = qb[j];
        #pragma unroll
        for (int k = 0; k < 30; k++) s += gsa[i*30+k]*qw[j*30+k];
        lsa[idx] = s;
    }
    __syncthreads();
    if (t < 60){
        int h = t / 30, i = t % 30;
        float s = 0.f;
        #pragma unroll
        for (int j = 0; j < 30; j++) s += lsa[i*30+j]*sq[h*30+j];
        sel[h][i] = s;
    }
    __syncthreads();
    if (t < 128){
        int h = t >> 6, o = t & 63;
        float s = 0.f;
        #pragma unroll
        for (int l = 0; l < 30; l++) s += sl1[(h*64+o)*30+l]*sel[h][l];
        h1s[h][o] = s;
    }
    __syncthreads();
    if (t < 2){
        float m = 0.f;
        for (int o = 0; o < 64; o++) m += h1s[t][o];
        m *= (1.f/64.f);
        float v = 0.f;
        for (int o = 0; o < 64; o++){ float d = h1s[t][o]-m; v += d*d; }
        v *= (1.f/64.f);
        sc8[t*2] = m; sc8[t*2+1] = rsqrtf(v + 1e-5f);
    }
    __syncthreads();
    if (t < 128){
        int h = t >> 6, o = t & 63;
        g_selh1[t] = sp_((h1s[h][o]-sc8[h*2])*sc8[h*2+1]*sg1[h*64+o] + sb1[h*64+o]);
    }
}

// ---------------- phase B ----------------
__global__ void __launch_bounds__(256)
sel_B(const float* __restrict__ sl2, int iter){
    __shared__ float h1s[128];
    int t = threadIdx.x;
    if (t < 128) h1s[t] = g_selh1[t];
    __syncthreads();
    int w = blockIdx.x*8 + (t >> 5);
    int lane = t & 31;
    if (w >= Hh*SZv) return;
    int h = w / SZv, s = w % SZv;
    const float* wp = &sl2[((size_t)iter*Hh*SZv + w)*64];
    float a = wp[lane]*h1s[h*64+lane] + wp[lane+32]*h1s[h*64+lane+32];
    #pragma unroll
    for (int o = 16; o > 0; o >>= 1) a += __shfl_down_sync(0xffffffffu, a, o);
    if (lane == 0) g_buf[h*SZv + s] = a;
}

// ---------------- phase C (1 block) ----------------
__global__ void __launch_bounds__(256)
sel_C(const float* __restrict__ sg2, const float* __restrict__ sb2,
      const float* __restrict__ son, int iter){
    __shared__ float buf[2][SZv];
    __shared__ float red[256];
    int t = threadIdx.x;
    sg2 += iter*2*SZv; sb2 += iter*2*SZv;
    son += iter*2*2*SZv;
    for (int i = t; i < 2*SZv; i += 256) buf[i/SZv][i%SZv] = g_buf[i];
    __syncthreads();
    for (int h = 0; h < 2; h++){
        float s = 0.f, ss = 0.f;
        for (int i = t; i < SZv; i += 256){ float v = buf[h][i]; s += v; ss += v*v; }
        s  = blk_reduce(s, red, t);
        ss = blk_reduce(ss, red, t);
        float mean = s*(1.f/SZv);
        float var  = ss*(1.f/SZv) - mean*mean;
        float rstd = rsqrtf(var + 1e-5f);
        float mx = -1e30f;
        for (int i = t; i < SZv; i += 256){
            float v = (buf[h][i]-mean)*rstd*sg2[h*SZv+i] + sb2[h*SZv+i];
            buf[h][i] = v;
            mx = fmaxf(mx, v);
        }
        mx = blk_reduce_max(mx, red, t);
        float se = 0.f;
        for (int i = t; i < SZv; i += 256){
            float e = expf(buf[h][i]-mx);
            buf[h][i] = e;
            se += e;
        }
        se = blk_reduce(se, red, t);
        float inv = 1.f/se;
        for (int i = t; i < SZv; i += 256) buf[h][i] *= inv;
        __syncthreads();
    }
    float d0 = 0.f, d1 = 0.f;
    for (int s = t; s < SZv; s += 256){
        float il = g_l2[s*2]*g_l2[s*2+1];
        d0 += son[s]*il + son[SZv+s]*buf[0][s];
        d1 += son[2*SZv+s]*il + son[2*SZv+SZv+s]*buf[1][s];
    }
    d0 = blk_reduce(d0, red, t);
    d1 = blk_reduce(d1, red, t);
    float on0 = sig_(d0), on1 = sig_(d1);
    float e00 = 0.f, e01 = 0.f, e10 = 0.f, e11 = 0.f;
    for (int s = t; s < SZv; s += 256){
        float o0 = on0*buf[0][s], o1 = on1*buf[1][s];
        float sc0 = o0*g_scalarT[(iter*SZv+s)*2+0];
        float sc1 = o1*g_scalarT[(iter*SZv+s)*2+1];
        if (fabsf(sc0) <= 1e-14f) sc0 = 1e-14f;
        if (fabsf(sc1) <= 1e-14f) sc1 = 1e-14f;
        g_scaled[s*2]   = sc0;
        g_scaled[s*2+1] = sc1;
        float l20 = fmaxf(o0, 1e-14f), l21 = fmaxf(o1, 1e-14f);
        g_l2[s*2] = l20; g_l2[s*2+1] = l21;
        float lg0 = logf(l20 + 1e-5f), lg1 = logf(l21 + 1e-5f);
        e00 += l20*lg0; e01 += l20*lg1;
        e10 += l21*lg0; e11 += l21*lg1;
    }
    e00 = blk_reduce(e00, red, t);
    e01 = blk_reduce(e01, red, t);
    e10 = blk_reduce(e10, red, t);
    e11 = blk_reduce(e11, red, t);
    if (t == 0){
        float g00 = -e00, g01 = -e01, g10 = -e10, g11 = -e11;
        float g = 0.01f*0.5f*(g00+g11) - 0.25f*(g01+g10);
        double cst = g_mse/((double)Bb*SZv) + g_jsum/((double)Lv*(double)Bb*(double)SZv);
        g_comp += (double)g + cst;
    }
}

// ---------------- final: out[b] = dot(raw_b, sc0+sc1); out[Bb] = comp ---
__global__ void __launch_bounds__(256)
finalize_dot(float* __restrict__ out){
    __shared__ float sc[SZv];
    int t = threadIdx.x;
    for (int i = t; i < SZv; i += 256) sc[i] = g_scaled[i*2] + g_scaled[i*2+1];
    __syncthreads();
    int warp = t >> 5, lane = t & 31;
    int b = blockIdx.x*8 + warp;
    const float* rw = &g_raw[(size_t)b*SZv];
    float s = 0.f;
    for (int i = lane; i < SZv; i += 32) s += rw[i]*sc[i];
    #pragma unroll
    for (int o = 16; o > 0; o >>= 1) s += __shfl_down_sync(0xffffffffu, s, o);
    if (lane == 0) out[b] = s;
    if (blockIdx.x == 0 && t == 0) out[Bb] = (float)g_comp;
}

// ---------------- host ----------------
extern "C" void kernel_launch(void* const* d_in, const int* in_sizes, int n_in,
                              void* d_out, int out_size) {
    const float* x    = (const float*)d_in[0];
    const float* ln_g = (const float*)d_in[1];
    const float* ln_b = (const float*)d_in[2];
    const float* ew1  = (const float*)d_in[3];
    const float* eb1  = (const float*)d_in[4];
    const float* ew2  = (const float*)d_in[5];
    const float* eb2  = (const float*)d_in[6];
    const float* ew3  = (const float*)d_in[7];
    const float* eb3  = (const float*)d_in[8];
    const float* dw1  = (const float*)d_in[9];
    const float* db1  = (const float*)d_in[10];
    const float* dw2  = (const float*)d_in[11];
    const float* db2  = (const float*)d_in[12];
    const float* dw3  = (const float*)d_in[13];
    const float* db3  = (const float*)d_in[14];
    const float* qw   = (const float*)d_in[15];
    const float* qb   = (const float*)d_in[16];
    const float* sq   = (const float*)d_in[17];
    const float* sl1  = (const float*)d_in[18];
    const float* sg1  = (const float*)d_in[19];
    const float* sb1  = (const float*)d_in[20];
    const float* sl2  = (const float*)d_in[21];
    const float* sg2  = (const float*)d_in[22];
    const float* sb2  = (const float*)d_in[23];
    const float* ssc  = (const float*)d_in[24];
    const float* son  = (const float*)d_in[25];
    float* out = (float*)d_out;

    float *pXn, *pH2, *pDh1, *pDh2, *pG1, *pAccE;
    double *pMse;
    cudaGetSymbolAddress((void**)&pXn,  g_xn);
    cudaGetSymbolAddress((void**)&pH2,  g_h2e);
    cudaGetSymbolAddress((void**)&pDh1, g_dh1);
    cudaGetSymbolAddress((void**)&pDh2, g_dh2);
    cudaGetSymbolAddress((void**)&pG1,  g_G1);
    cudaGetSymbolAddress((void**)&pAccE,g_accE);
    cudaGetSymbolAddress((void**)&pMse, g_mse);

    cudaFuncSetAttribute(hmma_gemm<0>, cudaFuncAttributeMaxDynamicSharedMemorySize, HMMA_SMEM);
    cudaFuncSetAttribute(hmma_gemm<1>, cudaFuncAttributeMaxDynamicSharedMemorySize, HMMA_SMEM);

    setup_k<<<2544,256>>>(ew3, ew2, ssc);
    tf32_gemm<6,0><<<dim3(1,1,35),256,SM1>>>(ew1, ew1, HAE, SZv, 32,
        nullptr, pG1, nullptr, 0, nullptr, nullptr);
    cvt_G1<<<64,256>>>();

    for (int iter = 0; iter < Dd; iter++){
        build_raw_fused<<<Bb,256>>>(x, ln_g, ln_b, iter > 0 ? 1 : 0);
        // enc1: xn @ ew1^T -> accE (split-K atomics)
        tf32_gemm<6,1><<<dim3(16,1,7),256,SM3>>>(pXn, ew1, HAE, SZv, 160,
            nullptr, pAccE, nullptr, 0, nullptr, nullptr);
        // enc2 (MODE 7): A-staging applies enc1 epi (h1 staged, d1 stored);
        // epilogue -> h2e (f32) + d2b (bf16)
        tf32_gemm<7,1><<<dim3(16,1,1),256,SM3>>>(pAccE, ew2, HAE, HAE, HAE,
            eb2, pH2, nullptr, 0, nullptr, eb1);
        // z + zstats + dec1 (parallel, 128 blocks)
        z_dec1<<<Bb/ZR,256>>>(ew3, eb3, dw1, db1);
        // dec2: dh1 @ dw2^T -> dh2 (sp)
        tf32_gemm<5,1><<<dim3(16,1,1),256,SM3>>>(pDh1, dw2, HAE, HAE, HAE,
            db2, pDh2, nullptr, 0, nullptr, nullptr);
        // dec3 + fused MSE
        tf32_gemm<1,1><<<dim3(16,9,1),256,SM3>>>(pDh2, dw3, SZv, HAE, HAE,
            db3, nullptr, pXn, SZv, pMse, nullptr);
        // TM / JQ (HMMA bf16)
        hmma_gemm<0><<<dim3(16,30), 256, HMMA_SMEM>>>();
        hmma_gemm<1><<<dim3(480,1), 256, HMMA_SMEM>>>();
        // selection chain
        sel_A<<<1,256>>>(qw, qb, sq, sl1, sg1, sb1, iter);
        sel_B<<<(Hh*SZv+7)/8,256>>>(sl2, iter);
        sel_C<<<1,256>>>(sg2, sb2, son, iter);
    }
    finalize_dot<<<Bb/8,256>>>(out);
}

// round 14
// speedup vs baseline: 1.1656x; 1.0628x over previous
#include <cuda_runtime.h>
#include <cuda_bf16.h>
#include <math.h>
#include <stdint.h>

#define Bb   2048
#define NIi  30
#define Hh   2
#define Dd   2
#define HAE  128
#define SZv  1120
#define Lv   30
#define NTRI 528
#define NV   (Lv*HAE)   /* 3840 */

// ---------------- device scratch ----------------
__device__ float g_raw[Bb*SZv];
__device__ float g_xn [Bb*SZv];
__device__ float g_d1[Bb*HAE];
__device__ float g_h2e[Bb*HAE];
__device__ float g_dh1[Bb*HAE], g_dh2[Bb*HAE];
__device__ float g_accE[Bb*HAE];
__device__ float g_G1[HAE*HAE];
__device__ __nv_bfloat16 g_G1b[HAE*HAE];
__device__ __nv_bfloat16 g_Vb[NV*HAE];
__device__ __nv_bfloat16 g_d2b[Bb*HAE];
__device__ float g_scalarT[Dd*SZv*Hh];
__device__ float g_zTz[Lv*Lv], g_az[Lv*Lv];
__device__ float g_l2[SZv*Hh];
__device__ float g_scaled[SZv*Hh];
__device__ float g_selh1[2*64];
__device__ float g_buf[Hh*SZv];
__device__ double g_mse, g_jsum, g_comp;
__device__ int g_iu0[NTRI], g_iu1[NTRI];

__device__ __forceinline__ float sp_(float x){ return fmaxf(x,0.f) + log1pf(__expf(-fabsf(x))); }
__device__ __forceinline__ float sig_(float x){ return 1.f/(1.f+__expf(-x)); }

__device__ __forceinline__ float blk_reduce(float v, float* red, int t){
    red[t]=v; __syncthreads();
    for(int st=128;st>0;st>>=1){ if(t<st) red[t]+=red[t+st]; __syncthreads(); }
    float r=red[0]; __syncthreads();
    return r;
}
__device__ __forceinline__ float blk_reduce_max(float v, float* red, int t){
    red[t]=v; __syncthreads();
    for(int st=128;st>0;st>>=1){ if(t<st) red[t]=fmaxf(red[t],red[t+st]); __syncthreads(); }
    float r=red[0]; __syncthreads();
    return r;
}

// ================= fused HMMA bf16: TM + JQ ==========
#define HS 136
#define HMMA_SMEM (2*128*HS*2)

__device__ __forceinline__ void mma16816(float* c, const uint32_t* a,
                                         uint32_t b0, uint32_t b1){
    asm volatile(
        "mma.sync.aligned.m16n8k16.row.col.f32.bf16.bf16.f32 "
        "{%0,%1,%2,%3}, {%4,%5,%6,%7}, {%8,%9}, {%0,%1,%2,%3};"
        : "+f"(c[0]), "+f"(c[1]), "+f"(c[2]), "+f"(c[3])
        : "r"(a[0]), "r"(a[1]), "r"(a[2]), "r"(a[3]), "r"(b0), "r"(b1));
}
__device__ __forceinline__ void ldsm_x4(uint32_t* r, uint32_t addr){
    asm volatile("ldmatrix.sync.aligned.m8n8.x4.shared.b16 {%0,%1,%2,%3}, [%4];"
        : "=r"(r[0]), "=r"(r[1]), "=r"(r[2]), "=r"(r[3]) : "r"(addr));
}
__device__ __forceinline__ void ldsm_x2(uint32_t& r0, uint32_t& r1, uint32_t addr){
    asm volatile("ldmatrix.sync.aligned.m8n8.x2.shared.b16 {%0,%1}, [%2];"
        : "=r"(r0), "=r"(r1) : "r"(addr));
}

__global__ void __launch_bounds__(256)
hmma_tmjq(){
    extern __shared__ __nv_bfloat16 dsm[];
    __nv_bfloat16* As = dsm;
    __nv_bfloat16* Bs = dsm + 128*HS;
    __shared__ float red[256];
    const int t = threadIdx.x, wid = t >> 5, lane = t & 31;
    const int g = lane >> 2, ti = lane & 3;
    const int m0 = blockIdx.x * 128;

    const __nv_bfloat16* Ag = g_d2b + (size_t)m0*HAE;
    const __nv_bfloat16* Bg = g_Vb + (size_t)blockIdx.y*128*HAE;

    for (int i = t; i < 2048; i += 256){
        int row = i >> 4, col = (i & 15) * 8;
        *reinterpret_cast<uint4*>(&As[row*HS + col]) =
            *reinterpret_cast<const uint4*>(&Ag[(size_t)row*HAE + col]);
        *reinterpret_cast<uint4*>(&Bs[row*HS + col]) =
            *reinterpret_cast<const uint4*>(&Bg[(size_t)row*HAE + col]);
    }
    __syncthreads();

    const int wm = wid >> 1, wn = wid & 1;
    const int r0 = wm*32, c0 = wn*64;
    float C[2][8][4];
    #pragma unroll
    for (int mi = 0; mi < 2; mi++)
        #pragma unroll
        for (int ni = 0; ni < 8; ni++)
            #pragma unroll
            for (int q = 0; q < 4; q++) C[mi][ni][q] = 0.f;

    const uint32_t asu = (uint32_t)__cvta_generic_to_shared(As);
    const uint32_t bsu = (uint32_t)__cvta_generic_to_shared(Bs);
    const uint32_t aBase = asu + ((uint32_t)((r0 + (lane & 15))*HS + ((lane >> 4) << 3)) << 1);
    const uint32_t bBase = bsu + ((uint32_t)((c0 + (lane & 7))*HS + ((lane & 8) ? 8 : 0)) << 1);

    // ---- pass 1: C = d2b @ Vb^T ----
    #pragma unroll
    for (int kk = 0; kk < 8; kk++){
        uint32_t Af[2][4];
        ldsm_x4(Af[0], aBase + kk*32);
        ldsm_x4(Af[1], aBase + 16*HS*2 + kk*32);
        #pragma unroll
        for (int ni = 0; ni < 8; ni++){
            uint32_t b0, b1;
            ldsm_x2(b0, b1, bBase + ni*(8*HS*2) + kk*32);
            mma16816(C[0][ni], Af[0], b0, b1);
            mma16816(C[1][ni], Af[1], b0, b1);
        }
    }
    __syncthreads();   // all pass-1 reads of As/Bs complete

    // ---- M = C * d1 -> As (bf16, in place of d2b tile) ----
    #pragma unroll
    for (int mi = 0; mi < 2; mi++){
        const int rl = r0 + mi*16 + g;
        const int r  = m0 + rl;
        #pragma unroll
        for (int ni = 0; ni < 8; ni++){
            const int a = c0 + ni*8 + ti*2;
            float2 dA = *reinterpret_cast<const float2*>(&g_d1[(size_t)r*HAE + a]);
            float2 dB = *reinterpret_cast<const float2*>(&g_d1[(size_t)(r+8)*HAE + a]);
            *reinterpret_cast<__nv_bfloat162*>(&As[rl*HS + a]) =
                __floats2bfloat162_rn(C[mi][ni][0]*dA.x, C[mi][ni][1]*dA.y);
            *reinterpret_cast<__nv_bfloat162*>(&As[(rl+8)*HS + a]) =
                __floats2bfloat162_rn(C[mi][ni][2]*dB.x, C[mi][ni][3]*dB.y);
        }
    }
    // ---- reload Bs = G1b (symmetric, NT form exact) ----
    for (int i = t; i < 2048; i += 256){
        int row = i >> 4, col = (i & 15) * 8;
        *reinterpret_cast<uint4*>(&Bs[row*HS + col]) =
            *reinterpret_cast<const uint4*>(&g_G1b[(size_t)row*HAE + col]);
    }
    __syncthreads();

    // ---- pass 2: C = M @ G1b^T ----
    #pragma unroll
    for (int mi = 0; mi < 2; mi++)
        #pragma unroll
        for (int ni = 0; ni < 8; ni++)
            #pragma unroll
            for (int q = 0; q < 4; q++) C[mi][ni][q] = 0.f;
    #pragma unroll
    for (int kk = 0; kk < 8; kk++){
        uint32_t Af[2][4];
        ldsm_x4(Af[0], aBase + kk*32);
        ldsm_x4(Af[1], aBase + 16*HS*2 + kk*32);
        #pragma unroll
        for (int ni = 0; ni < 8; ni++){
            uint32_t b0, b1;
            ldsm_x2(b0, b1, bBase + ni*(8*HS*2) + kk*32);
            mma16816(C[0][ni], Af[0], b0, b1);
            mma16816(C[1][ni], Af[1], b0, b1);
        }
    }

    // ---- jsum += dot(C, M) ----
    float loc = 0.f;
    #pragma unroll
    for (int mi = 0; mi < 2; mi++){
        const int rl = r0 + mi*16 + g;
        #pragma unroll
        for (int ni = 0; ni < 8; ni++){
            const int a = c0 + ni*8 + ti*2;
            __nv_bfloat162 mA = *reinterpret_cast<const __nv_bfloat162*>(&As[rl*HS + a]);
            __nv_bfloat162 mB = *reinterpret_cast<const __nv_bfloat162*>(&As[(rl+8)*HS + a]);
            loc += C[mi][ni][0]*__bfloat162float(mA.x)
                 + C[mi][ni][1]*__bfloat162float(mA.y)
                 + C[mi][ni][2]*__bfloat162float(mB.x)
                 + C[mi][ni][3]*__bfloat162float(mB.y);
        }
    }
    red[t] = loc; __syncthreads();
    for (int st = 128; st > 0; st >>= 1){ if (t < st) red[t] += red[t+st]; __syncthreads(); }
    if (t == 0) atomicAdd(&g_jsum, (double)red[0]);
}

// ================= TF32 GEMM ==========
// MODE 1: mse accumulate; MODE 5: sp only; MODE 6: split-K atomicAdd
// MODE 7: enc2 — A-staging applies enc1 epilogue; epilogue h2e f32 + d2b bf16
#define TS 20

__device__ __forceinline__ uint32_t to_tf32(float x){
    uint32_t u;
    asm("cvt.rna.tf32.f32 %0, %1;" : "=r"(u) : "f"(x));
    return u;
}
__device__ __forceinline__ void mma1688_tf32(float* c, const uint32_t* a,
                                             uint32_t b0, uint32_t b1){
    asm volatile(
        "mma.sync.aligned.m16n8k8.row.col.f32.tf32.tf32.f32 "
        "{%0,%1,%2,%3}, {%4,%5,%6,%7}, {%8,%9}, {%0,%1,%2,%3};"
        : "+f"(c[0]), "+f"(c[1]), "+f"(c[2]), "+f"(c[3])
        : "r"(a[0]), "r"(a[1]), "r"(a[2]), "r"(a[3]), "r"(b0), "r"(b1));
}

template<int MODE, int PREC>
__global__ void __launch_bounds__(256)
tf32_gemm(const float* __restrict__ A, const float* __restrict__ Bm,
          int N, int K, int Kc,
          const float* __restrict__ bias, float* __restrict__ out0,
          const float* __restrict__ aux, int s_aux, double* accd,
          const float* __restrict__ pA){
    extern __shared__ float tsm[];
    float* AsH = tsm;
    float* BsH = tsm + 128*TS;
    float* AsL = tsm + 2*128*TS;
    float* BsL = tsm + 3*128*TS;
    __shared__ float red[256];
    const int t = threadIdx.x, wid = t >> 5, lane = t & 31;
    const int g = lane >> 2, ti = lane & 3;
    const int m0 = blockIdx.x * 128, n0 = blockIdx.y * 128;
    const int kBeg = blockIdx.z * Kc, kEnd = min(K, kBeg + Kc);
    const int wm = wid >> 1, wn = wid & 1;
    const int r0 = wm*32, c0 = wn*64;

    float C[2][8][4];
    #pragma unroll
    for (int mi = 0; mi < 2; mi++)
        #pragma unroll
        for (int ni = 0; ni < 8; ni++)
            #pragma unroll
            for (int q = 0; q < 4; q++) C[mi][ni][q] = 0.f;

    for (int k0 = kBeg; k0 < kEnd; k0 += 16){
        #pragma unroll
        for (int i = 0; i < 2; i++){
            int li = t + i*256;
            int row = li >> 2, c = (li & 3) * 4;
            float4 va = *reinterpret_cast<const float4*>(&A[(size_t)(m0+row)*K + k0 + c]);
            float4 vb = make_float4(0.f,0.f,0.f,0.f);
            if (n0 + row < N)
                vb = *reinterpret_cast<const float4*>(&Bm[(size_t)(n0+row)*K + k0 + c]);
            float av[4] = {va.x,va.y,va.z,va.w};
            float bv[4] = {vb.x,vb.y,vb.z,vb.w};
            if (MODE == 7){
                #pragma unroll
                for (int q = 0; q < 4; q++){
                    int col = k0 + c + q;
                    float v = av[q] + pA[col];
                    av[q] = sp_(v);
                    g_d1[(size_t)(m0+row)*HAE + col] = sig_(v);
                }
            }
            #pragma unroll
            for (int q = 0; q < 4; q++){
                uint32_t ah = to_tf32(av[q]);
                uint32_t bh = to_tf32(bv[q]);
                AsH[row*TS + c + q] = __uint_as_float(ah);
                BsH[row*TS + c + q] = __uint_as_float(bh);
                if (PREC){
                    AsL[row*TS + c + q] = __uint_as_float(to_tf32(av[q] - __uint_as_float(ah)));
                    BsL[row*TS + c + q] = __uint_as_float(to_tf32(bv[q] - __uint_as_float(bh)));
                }
            }
        }
        __syncthreads();
        #pragma unroll
        for (int kk = 0; kk < 16; kk += 8){
            uint32_t AfH[2][4], AfL[2][4];
            #pragma unroll
            for (int mi = 0; mi < 2; mi++){
                const int ao = (r0 + mi*16 + g)*TS + kk;
                AfH[mi][0] = __float_as_uint(AsH[ao + ti]);
                AfH[mi][1] = __float_as_uint(AsH[ao + 8*TS + ti]);
                AfH[mi][2] = __float_as_uint(AsH[ao + ti + 4]);
                AfH[mi][3] = __float_as_uint(AsH[ao + 8*TS + ti + 4]);
                if (PREC){
                    AfL[mi][0] = __float_as_uint(AsL[ao + ti]);
                    AfL[mi][1] = __float_as_uint(AsL[ao + 8*TS + ti]);
                    AfL[mi][2] = __float_as_uint(AsL[ao + ti + 4]);
                    AfL[mi][3] = __float_as_uint(AsL[ao + 8*TS + ti + 4]);
                }
            }
            #pragma unroll
            for (int ni = 0; ni < 8; ni++){
                const int bo = (c0 + ni*8 + g)*TS + kk;
                uint32_t bH0 = __float_as_uint(BsH[bo + ti]);
                uint32_t bH1 = __float_as_uint(BsH[bo + ti + 4]);
                mma1688_tf32(C[0][ni], AfH[0], bH0, bH1);
                mma1688_tf32(C[1][ni], AfH[1], bH0, bH1);
                if (PREC){
                    uint32_t bL0 = __float_as_uint(BsL[bo + ti]);
                    uint32_t bL1 = __float_as_uint(BsL[bo + ti + 4]);
                    mma1688_tf32(C[0][ni], AfL[0], bH0, bH1);
                    mma1688_tf32(C[1][ni], AfL[1], bH0, bH1);
                    mma1688_tf32(C[0][ni], AfH[0], bL0, bL1);
                    mma1688_tf32(C[1][ni], AfH[1], bL0, bL1);
                }
            }
        }
        __syncthreads();
    }

    if (MODE == 5){
        #pragma unroll
        for (int mi = 0; mi < 2; mi++){
            const int r = m0 + r0 + mi*16 + g;
            #pragma unroll
            for (int ni = 0; ni < 8; ni++){
                const int gn = n0 + c0 + ni*8 + 2*ti;
                if (gn < N){
                    float b0v = bias[gn], b1v = bias[gn+1];
                    size_t oA = (size_t)r*HAE + gn;
                    size_t oB = (size_t)(r+8)*HAE + gn;
                    out0[oA]   = sp_(C[mi][ni][0] + b0v);
                    out0[oA+1] = sp_(C[mi][ni][1] + b1v);
                    out0[oB]   = sp_(C[mi][ni][2] + b0v);
                    out0[oB+1] = sp_(C[mi][ni][3] + b1v);
                }
            }
        }
    } else if (MODE == 7){
        #pragma unroll
        for (int mi = 0; mi < 2; mi++){
            const int r = m0 + r0 + mi*16 + g;
            #pragma unroll
            for (int ni = 0; ni < 8; ni++){
                const int gn = c0 + ni*8 + 2*ti;
                float b0v = bias[gn], b1v = bias[gn+1];
                float v00 = C[mi][ni][0] + b0v, v01 = C[mi][ni][1] + b1v;
                float v10 = C[mi][ni][2] + b0v, v11 = C[mi][ni][3] + b1v;
                size_t oA = (size_t)r*HAE + gn;
                size_t oB = (size_t)(r+8)*HAE + gn;
                out0[oA]   = sp_(v00); out0[oA+1] = sp_(v01);
                out0[oB]   = sp_(v10); out0[oB+1] = sp_(v11);
                *reinterpret_cast<__nv_bfloat162*>(&g_d2b[oA]) =
                    __floats2bfloat162_rn(sig_(v00), sig_(v01));
                *reinterpret_cast<__nv_bfloat162*>(&g_d2b[oB]) =
                    __floats2bfloat162_rn(sig_(v10), sig_(v11));
            }
        }
    } else if (MODE == 1){
        float loc = 0.f;
        #pragma unroll
        for (int mi = 0; mi < 2; mi++){
            const int r = m0 + r0 + mi*16 + g;
            #pragma unroll
            for (int ni = 0; ni < 8; ni++){
                const int gn = n0 + c0 + ni*8 + 2*ti;
                if (gn < N){
                    float b0v = bias[gn], b1v = bias[gn+1];
                    float d0 = aux[(size_t)r*s_aux + gn]       - (C[mi][ni][0] + b0v);
                    float d1 = aux[(size_t)r*s_aux + gn + 1]   - (C[mi][ni][1] + b1v);
                    float d2 = aux[(size_t)(r+8)*s_aux + gn]   - (C[mi][ni][2] + b0v);
                    float d3 = aux[(size_t)(r+8)*s_aux + gn+1] - (C[mi][ni][3] + b1v);
                    loc += d0*d0 + d1*d1 + d2*d2 + d3*d3;
                }
            }
        }
        red[t] = loc; __syncthreads();
        for (int st = 128; st > 0; st >>= 1){ if (t < st) red[t] += red[t+st]; __syncthreads(); }
        if (t == 0) atomicAdd(accd, (double)red[0]);
    } else { // MODE 6
        #pragma unroll
        for (int mi = 0; mi < 2; mi++){
            const int r = m0 + r0 + mi*16 + g;
            #pragma unroll
            for (int ni = 0; ni < 8; ni++){
                const int gn = n0 + c0 + ni*8 + 2*ti;
                if (gn < N){
                    atomicAdd(&out0[(size_t)r*HAE + gn],       C[mi][ni][0]);
                    atomicAdd(&out0[(size_t)r*HAE + gn + 1],   C[mi][ni][1]);
                    atomicAdd(&out0[(size_t)(r+8)*HAE + gn],   C[mi][ni][2]);
                    atomicAdd(&out0[(size_t)(r+8)*HAE + gn+1], C[mi][ni][3]);
                }
            }
        }
    }
}

#define SM1 (2*128*TS*4)
#define SM3 (4*128*TS*4)

// ---------------- setup: V + scalarT + init (one kernel) ----------------
__global__ void setup_k(const float* __restrict__ ew3, const float* __restrict__ ew2,
                        const float* __restrict__ ssc){
    int bid = blockIdx.x, t = threadIdx.x;
    if (bid < 1920){
        int idx = bid*256 + t;
        int bb = idx & 127;
        int n  = idx >> 7;
        int l  = n >> 7;
        int a  = n & 127;
        g_Vb[idx] = __float2bfloat16(ew3[l*HAE + bb] * ew2[bb*HAE + a]);
    } else if (bid < 1984){
        int t2 = (bid - 1920)*256 + t;
        if (t2 < SZv*Hh) g_l2[t2] = 0.5f;
        if (t2 < HAE*HAE) g_G1[t2] = 0.f;
        if (t2 == 0) g_comp = 0.0;
        if (t2 < NTRI){
            int rem = t2, i = 0;
            while (rem >= 32 - i){ rem -= 32 - i; i++; }
            g_iu0[t2] = i; g_iu1[t2] = i + rem;
        }
    } else {
        int gid = (bid - 1984)*256 + t;
        int w = gid >> 5, lane = gid & 31;
        if (w >= Dd*Hh*SZv) return;
        int i = w / (Hh*SZv);
        int rem = w % (Hh*SZv);
        int h = rem / SZv;
        int s = rem % SZv;
        const float* row = &ssc[(((size_t)(i*Hh+h)*SZv)+s)*SZv];
        float a = 0.f;
        for (int k = lane; k < SZv; k += 32) a += row[k];
        #pragma unroll
        for (int o = 16; o > 0; o >>= 1) a += __shfl_down_sync(0xffffffffu, a, o);
        if (lane == 0) g_scalarT[(i*SZv+s)*Hh + h] = a;
    }
}

__global__ void cvt_G1(){
    int t = blockIdx.x*256 + threadIdx.x;
    if (t < HAE*HAE) g_G1b[t] = __float2bfloat16(g_G1[t]);
}

// ---------------- raw / groupnorm (+ per-iter zeroing, + out-dot) --------
__global__ void __launch_bounds__(256)
build_raw_fused(const float* __restrict__ x, const float* __restrict__ ln_g,
                const float* __restrict__ ln_b, int do_out){
    __shared__ float nx[32];
    __shared__ float rw[SZv];
    __shared__ float sc[SZv*2];
    __shared__ float redA[256], redB[256];
    int b = blockIdx.x, t = threadIdx.x;
    int gid = b*256 + t;
    if (gid < Bb*HAE) g_accE[gid] = 0.f;
    if (gid < Lv*Lv){ g_zTz[gid] = 0.f; g_az[gid] = 0.f; }
    if (gid == Bb*HAE){ g_mse = 0.0; g_jsum = 0.0; }

    float s0 = 0.f, s1 = 0.f;
    if (do_out){
        for (int i = t; i < SZv*2; i += 256) sc[i] = g_scaled[i];
        __syncthreads();
        const float* rwg = &g_raw[(size_t)b*SZv];
        for (int i = t; i < SZv; i += 256){
            float v = rwg[i];
            s0 += v*sc[i*2];
            s1 += v*sc[i*2+1];
        }
        s0 = blk_reduce(s0, redA, t);
        s1 = blk_reduce(s1, redA, t);
    }
    if (t < NIi) nx[t] = x[b*NIi + t];
    else if (t == NIi)   nx[t] = s0;
    else if (t == NIi+1) nx[t] = s1;
    __syncthreads();
    float s = 0.f, ss = 0.f;
    for (int idx = t; idx < SZv; idx += 256){
        float v;
        if (idx < NTRI){
            int i = g_iu0[idx], j = g_iu1[idx];
            v = (i == j) ? nx[i] : nx[i] + nx[j];
        } else if (idx < 2*NTRI){
            int k = idx - NTRI;
            v = nx[g_iu0[k]] * nx[g_iu1[k]];
        } else if (idx < 2*NTRI + 32){
            v = sinf(nx[idx - 2*NTRI]);
        } else {
            v = cosf(nx[idx - 2*NTRI - 32]);
        }
        rw[idx] = v; s += v; ss += v*v;
    }
    redA[t] = s; redB[t] = ss; __syncthreads();
    for (int st = 128; st > 0; st >>= 1){
        if (t < st){ redA[t] += redA[t+st]; redB[t] += redB[t+st]; }
        __syncthreads();
    }
    float mean = redA[0] / SZv;
    float var  = redB[0] / SZv - mean*mean;
    float rstd = rsqrtf(var + 1e-5f);
    for (int idx = t; idx < SZv; idx += 256){
        float v = rw[idx];
        g_raw[(size_t)b*SZv + idx] = v;
        g_xn [(size_t)b*SZv + idx] = (v - mean)*rstd*ln_g[idx] + ln_b[idx];
    }
}

// ---------------- z + zstats + dec1 (16 rows/block, 128 blocks) ---------
#define ZR 16
__global__ void __launch_bounds__(256)
z_dec1(const float* __restrict__ ew3, const float* __restrict__ eb3,
       const float* __restrict__ dw1, const float* __restrict__ db1){
    __shared__ float hs[ZR][129];
    __shared__ float w3[30][129];
    __shared__ float zs[ZR][31];
    int t = threadIdx.x;
    int b0 = blockIdx.x * ZR;
    for (int i = t; i < ZR*HAE; i += 256) hs[i>>7][i&127] = g_h2e[(size_t)b0*HAE + i];
    for (int i = t; i < 30*HAE; i += 256) w3[i>>7][i&127] = ew3[i];
    __syncthreads();
    for (int idx = t; idx < ZR*30; idx += 256){
        int r = idx / 30, l = idx % 30;
        float s = eb3[l];
        #pragma unroll 8
        for (int k = 0; k < HAE; k++) s += hs[r][k]*w3[l][k];
        zs[r][l] = s;
    }
    __syncthreads();
    for (int idx = t; idx < 900; idx += 256){
        int i = idx / 30, j = idx % 30;
        float a = 0.f, ab = 0.f;
        #pragma unroll
        for (int r = 0; r < ZR; r++){
            float zi = zs[r][i], zj = zs[r][j];
            a  += zi*zj;
            ab += fabsf(zi)*fabsf(zj);
        }
        atomicAdd(&g_zTz[idx], a);
        atomicAdd(&g_az[idx], ab);
    }
    for (int idx = t; idx < ZR*HAE; idx += 256){
        int r = idx >> 7, o = idx & 127;
        float s = db1[o];
        #pragma unroll
        for (int l = 0; l < 30; l++) s += zs[r][l]*dw1[o*30 + l];
        g_dh1[(size_t)(b0+r)*HAE + o] = sp_(s);
    }
}

// ---------------- selection chain, phase A (1 block) --------------------
__global__ void __launch_bounds__(256)
sel_A(const float* __restrict__ qw, const float* __restrict__ qb,
      const float* __restrict__ sq,
      const float* __restrict__ sl1, const float* __restrict__ sg1,
      const float* __restrict__ sb1, int iter){
    __shared__ float gsa[900], lsa[900];
    __shared__ float sel[2][30], h1s[2][64];
    __shared__ float sc8[8];
    int t = threadIdx.x;
    qw  += iter*900;  qb  += iter*30;   sq  += iter*60;
    sl1 += iter*2*64*30; sg1 += iter*128; sb1 += iter*128;
    for (int i = t; i < 900; i += 256) gsa[i] = g_zTz[i] / fmaxf(g_az[i], 1e-5f);
    __syncthreads();
    for (int idx = t; idx < 900; idx += 256){
        int i = idx / 30, j = idx % 30;
        float s = qb[j];
        #pragma unroll
        for (int k = 0; k < 30; k++) s += gsa[i*30+k]*qw[j*30+k];
        lsa[idx] = s;
    }
    __syncthreads();
    if (t < 60){
        int h = t / 30, i = t % 30;
        float s = 0.f;
        #pragma unroll
        for (int j = 0; j < 30; j++) s += lsa[i*30+j]*sq[h*30+j];
        sel[h][i] = s;
    }
    __syncthreads();
    if (t < 128){
        int h = t >> 6, o = t & 63;
        float s = 0.f;
        #pragma unroll
        for (int l = 0; l < 30; l++) s += sl1[(h*64+o)*30+l]*sel[h][l];
        h1s[h][o] = s;
    }
    __syncthreads();
    if (t < 2){
        float m = 0.f;
        for (int o = 0; o < 64; o++) m += h1s[t][o];
        m *= (1.f/64.f);
        float v = 0.f;
        for (int o = 0; o < 64; o++){ float d = h1s[t][o]-m; v += d*d; }
        v *= (1.f/64.f);
        sc8[t*2] = m; sc8[t*2+1] = rsqrtf(v + 1e-5f);
    }
    __syncthreads();
    if (t < 128){
        int h = t >> 6, o = t & 63;
        g_selh1[t] = sp_((h1s[h][o]-sc8[h*2])*sc8[h*2+1]*sg1[h*64+o] + sb1[h*64+o]);
    }
}

// ---------------- phase B ----------------
__global__ void __launch_bounds__(256)
sel_B(const float* __restrict__ sl2, int iter){
    __shared__ float h1s[128];
    int t = threadIdx.x;
    if (t < 128) h1s[t] = g_selh1[t];
    __syncthreads();
    int w = blockIdx.x*8 + (t >> 5);
    int lane = t & 31;
    if (w >= Hh*SZv) return;
    int h = w / SZv, s = w % SZv;
    const float* wp = &sl2[((size_t)iter*Hh*SZv + w)*64];
    float a = wp[lane]*h1s[h*64+lane] + wp[lane+32]*h1s[h*64+lane+32];
    #pragma unroll
    for (int o = 16; o > 0; o >>= 1) a += __shfl_down_sync(0xffffffffu, a, o);
    if (lane == 0) g_buf[h*SZv + s] = a;
}

// ---------------- phase C (1 block) ----------------
__global__ void __launch_bounds__(256)
sel_C(const float* __restrict__ sg2, const float* __restrict__ sb2,
      const float* __restrict__ son, int iter){
    __shared__ float buf[2][SZv];
    __shared__ float red[256];
    int t = threadIdx.x;
    sg2 += iter*2*SZv; sb2 += iter*2*SZv;
    son += iter*2*2*SZv;
    for (int i = t; i < 2*SZv; i += 256) buf[i/SZv][i%SZv] = g_buf[i];
    __syncthreads();
    for (int h = 0; h < 2; h++){
        float s = 0.f, ss = 0.f;
        for (int i = t; i < SZv; i += 256){ float v = buf[h][i]; s += v; ss += v*v; }
        s  = blk_reduce(s, red, t);
        ss = blk_reduce(ss, red, t);
        float mean = s*(1.f/SZv);
        float var  = ss*(1.f/SZv) - mean*mean;
        float rstd = rsqrtf(var + 1e-5f);
        float mx = -1e30f;
        for (int i = t; i < SZv; i += 256){
            float v = (buf[h][i]-mean)*rstd*sg2[h*SZv+i] + sb2[h*SZv+i];
            buf[h][i] = v;
            mx = fmaxf(mx, v);
        }
        mx = blk_reduce_max(mx, red, t);
        float se = 0.f;
        for (int i = t; i < SZv; i += 256){
            float e = expf(buf[h][i]-mx);
            buf[h][i] = e;
            se += e;
        }
        se = blk_reduce(se, red, t);
        float inv = 1.f/se;
        for (int i = t; i < SZv; i += 256) buf[h][i] *= inv;
        __syncthreads();
    }
    float d0 = 0.f, d1 = 0.f;
    for (int s = t; s < SZv; s += 256){
        float il = g_l2[s*2]*g_l2[s*2+1];
        d0 += son[s]*il + son[SZv+s]*buf[0][s];
        d1 += son[2*SZv+s]*il + son[2*SZv+SZv+s]*buf[1][s];
    }
    d0 = blk_reduce(d0, red, t);
    d1 = blk_reduce(d1, red, t);
    float on0 = sig_(d0), on1 = sig_(d1);
    float e00 = 0.f, e01 = 0.f, e10 = 0.f, e11 = 0.f;
    for (int s = t; s < SZv; s += 256){
        float o0 = on0*buf[0][s], o1 = on1*buf[1][s];
        float sc0 = o0*g_scalarT[(iter*SZv+s)*2+0];
        float sc1 = o1*g_scalarT[(iter*SZv+s)*2+1];
        if (fabsf(sc0) <= 1e-14f) sc0 = 1e-14f;
        if (fabsf(sc1) <= 1e-14f) sc1 = 1e-14f;
        g_scaled[s*2]   = sc0;
        g_scaled[s*2+1] = sc1;
        float l20 = fmaxf(o0, 1e-14f), l21 = fmaxf(o1, 1e-14f);
        g_l2[s*2] = l20; g_l2[s*2+1] = l21;
        float lg0 = logf(l20 + 1e-5f), lg1 = logf(l21 + 1e-5f);
        e00 += l20*lg0; e01 += l20*lg1;
        e10 += l21*lg0; e11 += l21*lg1;
    }
    e00 = blk_reduce(e00, red, t);
    e01 = blk_reduce(e01, red, t);
    e10 = blk_reduce(e10, red, t);
    e11 = blk_reduce(e11, red, t);
    if (t == 0){
        float g00 = -e00, g01 = -e01, g10 = -e10, g11 = -e11;
        float g = 0.01f*0.5f*(g00+g11) - 0.25f*(g01+g10);
        double cst = g_mse/((double)Bb*SZv) + g_jsum/((double)Lv*(double)Bb*(double)SZv);
        g_comp += (double)g + cst;
    }
}

// ---------------- final: out[b] = dot(raw_b, sc0+sc1); out[Bb] = comp ---
__global__ void __launch_bounds__(256)
finalize_dot(float* __restrict__ out){
    __shared__ float sc[SZv];
    int t = threadIdx.x;
    for (int i = t; i < SZv; i += 256) sc[i] = g_scaled[i*2] + g_scaled[i*2+1];
    __syncthreads();
    int warp = t >> 5, lane = t & 31;
    int b = blockIdx.x*8 + warp;
    const float* rw = &g_raw[(size_t)b*SZv];
    float s = 0.f;
    for (int i = lane; i < SZv; i += 32) s += rw[i]*sc[i];
    #pragma unroll
    for (int o = 16; o > 0; o >>= 1) s += __shfl_down_sync(0xffffffffu, s, o);
    if (lane == 0) out[b] = s;
    if (blockIdx.x == 0 && t == 0) out[Bb] = (float)g_comp;
}

// ---------------- host ----------------
extern "C" void kernel_launch(void* const* d_in, const int* in_sizes, int n_in,
                              void* d_out, int out_size) {
    const float* x    = (const float*)d_in[0];
    const float* ln_g = (const float*)d_in[1];
    const float* ln_b = (const float*)d_in[2];
    const float* ew1  = (const float*)d_in[3];
    const float* eb1  = (const float*)d_in[4];
    const float* ew2  = (const float*)d_in[5];
    const float* eb2  = (const float*)d_in[6];
    const float* ew3  = (const float*)d_in[7];
    const float* eb3  = (const float*)d_in[8];
    const float* dw1  = (const float*)d_in[9];
    const float* db1  = (const float*)d_in[10];
    const float* dw2  = (const float*)d_in[11];
    const float* db2  = (const float*)d_in[12];
    const float* dw3  = (const float*)d_in[13];
    const float* db3  = (const float*)d_in[14];
    const float* qw   = (const float*)d_in[15];
    const float* qb   = (const float*)d_in[16];
    const float* sq   = (const float*)d_in[17];
    const float* sl1  = (const float*)d_in[18];
    const float* sg1  = (const float*)d_in[19];
    const float* sb1  = (const float*)d_in[20];
    const float* sl2  = (const float*)d_in[21];
    const float* sg2  = (const float*)d_in[22];
    const float* sb2  = (const float*)d_in[23];
    const float* ssc  = (const float*)d_in[24];
    const float* son  = (const float*)d_in[25];
    float* out = (float*)d_out;

    float *pXn, *pH2, *pDh1, *pDh2, *pG1, *pAccE;
    double *pMse;
    cudaGetSymbolAddress((void**)&pXn,  g_xn);
    cudaGetSymbolAddress((void**)&pH2,  g_h2e);
    cudaGetSymbolAddress((void**)&pDh1, g_dh1);
    cudaGetSymbolAddress((void**)&pDh2, g_dh2);
    cudaGetSymbolAddress((void**)&pG1,  g_G1);
    cudaGetSymbolAddress((void**)&pAccE,g_accE);
    cudaGetSymbolAddress((void**)&pMse, g_mse);

    cudaFuncSetAttribute(hmma_tmjq, cudaFuncAttributeMaxDynamicSharedMemorySize, HMMA_SMEM);

    setup_k<<<2544,256>>>(ew3, ew2, ssc);
    tf32_gemm<6,0><<<dim3(1,1,35),256,SM1>>>(ew1, ew1, HAE, SZv, 32,
        nullptr, pG1, nullptr, 0, nullptr, nullptr);
    cvt_G1<<<64,256>>>();

    for (int iter = 0; iter < Dd; iter++){
        build_raw_fused<<<Bb,256>>>(x, ln_g, ln_b, iter > 0 ? 1 : 0);
        // enc1: xn @ ew1^T -> accE (split-K atomics)
        tf32_gemm<6,1><<<dim3(16,1,7),256,SM3>>>(pXn, ew1, HAE, SZv, 160,
            nullptr, pAccE, nullptr, 0, nullptr, nullptr);
        // enc2 (MODE 7): A-staging applies enc1 epi; epilogue h2e + d2b
        tf32_gemm<7,1><<<dim3(16,1,1),256,SM3>>>(pAccE, ew2, HAE, HAE, HAE,
            eb2, pH2, nullptr, 0, nullptr, eb1);
        // z + zstats + dec1
        z_dec1<<<Bb/ZR,256>>>(ew3, eb3, dw1, db1);
        // dec2: dh1 @ dw2^T -> dh2 (sp)
        tf32_gemm<5,1><<<dim3(16,1,1),256,SM3>>>(pDh1, dw2, HAE, HAE, HAE,
            db2, pDh2, nullptr, 0, nullptr, nullptr);
        // dec3 + fused MSE
        tf32_gemm<1,1><<<dim3(16,9,1),256,SM3>>>(pDh2, dw3, SZv, HAE, HAE,
            db3, nullptr, pXn, SZv, pMse, nullptr);
        // fused TM + JQ (HMMA bf16, no M round-trip)
        hmma_tmjq<<<dim3(16,30), 256, HMMA_SMEM>>>();
        // selection chain
        sel_A<<<1,256>>>(qw, qb, sq, sl1, sg1, sb1, iter);
        sel_B<<<(Hh*SZv+7)/8,256>>>(sl2, iter);
        sel_C<<<1,256>>>(sg2, sb2, son, iter);
    }
    finalize_dot<<<Bb/8,256>>>(out);
}

// round 15
// speedup vs baseline: 1.1840x; 1.0158x over previous
#include <cuda_runtime.h>
#include <cuda_bf16.h>
#include <math.h>
#include <stdint.h>

#define Bb   2048
#define NIi  30
#define Hh   2
#define Dd   2
#define HAE  128
#define SZv  1120
#define Lv   30
#define NTRI 528
#define NV   (Lv*HAE)   /* 3840 */

// ---------------- device scratch ----------------
__device__ float g_raw[Bb*SZv];
__device__ float g_xn [Bb*SZv];
__device__ float g_d1[Bb*HAE];
__device__ float g_h2e[Bb*HAE];
__device__ float g_dh1[Bb*HAE], g_dh2[Bb*HAE];
__device__ float g_accE[Bb*HAE];
__device__ float g_G1[HAE*HAE];
__device__ __nv_bfloat16 g_G1b[HAE*HAE];
__device__ __nv_bfloat16 g_Vb[NV*HAE];
__device__ __nv_bfloat16 g_d2b[Bb*HAE];
__device__ float g_scalarT[Dd*SZv*Hh];
__device__ float g_zTz[Lv*Lv], g_az[Lv*Lv];
__device__ float g_l2[SZv*Hh];
__device__ float g_scaled[SZv*Hh];
__device__ float g_buf[Hh*SZv];
__device__ double g_mse, g_jsum, g_comp;
__device__ int g_iu0[NTRI], g_iu1[NTRI];

__device__ __forceinline__ float sp_(float x){ return fmaxf(x,0.f) + log1pf(__expf(-fabsf(x))); }
__device__ __forceinline__ float sig_(float x){ return 1.f/(1.f+__expf(-x)); }

__device__ __forceinline__ float blk_reduce(float v, float* red, int t){
    red[t]=v; __syncthreads();
    for(int st=128;st>0;st>>=1){ if(t<st) red[t]+=red[t+st]; __syncthreads(); }
    float r=red[0]; __syncthreads();
    return r;
}
__device__ __forceinline__ float blk_reduce_max(float v, float* red, int t){
    red[t]=v; __syncthreads();
    for(int st=128;st>0;st>>=1){ if(t<st) red[t]=fmaxf(red[t],red[t+st]); __syncthreads(); }
    float r=red[0]; __syncthreads();
    return r;
}

// ================= HMMA helpers ==========
#define HS 136
#define HMMA_SMEM (2*128*HS*2)   /* 69632 bytes */
#define ZR 16

__device__ __forceinline__ void mma16816(float* c, const uint32_t* a,
                                         uint32_t b0, uint32_t b1){
    asm volatile(
        "mma.sync.aligned.m16n8k16.row.col.f32.bf16.bf16.f32 "
        "{%0,%1,%2,%3}, {%4,%5,%6,%7}, {%8,%9}, {%0,%1,%2,%3};"
        : "+f"(c[0]), "+f"(c[1]), "+f"(c[2]), "+f"(c[3])
        : "r"(a[0]), "r"(a[1]), "r"(a[2]), "r"(a[3]), "r"(b0), "r"(b1));
}
__device__ __forceinline__ void ldsm_x4(uint32_t* r, uint32_t addr){
    asm volatile("ldmatrix.sync.aligned.m8n8.x4.shared.b16 {%0,%1,%2,%3}, [%4];"
        : "=r"(r[0]), "=r"(r[1]), "=r"(r[2]), "=r"(r[3]) : "r"(addr));
}
__device__ __forceinline__ void ldsm_x2(uint32_t& r0, uint32_t& r1, uint32_t addr){
    asm volatile("ldmatrix.sync.aligned.m8n8.x2.shared.b16 {%0,%1}, [%2];"
        : "=r"(r0), "=r"(r1) : "r"(addr));
}

// ---- TM+JQ body (blocks 0..479 of hmma_z) ----
__device__ void hmma_body(__nv_bfloat16* As, __nv_bfloat16* Bs, float* red,
                          int bx, int by){
    const int t = threadIdx.x, wid = t >> 5, lane = t & 31;
    const int g = lane >> 2, ti = lane & 3;
    const int m0 = bx * 128;

    const __nv_bfloat16* Ag = g_d2b + (size_t)m0*HAE;
    const __nv_bfloat16* Bg = g_Vb + (size_t)by*128*HAE;

    for (int i = t; i < 2048; i += 256){
        int row = i >> 4, col = (i & 15) * 8;
        *reinterpret_cast<uint4*>(&As[row*HS + col]) =
            *reinterpret_cast<const uint4*>(&Ag[(size_t)row*HAE + col]);
        *reinterpret_cast<uint4*>(&Bs[row*HS + col]) =
            *reinterpret_cast<const uint4*>(&Bg[(size_t)row*HAE + col]);
    }
    __syncthreads();

    const int wm = wid >> 1, wn = wid & 1;
    const int r0 = wm*32, c0 = wn*64;
    float C[2][8][4];
    #pragma unroll
    for (int mi = 0; mi < 2; mi++)
        #pragma unroll
        for (int ni = 0; ni < 8; ni++)
            #pragma unroll
            for (int q = 0; q < 4; q++) C[mi][ni][q] = 0.f;

    const uint32_t asu = (uint32_t)__cvta_generic_to_shared(As);
    const uint32_t bsu = (uint32_t)__cvta_generic_to_shared(Bs);
    const uint32_t aBase = asu + ((uint32_t)((r0 + (lane & 15))*HS + ((lane >> 4) << 3)) << 1);
    const uint32_t bBase = bsu + ((uint32_t)((c0 + (lane & 7))*HS + ((lane & 8) ? 8 : 0)) << 1);

    // pass 1: C = d2b @ Vb^T
    #pragma unroll
    for (int kk = 0; kk < 8; kk++){
        uint32_t Af[2][4];
        ldsm_x4(Af[0], aBase + kk*32);
        ldsm_x4(Af[1], aBase + 16*HS*2 + kk*32);
        #pragma unroll
        for (int ni = 0; ni < 8; ni++){
            uint32_t b0, b1;
            ldsm_x2(b0, b1, bBase + ni*(8*HS*2) + kk*32);
            mma16816(C[0][ni], Af[0], b0, b1);
            mma16816(C[1][ni], Af[1], b0, b1);
        }
    }
    __syncthreads();

    // M = C * d1 -> As (bf16)
    #pragma unroll
    for (int mi = 0; mi < 2; mi++){
        const int rl = r0 + mi*16 + g;
        const int r  = m0 + rl;
        #pragma unroll
        for (int ni = 0; ni < 8; ni++){
            const int a = c0 + ni*8 + ti*2;
            float2 dA = *reinterpret_cast<const float2*>(&g_d1[(size_t)r*HAE + a]);
            float2 dB = *reinterpret_cast<const float2*>(&g_d1[(size_t)(r+8)*HAE + a]);
            *reinterpret_cast<__nv_bfloat162*>(&As[rl*HS + a]) =
                __floats2bfloat162_rn(C[mi][ni][0]*dA.x, C[mi][ni][1]*dA.y);
            *reinterpret_cast<__nv_bfloat162*>(&As[(rl+8)*HS + a]) =
                __floats2bfloat162_rn(C[mi][ni][2]*dB.x, C[mi][ni][3]*dB.y);
        }
    }
    // reload Bs = G1b (symmetric)
    for (int i = t; i < 2048; i += 256){
        int row = i >> 4, col = (i & 15) * 8;
        *reinterpret_cast<uint4*>(&Bs[row*HS + col]) =
            *reinterpret_cast<const uint4*>(&g_G1b[(size_t)row*HAE + col]);
    }
    __syncthreads();

    // pass 2: C = M @ G1b^T
    #pragma unroll
    for (int mi = 0; mi < 2; mi++)
        #pragma unroll
        for (int ni = 0; ni < 8; ni++)
            #pragma unroll
            for (int q = 0; q < 4; q++) C[mi][ni][q] = 0.f;
    #pragma unroll
    for (int kk = 0; kk < 8; kk++){
        uint32_t Af[2][4];
        ldsm_x4(Af[0], aBase + kk*32);
        ldsm_x4(Af[1], aBase + 16*HS*2 + kk*32);
        #pragma unroll
        for (int ni = 0; ni < 8; ni++){
            uint32_t b0, b1;
            ldsm_x2(b0, b1, bBase + ni*(8*HS*2) + kk*32);
            mma16816(C[0][ni], Af[0], b0, b1);
            mma16816(C[1][ni], Af[1], b0, b1);
        }
    }

    // jsum += dot(C, M)
    float loc = 0.f;
    #pragma unroll
    for (int mi = 0; mi < 2; mi++){
        const int rl = r0 + mi*16 + g;
        #pragma unroll
        for (int ni = 0; ni < 8; ni++){
            const int a = c0 + ni*8 + ti*2;
            __nv_bfloat162 mA = *reinterpret_cast<const __nv_bfloat162*>(&As[rl*HS + a]);
            __nv_bfloat162 mB = *reinterpret_cast<const __nv_bfloat162*>(&As[(rl+8)*HS + a]);
            loc += C[mi][ni][0]*__bfloat162float(mA.x)
                 + C[mi][ni][1]*__bfloat162float(mA.y)
                 + C[mi][ni][2]*__bfloat162float(mB.x)
                 + C[mi][ni][3]*__bfloat162float(mB.y);
        }
    }
    red[t] = loc; __syncthreads();
    for (int st = 128; st > 0; st >>= 1){ if (t < st) red[t] += red[t+st]; __syncthreads(); }
    if (t == 0) atomicAdd(&g_jsum, (double)red[0]);
}

// ---- z + zstats + dec1 body (blocks 480..607 of hmma_z) ----
__device__ void zdec1_body(float* sm, int zb,
                           const float* __restrict__ ew3, const float* __restrict__ eb3,
                           const float* __restrict__ dw1, const float* __restrict__ db1){
    float* hs = sm;                 // [ZR][129]
    float* w3 = hs + ZR*129;        // [30][129]
    float* zs = w3 + 30*129;        // [ZR][31]
    int t = threadIdx.x;
    int b0 = zb * ZR;
    for (int i = t; i < ZR*HAE; i += 256) hs[(i>>7)*129 + (i&127)] = g_h2e[(size_t)b0*HAE + i];
    for (int i = t; i < 30*HAE; i += 256) w3[(i>>7)*129 + (i&127)] = ew3[i];
    __syncthreads();
    for (int idx = t; idx < ZR*30; idx += 256){
        int r = idx / 30, l = idx % 30;
        float s = eb3[l];
        #pragma unroll 8
        for (int k = 0; k < HAE; k++) s += hs[r*129 + k]*w3[l*129 + k];
        zs[r*31 + l] = s;
    }
    __syncthreads();
    for (int idx = t; idx < 900; idx += 256){
        int i = idx / 30, j = idx % 30;
        float a = 0.f, ab = 0.f;
        #pragma unroll
        for (int r = 0; r < ZR; r++){
            float zi = zs[r*31 + i], zj = zs[r*31 + j];
            a  += zi*zj;
            ab += fabsf(zi)*fabsf(zj);
        }
        atomicAdd(&g_zTz[idx], a);
        atomicAdd(&g_az[idx], ab);
    }
    for (int idx = t; idx < ZR*HAE; idx += 256){
        int r = idx >> 7, o = idx & 127;
        float s = db1[o];
        #pragma unroll
        for (int l = 0; l < 30; l++) s += zs[r*31 + l]*dw1[o*30 + l];
        g_dh1[(size_t)(b0+r)*HAE + o] = sp_(s);
    }
}

// ---- merged launch: TM+JQ (480 blocks) || z/zstats/dec1 (128 blocks) ----
__global__ void __launch_bounds__(256)
hmma_z(const float* __restrict__ ew3, const float* __restrict__ eb3,
       const float* __restrict__ dw1, const float* __restrict__ db1){
    extern __shared__ char dyn[];
    __shared__ float red[256];
    if (blockIdx.x < 480){
        __nv_bfloat16* As = reinterpret_cast<__nv_bfloat16*>(dyn);
        hmma_body(As, As + 128*HS, red, blockIdx.x & 15, blockIdx.x >> 4);
    } else {
        zdec1_body(reinterpret_cast<float*>(dyn), blockIdx.x - 480, ew3, eb3, dw1, db1);
    }
}

// ================= TF32 GEMM ==========
// MODE 1: mse accumulate; MODE 5: sp only; MODE 6: split-K atomicAdd
// MODE 7: enc2 — A-staging applies enc1 epilogue; epilogue h2e f32 + d2b bf16
#define TS 20

__device__ __forceinline__ uint32_t to_tf32(float x){
    uint32_t u;
    asm("cvt.rna.tf32.f32 %0, %1;" : "=r"(u) : "f"(x));
    return u;
}
__device__ __forceinline__ void mma1688_tf32(float* c, const uint32_t* a,
                                             uint32_t b0, uint32_t b1){
    asm volatile(
        "mma.sync.aligned.m16n8k8.row.col.f32.tf32.tf32.f32 "
        "{%0,%1,%2,%3}, {%4,%5,%6,%7}, {%8,%9}, {%0,%1,%2,%3};"
        : "+f"(c[0]), "+f"(c[1]), "+f"(c[2]), "+f"(c[3])
        : "r"(a[0]), "r"(a[1]), "r"(a[2]), "r"(a[3]), "r"(b0), "r"(b1));
}

template<int MODE, int PREC>
__global__ void __launch_bounds__(256)
tf32_gemm(const float* __restrict__ A, const float* __restrict__ Bm,
          int N, int K, int Kc,
          const float* __restrict__ bias, float* __restrict__ out0,
          const float* __restrict__ aux, int s_aux, double* accd,
          const float* __restrict__ pA){
    extern __shared__ float tsm[];
    float* AsH = tsm;
    float* BsH = tsm + 128*TS;
    float* AsL = tsm + 2*128*TS;
    float* BsL = tsm + 3*128*TS;
    __shared__ float red[256];
    const int t = threadIdx.x, wid = t >> 5, lane = t & 31;
    const int g = lane >> 2, ti = lane & 3;
    const int m0 = blockIdx.x * 128, n0 = blockIdx.y * 128;
    const int kBeg = blockIdx.z * Kc, kEnd = min(K, kBeg + Kc);
    const int wm = wid >> 1, wn = wid & 1;
    const int r0 = wm*32, c0 = wn*64;

    float C[2][8][4];
    #pragma unroll
    for (int mi = 0; mi < 2; mi++)
        #pragma unroll
        for (int ni = 0; ni < 8; ni++)
            #pragma unroll
            for (int q = 0; q < 4; q++) C[mi][ni][q] = 0.f;

    for (int k0 = kBeg; k0 < kEnd; k0 += 16){
        #pragma unroll
        for (int i = 0; i < 2; i++){
            int li = t + i*256;
            int row = li >> 2, c = (li & 3) * 4;
            float4 va = *reinterpret_cast<const float4*>(&A[(size_t)(m0+row)*K + k0 + c]);
            float4 vb = make_float4(0.f,0.f,0.f,0.f);
            if (n0 + row < N)
                vb = *reinterpret_cast<const float4*>(&Bm[(size_t)(n0+row)*K + k0 + c]);
            float av[4] = {va.x,va.y,va.z,va.w};
            float bv[4] = {vb.x,vb.y,vb.z,vb.w};
            if (MODE == 7){
                #pragma unroll
                for (int q = 0; q < 4; q++){
                    int col = k0 + c + q;
                    float v = av[q] + pA[col];
                    av[q] = sp_(v);
                    g_d1[(size_t)(m0+row)*HAE + col] = sig_(v);
                }
            }
            #pragma unroll
            for (int q = 0; q < 4; q++){
                uint32_t ah = to_tf32(av[q]);
                uint32_t bh = to_tf32(bv[q]);
                AsH[row*TS + c + q] = __uint_as_float(ah);
                BsH[row*TS + c + q] = __uint_as_float(bh);
                if (PREC){
                    AsL[row*TS + c + q] = __uint_as_float(to_tf32(av[q] - __uint_as_float(ah)));
                    BsL[row*TS + c + q] = __uint_as_float(to_tf32(bv[q] - __uint_as_float(bh)));
                }
            }
        }
        __syncthreads();
        #pragma unroll
        for (int kk = 0; kk < 16; kk += 8){
            uint32_t AfH[2][4], AfL[2][4];
            #pragma unroll
            for (int mi = 0; mi < 2; mi++){
                const int ao = (r0 + mi*16 + g)*TS + kk;
                AfH[mi][0] = __float_as_uint(AsH[ao + ti]);
                AfH[mi][1] = __float_as_uint(AsH[ao + 8*TS + ti]);
                AfH[mi][2] = __float_as_uint(AsH[ao + ti + 4]);
                AfH[mi][3] = __float_as_uint(AsH[ao + 8*TS + ti + 4]);
                if (PREC){
                    AfL[mi][0] = __float_as_uint(AsL[ao + ti]);
                    AfL[mi][1] = __float_as_uint(AsL[ao + 8*TS + ti]);
                    AfL[mi][2] = __float_as_uint(AsL[ao + ti + 4]);
                    AfL[mi][3] = __float_as_uint(AsL[ao + 8*TS + ti + 4]);
                }
            }
            #pragma unroll
            for (int ni = 0; ni < 8; ni++){
                const int bo = (c0 + ni*8 + g)*TS + kk;
                uint32_t bH0 = __float_as_uint(BsH[bo + ti]);
                uint32_t bH1 = __float_as_uint(BsH[bo + ti + 4]);
                mma1688_tf32(C[0][ni], AfH[0], bH0, bH1);
                mma1688_tf32(C[1][ni], AfH[1], bH0, bH1);
                if (PREC){
                    uint32_t bL0 = __float_as_uint(BsL[bo + ti]);
                    uint32_t bL1 = __float_as_uint(BsL[bo + ti + 4]);
                    mma1688_tf32(C[0][ni], AfL[0], bH0, bH1);
                    mma1688_tf32(C[1][ni], AfL[1], bH0, bH1);
                    mma1688_tf32(C[0][ni], AfH[0], bL0, bL1);
                    mma1688_tf32(C[1][ni], AfH[1], bL0, bL1);
                }
            }
        }
        __syncthreads();
    }

    if (MODE == 5){
        #pragma unroll
        for (int mi = 0; mi < 2; mi++){
            const int r = m0 + r0 + mi*16 + g;
            #pragma unroll
            for (int ni = 0; ni < 8; ni++){
                const int gn = n0 + c0 + ni*8 + 2*ti;
                if (gn < N){
                    float b0v = bias[gn], b1v = bias[gn+1];
                    size_t oA = (size_t)r*HAE + gn;
                    size_t oB = (size_t)(r+8)*HAE + gn;
                    out0[oA]   = sp_(C[mi][ni][0] + b0v);
                    out0[oA+1] = sp_(C[mi][ni][1] + b1v);
                    out0[oB]   = sp_(C[mi][ni][2] + b0v);
                    out0[oB+1] = sp_(C[mi][ni][3] + b1v);
                }
            }
        }
    } else if (MODE == 7){
        #pragma unroll
        for (int mi = 0; mi < 2; mi++){
            const int r = m0 + r0 + mi*16 + g;
            #pragma unroll
            for (int ni = 0; ni < 8; ni++){
                const int gn = c0 + ni*8 + 2*ti;
                float b0v = bias[gn], b1v = bias[gn+1];
                float v00 = C[mi][ni][0] + b0v, v01 = C[mi][ni][1] + b1v;
                float v10 = C[mi][ni][2] + b0v, v11 = C[mi][ni][3] + b1v;
                size_t oA = (size_t)r*HAE + gn;
                size_t oB = (size_t)(r+8)*HAE + gn;
                out0[oA]   = sp_(v00); out0[oA+1] = sp_(v01);
                out0[oB]   = sp_(v10); out0[oB+1] = sp_(v11);
                *reinterpret_cast<__nv_bfloat162*>(&g_d2b[oA]) =
                    __floats2bfloat162_rn(sig_(v00), sig_(v01));
                *reinterpret_cast<__nv_bfloat162*>(&g_d2b[oB]) =
                    __floats2bfloat162_rn(sig_(v10), sig_(v11));
            }
        }
    } else if (MODE == 1){
        float loc = 0.f;
        #pragma unroll
        for (int mi = 0; mi < 2; mi++){
            const int r = m0 + r0 + mi*16 + g;
            #pragma unroll
            for (int ni = 0; ni < 8; ni++){
                const int gn = n0 + c0 + ni*8 + 2*ti;
                if (gn < N){
                    float b0v = bias[gn], b1v = bias[gn+1];
                    float d0 = aux[(size_t)r*s_aux + gn]       - (C[mi][ni][0] + b0v);
                    float d1 = aux[(size_t)r*s_aux + gn + 1]   - (C[mi][ni][1] + b1v);
                    float d2 = aux[(size_t)(r+8)*s_aux + gn]   - (C[mi][ni][2] + b0v);
                    float d3 = aux[(size_t)(r+8)*s_aux + gn+1] - (C[mi][ni][3] + b1v);
                    loc += d0*d0 + d1*d1 + d2*d2 + d3*d3;
                }
            }
        }
        red[t] = loc; __syncthreads();
        for (int st = 128; st > 0; st >>= 1){ if (t < st) red[t] += red[t+st]; __syncthreads(); }
        if (t == 0) atomicAdd(accd, (double)red[0]);
    } else { // MODE 6
        #pragma unroll
        for (int mi = 0; mi < 2; mi++){
            const int r = m0 + r0 + mi*16 + g;
            #pragma unroll
            for (int ni = 0; ni < 8; ni++){
                const int gn = n0 + c0 + ni*8 + 2*ti;
                if (gn < N){
                    atomicAdd(&out0[(size_t)r*HAE + gn],       C[mi][ni][0]);
                    atomicAdd(&out0[(size_t)r*HAE + gn + 1],   C[mi][ni][1]);
                    atomicAdd(&out0[(size_t)(r+8)*HAE + gn],   C[mi][ni][2]);
                    atomicAdd(&out0[(size_t)(r+8)*HAE + gn+1], C[mi][ni][3]);
                }
            }
        }
    }
}

#define SM1 (2*128*TS*4)
#define SM3 (4*128*TS*4)

// ---------------- setup: V + scalarT + init (one kernel) ----------------
__global__ void setup_k(const float* __restrict__ ew3, const float* __restrict__ ew2,
                        const float* __restrict__ ssc){
    int bid = blockIdx.x, t = threadIdx.x;
    if (bid < 1920){
        int idx = bid*256 + t;
        int bb = idx & 127;
        int n  = idx >> 7;
        int l  = n >> 7;
        int a  = n & 127;
        g_Vb[idx] = __float2bfloat16(ew3[l*HAE + bb] * ew2[bb*HAE + a]);
    } else if (bid < 1984){
        int t2 = (bid - 1920)*256 + t;
        if (t2 < SZv*Hh) g_l2[t2] = 0.5f;
        if (t2 < HAE*HAE) g_G1[t2] = 0.f;
        if (t2 == 0) g_comp = 0.0;
        if (t2 < NTRI){
            int rem = t2, i = 0;
            while (rem >= 32 - i){ rem -= 32 - i; i++; }
            g_iu0[t2] = i; g_iu1[t2] = i + rem;
        }
    } else {
        int gid = (bid - 1984)*256 + t;
        int w = gid >> 5, lane = gid & 31;
        if (w >= Dd*Hh*SZv) return;
        int i = w / (Hh*SZv);
        int rem = w % (Hh*SZv);
        int h = rem / SZv;
        int s = rem % SZv;
        const float* row = &ssc[(((size_t)(i*Hh+h)*SZv)+s)*SZv];
        float a = 0.f;
        for (int k = lane; k < SZv; k += 32) a += row[k];
        #pragma unroll
        for (int o = 16; o > 0; o >>= 1) a += __shfl_down_sync(0xffffffffu, a, o);
        if (lane == 0) g_scalarT[(i*SZv+s)*Hh + h] = a;
    }
}

__global__ void cvt_G1(){
    int t = blockIdx.x*256 + threadIdx.x;
    if (t < HAE*HAE) g_G1b[t] = __float2bfloat16(g_G1[t]);
}

// ---------------- raw / groupnorm (+ per-iter zeroing, + out-dot) --------
__global__ void __launch_bounds__(256)
build_raw_fused(const float* __restrict__ x, const float* __restrict__ ln_g,
                const float* __restrict__ ln_b, int do_out){
    __shared__ float nx[32];
    __shared__ float rw[SZv];
    __shared__ float sc[SZv*2];
    __shared__ float redA[256], redB[256];
    int b = blockIdx.x, t = threadIdx.x;
    int gid = b*256 + t;
    if (gid < Bb*HAE) g_accE[gid] = 0.f;
    if (gid < Lv*Lv){ g_zTz[gid] = 0.f; g_az[gid] = 0.f; }
    if (gid == Bb*HAE){ g_mse = 0.0; g_jsum = 0.0; }

    float s0 = 0.f, s1 = 0.f;
    if (do_out){
        for (int i = t; i < SZv*2; i += 256) sc[i] = g_scaled[i];
        __syncthreads();
        const float* rwg = &g_raw[(size_t)b*SZv];
        for (int i = t; i < SZv; i += 256){
            float v = rwg[i];
            s0 += v*sc[i*2];
            s1 += v*sc[i*2+1];
        }
        s0 = blk_reduce(s0, redA, t);
        s1 = blk_reduce(s1, redA, t);
    }
    if (t < NIi) nx[t] = x[b*NIi + t];
    else if (t == NIi)   nx[t] = s0;
    else if (t == NIi+1) nx[t] = s1;
    __syncthreads();
    float s = 0.f, ss = 0.f;
    for (int idx = t; idx < SZv; idx += 256){
        float v;
        if (idx < NTRI){
            int i = g_iu0[idx], j = g_iu1[idx];
            v = (i == j) ? nx[i] : nx[i] + nx[j];
        } else if (idx < 2*NTRI){
            int k = idx - NTRI;
            v = nx[g_iu0[k]] * nx[g_iu1[k]];
        } else if (idx < 2*NTRI + 32){
            v = sinf(nx[idx - 2*NTRI]);
        } else {
            v = cosf(nx[idx - 2*NTRI - 32]);
        }
        rw[idx] = v; s += v; ss += v*v;
    }
    redA[t] = s; redB[t] = ss; __syncthreads();
    for (int st = 128; st > 0; st >>= 1){
        if (t < st){ redA[t] += redA[t+st]; redB[t] += redB[t+st]; }
        __syncthreads();
    }
    float mean = redA[0] / SZv;
    float var  = redB[0] / SZv - mean*mean;
    float rstd = rsqrtf(var + 1e-5f);
    for (int idx = t; idx < SZv; idx += 256){
        float v = rw[idx];
        g_raw[(size_t)b*SZv + idx] = v;
        g_xn [(size_t)b*SZv + idx] = (v - mean)*rstd*ln_g[idx] + ln_b[idx];
    }
}

// ---------------- selection: A-chain (redundant per block) + B dot ------
__global__ void __launch_bounds__(256)
sel_AB(const float* __restrict__ qw, const float* __restrict__ qb,
       const float* __restrict__ sq,
       const float* __restrict__ sl1, const float* __restrict__ sg1,
       const float* __restrict__ sb1,
       const float* __restrict__ sl2, int iter){
    __shared__ float gsa[900], lsa[900];
    __shared__ float sel[2][30], h1s[2][64];
    __shared__ float sc8[8];
    __shared__ float h1f[128];
    int t = threadIdx.x;
    qw  += iter*900;  qb  += iter*30;   sq  += iter*60;
    sl1 += iter*2*64*30; sg1 += iter*128; sb1 += iter*128;
    for (int i = t; i < 900; i += 256) gsa[i] = g_zTz[i] / fmaxf(g_az[i], 1e-5f);
    __syncthreads();
    for (int idx = t; idx < 900; idx += 256){
        int i = idx / 30, j = idx % 30;
        float s = qb[j];
        #pragma unroll
        for (int k = 0; k < 30; k++) s += gsa[i*30+k]*qw[j*30+k];
        lsa[idx] = s;
    }
    __syncthreads();
    if (t < 60){
        int h = t / 30, i = t % 30;
        float s = 0.f;
        #pragma unroll
        for (int j = 0; j < 30; j++) s += lsa[i*30+j]*sq[h*30+j];
        sel[h][i] = s;
    }
    __syncthreads();
    if (t < 128){
        int h = t >> 6, o = t & 63;
        float s = 0.f;
        #pragma unroll
        for (int l = 0; l < 30; l++) s += sl1[(h*64+o)*30+l]*sel[h][l];
        h1s[h][o] = s;
    }
    __syncthreads();
    if (t < 2){
        float m = 0.f;
        for (int o = 0; o < 64; o++) m += h1s[t][o];
        m *= (1.f/64.f);
        float v = 0.f;
        for (int o = 0; o < 64; o++){ float d = h1s[t][o]-m; v += d*d; }
        v *= (1.f/64.f);
        sc8[t*2] = m; sc8[t*2+1] = rsqrtf(v + 1e-5f);
    }
    __syncthreads();
    if (t < 128){
        int h = t >> 6, o = t & 63;
        h1f[t] = sp_((h1s[h][o]-sc8[h*2])*sc8[h*2+1]*sg1[h*64+o] + sb1[h*64+o]);
    }
    __syncthreads();
    // B: warp-per-output dot over sl2
    int w = blockIdx.x*8 + (t >> 5);
    int lane = t & 31;
    if (w >= Hh*SZv) return;
    int h = w / SZv, s = w % SZv;
    const float* wp = &sl2[((size_t)iter*Hh*SZv + w)*64];
    float a = wp[lane]*h1f[h*64+lane] + wp[lane+32]*h1f[h*64+lane+32];
    #pragma unroll
    for (int o = 16; o > 0; o >>= 1) a += __shfl_down_sync(0xffffffffu, a, o);
    if (lane == 0) g_buf[h*SZv + s] = a;
}

// ---------------- phase C (1 block) ----------------
__global__ void __launch_bounds__(256)
sel_C(const float* __restrict__ sg2, const float* __restrict__ sb2,
      const float* __restrict__ son, int iter){
    __shared__ float buf[2][SZv];
    __shared__ float red[256];
    int t = threadIdx.x;
    sg2 += iter*2*SZv; sb2 += iter*2*SZv;
    son += iter*2*2*SZv;
    for (int i = t; i < 2*SZv; i += 256) buf[i/SZv][i%SZv] = g_buf[i];
    __syncthreads();
    for (int h = 0; h < 2; h++){
        float s = 0.f, ss = 0.f;
        for (int i = t; i < SZv; i += 256){ float v = buf[h][i]; s += v; ss += v*v; }
        s  = blk_reduce(s, red, t);
        ss = blk_reduce(ss, red, t);
        float mean = s*(1.f/SZv);
        float var  = ss*(1.f/SZv) - mean*mean;
        float rstd = rsqrtf(var + 1e-5f);
        float mx = -1e30f;
        for (int i = t; i < SZv; i += 256){
            float v = (buf[h][i]-mean)*rstd*sg2[h*SZv+i] + sb2[h*SZv+i];
            buf[h][i] = v;
            mx = fmaxf(mx, v);
        }
        mx = blk_reduce_max(mx, red, t);
        float se = 0.f;
        for (int i = t; i < SZv; i += 256){
            float e = expf(buf[h][i]-mx);
            buf[h][i] = e;
            se += e;
        }
        se = blk_reduce(se, red, t);
        float inv = 1.f/se;
        for (int i = t; i < SZv; i += 256) buf[h][i] *= inv;
        __syncthreads();
    }
    float d0 = 0.f, d1 = 0.f;
    for (int s = t; s < SZv; s += 256){
        float il = g_l2[s*2]*g_l2[s*2+1];
        d0 += son[s]*il + son[SZv+s]*buf[0][s];
        d1 += son[2*SZv+s]*il + son[2*SZv+SZv+s]*buf[1][s];
    }
    d0 = blk_reduce(d0, red, t);
    d1 = blk_reduce(d1, red, t);
    float on0 = sig_(d0), on1 = sig_(d1);
    float e00 = 0.f, e01 = 0.f, e10 = 0.f, e11 = 0.f;
    for (int s = t; s < SZv; s += 256){
        float o0 = on0*buf[0][s], o1 = on1*buf[1][s];
        float sc0 = o0*g_scalarT[(iter*SZv+s)*2+0];
        float sc1 = o1*g_scalarT[(iter*SZv+s)*2+1];
        if (fabsf(sc0) <= 1e-14f) sc0 = 1e-14f;
        if (fabsf(sc1) <= 1e-14f) sc1 = 1e-14f;
        g_scaled[s*2]   = sc0;
        g_scaled[s*2+1] = sc1;
        float l20 = fmaxf(o0, 1e-14f), l21 = fmaxf(o1, 1e-14f);
        g_l2[s*2] = l20; g_l2[s*2+1] = l21;
        float lg0 = logf(l20 + 1e-5f), lg1 = logf(l21 + 1e-5f);
        e00 += l20*lg0; e01 += l20*lg1;
        e10 += l21*lg0; e11 += l21*lg1;
    }
    e00 = blk_reduce(e00, red, t);
    e01 = blk_reduce(e01, red, t);
    e10 = blk_reduce(e10, red, t);
    e11 = blk_reduce(e11, red, t);
    if (t == 0){
        float g00 = -e00, g01 = -e01, g10 = -e10, g11 = -e11;
        float g = 0.01f*0.5f*(g00+g11) - 0.25f*(g01+g10);
        double cst = g_mse/((double)Bb*SZv) + g_jsum/((double)Lv*(double)Bb*(double)SZv);
        g_comp += (double)g + cst;
    }
}

// ---------------- final: out[b] = dot(raw_b, sc0+sc1); out[Bb] = comp ---
__global__ void __launch_bounds__(256)
finalize_dot(float* __restrict__ out){
    __shared__ float sc[SZv];
    int t = threadIdx.x;
    for (int i = t; i < SZv; i += 256) sc[i] = g_scaled[i*2] + g_scaled[i*2+1];
    __syncthreads();
    int warp = t >> 5, lane = t & 31;
    int b = blockIdx.x*8 + warp;
    const float* rw = &g_raw[(size_t)b*SZv];
    float s = 0.f;
    for (int i = lane; i < SZv; i += 32) s += rw[i]*sc[i];
    #pragma unroll
    for (int o = 16; o > 0; o >>= 1) s += __shfl_down_sync(0xffffffffu, s, o);
    if (lane == 0) out[b] = s;
    if (blockIdx.x == 0 && t == 0) out[Bb] = (float)g_comp;
}

// ---------------- host ----------------
extern "C" void kernel_launch(void* const* d_in, const int* in_sizes, int n_in,
                              void* d_out, int out_size) {
    const float* x    = (const float*)d_in[0];
    const float* ln_g = (const float*)d_in[1];
    const float* ln_b = (const float*)d_in[2];
    const float* ew1  = (const float*)d_in[3];
    const float* eb1  = (const float*)d_in[4];
    const float* ew2  = (const float*)d_in[5];
    const float* eb2  = (const float*)d_in[6];
    const float* ew3  = (const float*)d_in[7];
    const float* eb3  = (const float*)d_in[8];
    const float* dw1  = (const float*)d_in[9];
    const float* db1  = (const float*)d_in[10];
    const float* dw2  = (const float*)d_in[11];
    const float* db2  = (const float*)d_in[12];
    const float* dw3  = (const float*)d_in[13];
    const float* db3  = (const float*)d_in[14];
    const float* qw   = (const float*)d_in[15];
    const float* qb   = (const float*)d_in[16];
    const float* sq   = (const float*)d_in[17];
    const float* sl1  = (const float*)d_in[18];
    const float* sg1  = (const float*)d_in[19];
    const float* sb1  = (const float*)d_in[20];
    const float* sl2  = (const float*)d_in[21];
    const float* sg2  = (const float*)d_in[22];
    const float* sb2  = (const float*)d_in[23];
    const float* ssc  = (const float*)d_in[24];
    const float* son  = (const float*)d_in[25];
    float* out = (float*)d_out;

    float *pXn, *pH2, *pDh1, *pDh2, *pG1, *pAccE;
    double *pMse;
    cudaGetSymbolAddress((void**)&pXn,  g_xn);
    cudaGetSymbolAddress((void**)&pH2,  g_h2e);
    cudaGetSymbolAddress((void**)&pDh1, g_dh1);
    cudaGetSymbolAddress((void**)&pDh2, g_dh2);
    cudaGetSymbolAddress((void**)&pG1,  g_G1);
    cudaGetSymbolAddress((void**)&pAccE,g_accE);
    cudaGetSymbolAddress((void**)&pMse, g_mse);

    cudaFuncSetAttribute(hmma_z, cudaFuncAttributeMaxDynamicSharedMemorySize, HMMA_SMEM);

    setup_k<<<2544,256>>>(ew3, ew2, ssc);
    tf32_gemm<6,0><<<dim3(1,1,35),256,SM1>>>(ew1, ew1, HAE, SZv, 32,
        nullptr, pG1, nullptr, 0, nullptr, nullptr);
    cvt_G1<<<64,256>>>();

    for (int iter = 0; iter < Dd; iter++){
        build_raw_fused<<<Bb,256>>>(x, ln_g, ln_b, iter > 0 ? 1 : 0);
        // enc1: xn @ ew1^T -> accE (split-K atomics)
        tf32_gemm<6,1><<<dim3(16,1,7),256,SM3>>>(pXn, ew1, HAE, SZv, 160,
            nullptr, pAccE, nullptr, 0, nullptr, nullptr);
        // enc2 (MODE 7): A-staging applies enc1 epi; epilogue h2e + d2b
        tf32_gemm<7,1><<<dim3(16,1,1),256,SM3>>>(pAccE, ew2, HAE, HAE, HAE,
            eb2, pH2, nullptr, 0, nullptr, eb1);
        // merged: TM+JQ (480 blocks) || z+zstats+dec1 (128 blocks)
        hmma_z<<<608, 256, HMMA_SMEM>>>(ew3, eb3, dw1, db1);
        // dec2: dh1 @ dw2^T -> dh2 (sp)
        tf32_gemm<5,1><<<dim3(16,1,1),256,SM3>>>(pDh1, dw2, HAE, HAE, HAE,
            db2, pDh2, nullptr, 0, nullptr, nullptr);
        // dec3 + fused MSE
        tf32_gemm<1,1><<<dim3(16,9,1),256,SM3>>>(pDh2, dw3, SZv, HAE, HAE,
            db3, nullptr, pXn, SZv, pMse, nullptr);
        // selection: A-chain + B dot, then C
        sel_AB<<<(Hh*SZv+7)/8,256>>>(qw, qb, sq, sl1, sg1, sb1, sl2, iter);
        sel_C<<<1,256>>>(sg2, sb2, son, iter);
    }
    finalize_dot<<<Bb/8,256>>>(out);
}

// round 16
// speedup vs baseline: 1.2616x; 1.0655x over previous
#include <cuda_runtime.h>
#include <cuda_bf16.h>
#include <math.h>
#include <stdint.h>

#define Bb   2048
#define NIi  30
#define Hh   2
#define Dd   2
#define HAE  128
#define SZv  1120
#define Lv   30
#define NTRI 528
#define NV   (Lv*HAE)   /* 3840 */

// ---------------- device scratch ----------------
__device__ float g_raw[Bb*SZv];
__device__ float g_xn [Bb*SZv];
__device__ float g_d1[Bb*HAE];
__device__ float g_h2e[Bb*HAE];
__device__ float g_dh1[Bb*HAE], g_dh2[Bb*HAE];
__device__ float g_accE[Bb*HAE];
__device__ float g_G1[HAE*HAE];
__device__ __nv_bfloat16 g_G1b[HAE*HAE];
__device__ __nv_bfloat16 g_Vb[NV*HAE];
__device__ __nv_bfloat16 g_d2b[Bb*HAE];
__device__ float g_scalarT[Dd*SZv*Hh];
__device__ float g_zTz[Lv*Lv], g_az[Lv*Lv];
__device__ float g_l2[SZv*Hh];
__device__ float g_scaled[SZv*Hh];
__device__ float g_buf[Hh*SZv];
__device__ double g_mse, g_jsum, g_comp;
__device__ int g_iu0[NTRI], g_iu1[NTRI];

__device__ __forceinline__ float sp_(float x){ return fmaxf(x,0.f) + log1pf(__expf(-fabsf(x))); }
__device__ __forceinline__ float sig_(float x){ return 1.f/(1.f+__expf(-x)); }

__device__ __forceinline__ float blk_reduce(float v, float* red, int t){
    red[t]=v; __syncthreads();
    for(int st=128;st>0;st>>=1){ if(t<st) red[t]+=red[t+st]; __syncthreads(); }
    float r=red[0]; __syncthreads();
    return r;
}
__device__ __forceinline__ float blk_reduce_max(float v, float* red, int t){
    red[t]=v; __syncthreads();
    for(int st=128;st>0;st>>=1){ if(t<st) red[t]=fmaxf(red[t],red[t+st]); __syncthreads(); }
    float r=red[0]; __syncthreads();
    return r;
}

// ================= HMMA helpers ==========
#define HS 136
#define HMMA_SMEM (2*128*HS*2)
#define ZR 16

__device__ __forceinline__ void mma16816(float* c, const uint32_t* a,
                                         uint32_t b0, uint32_t b1){
    asm volatile(
        "mma.sync.aligned.m16n8k16.row.col.f32.bf16.bf16.f32 "
        "{%0,%1,%2,%3}, {%4,%5,%6,%7}, {%8,%9}, {%0,%1,%2,%3};"
        : "+f"(c[0]), "+f"(c[1]), "+f"(c[2]), "+f"(c[3])
        : "r"(a[0]), "r"(a[1]), "r"(a[2]), "r"(a[3]), "r"(b0), "r"(b1));
}
__device__ __forceinline__ void ldsm_x4(uint32_t* r, uint32_t addr){
    asm volatile("ldmatrix.sync.aligned.m8n8.x4.shared.b16 {%0,%1,%2,%3}, [%4];"
        : "=r"(r[0]), "=r"(r[1]), "=r"(r[2]), "=r"(r[3]) : "r"(addr));
}
__device__ __forceinline__ void ldsm_x2(uint32_t& r0, uint32_t& r1, uint32_t addr){
    asm volatile("ldmatrix.sync.aligned.m8n8.x2.shared.b16 {%0,%1}, [%2];"
        : "=r"(r0), "=r"(r1) : "r"(addr));
}

// ---- TM+JQ body ----
__device__ void hmma_body(__nv_bfloat16* As, __nv_bfloat16* Bs, float* red,
                          int bx, int by){
    const int t = threadIdx.x, wid = t >> 5, lane = t & 31;
    const int g = lane >> 2, ti = lane & 3;
    const int m0 = bx * 128;

    const __nv_bfloat16* Ag = g_d2b + (size_t)m0*HAE;
    const __nv_bfloat16* Bg = g_Vb + (size_t)by*128*HAE;

    for (int i = t; i < 2048; i += 256){
        int row = i >> 4, col = (i & 15) * 8;
        *reinterpret_cast<uint4*>(&As[row*HS + col]) =
            *reinterpret_cast<const uint4*>(&Ag[(size_t)row*HAE + col]);
        *reinterpret_cast<uint4*>(&Bs[row*HS + col]) =
            *reinterpret_cast<const uint4*>(&Bg[(size_t)row*HAE + col]);
    }
    __syncthreads();

    const int wm = wid >> 1, wn = wid & 1;
    const int r0 = wm*32, c0 = wn*64;
    float C[2][8][4];
    #pragma unroll
    for (int mi = 0; mi < 2; mi++)
        #pragma unroll
        for (int ni = 0; ni < 8; ni++)
            #pragma unroll
            for (int q = 0; q < 4; q++) C[mi][ni][q] = 0.f;

    const uint32_t asu = (uint32_t)__cvta_generic_to_shared(As);
    const uint32_t bsu = (uint32_t)__cvta_generic_to_shared(Bs);
    const uint32_t aBase = asu + ((uint32_t)((r0 + (lane & 15))*HS + ((lane >> 4) << 3)) << 1);
    const uint32_t bBase = bsu + ((uint32_t)((c0 + (lane & 7))*HS + ((lane & 8) ? 8 : 0)) << 1);

    #pragma unroll
    for (int kk = 0; kk < 8; kk++){
        uint32_t Af[2][4];
        ldsm_x4(Af[0], aBase + kk*32);
        ldsm_x4(Af[1], aBase + 16*HS*2 + kk*32);
        #pragma unroll
        for (int ni = 0; ni < 8; ni++){
            uint32_t b0, b1;
            ldsm_x2(b0, b1, bBase + ni*(8*HS*2) + kk*32);
            mma16816(C[0][ni], Af[0], b0, b1);
            mma16816(C[1][ni], Af[1], b0, b1);
        }
    }
    __syncthreads();

    #pragma unroll
    for (int mi = 0; mi < 2; mi++){
        const int rl = r0 + mi*16 + g;
        const int r  = m0 + rl;
        #pragma unroll
        for (int ni = 0; ni < 8; ni++){
            const int a = c0 + ni*8 + ti*2;
            float2 dA = *reinterpret_cast<const float2*>(&g_d1[(size_t)r*HAE + a]);
            float2 dB = *reinterpret_cast<const float2*>(&g_d1[(size_t)(r+8)*HAE + a]);
            *reinterpret_cast<__nv_bfloat162*>(&As[rl*HS + a]) =
                __floats2bfloat162_rn(C[mi][ni][0]*dA.x, C[mi][ni][1]*dA.y);
            *reinterpret_cast<__nv_bfloat162*>(&As[(rl+8)*HS + a]) =
                __floats2bfloat162_rn(C[mi][ni][2]*dB.x, C[mi][ni][3]*dB.y);
        }
    }
    for (int i = t; i < 2048; i += 256){
        int row = i >> 4, col = (i & 15) * 8;
        *reinterpret_cast<uint4*>(&Bs[row*HS + col]) =
            *reinterpret_cast<const uint4*>(&g_G1b[(size_t)row*HAE + col]);
    }
    __syncthreads();

    #pragma unroll
    for (int mi = 0; mi < 2; mi++)
        #pragma unroll
        for (int ni = 0; ni < 8; ni++)
            #pragma unroll
            for (int q = 0; q < 4; q++) C[mi][ni][q] = 0.f;
    #pragma unroll
    for (int kk = 0; kk < 8; kk++){
        uint32_t Af[2][4];
        ldsm_x4(Af[0], aBase + kk*32);
        ldsm_x4(Af[1], aBase + 16*HS*2 + kk*32);
        #pragma unroll
        for (int ni = 0; ni < 8; ni++){
            uint32_t b0, b1;
            ldsm_x2(b0, b1, bBase + ni*(8*HS*2) + kk*32);
            mma16816(C[0][ni], Af[0], b0, b1);
            mma16816(C[1][ni], Af[1], b0, b1);
        }
    }

    float loc = 0.f;
    #pragma unroll
    for (int mi = 0; mi < 2; mi++){
        const int rl = r0 + mi*16 + g;
        #pragma unroll
        for (int ni = 0; ni < 8; ni++){
            const int a = c0 + ni*8 + ti*2;
            __nv_bfloat162 mA = *reinterpret_cast<const __nv_bfloat162*>(&As[rl*HS + a]);
            __nv_bfloat162 mB = *reinterpret_cast<const __nv_bfloat162*>(&As[(rl+8)*HS + a]);
            loc += C[mi][ni][0]*__bfloat162float(mA.x)
                 + C[mi][ni][1]*__bfloat162float(mA.y)
                 + C[mi][ni][2]*__bfloat162float(mB.x)
                 + C[mi][ni][3]*__bfloat162float(mB.y);
        }
    }
    red[t] = loc; __syncthreads();
    for (int st = 128; st > 0; st >>= 1){ if (t < st) red[t] += red[t+st]; __syncthreads(); }
    if (t == 0) atomicAdd(&g_jsum, (double)red[0]);
}

// ---- z + zstats + dec1 body ----
__device__ void zdec1_body(float* sm, int zb,
                           const float* __restrict__ ew3, const float* __restrict__ eb3,
                           const float* __restrict__ dw1, const float* __restrict__ db1){
    float* hs = sm;
    float* w3 = hs + ZR*129;
    float* zs = w3 + 30*129;
    int t = threadIdx.x;
    int b0 = zb * ZR;
    for (int i = t; i < ZR*HAE; i += 256) hs[(i>>7)*129 + (i&127)] = g_h2e[(size_t)b0*HAE + i];
    for (int i = t; i < 30*HAE; i += 256) w3[(i>>7)*129 + (i&127)] = ew3[i];
    __syncthreads();
    for (int idx = t; idx < ZR*30; idx += 256){
        int r = idx / 30, l = idx % 30;
        float s = eb3[l];
        #pragma unroll 8
        for (int k = 0; k < HAE; k++) s += hs[r*129 + k]*w3[l*129 + k];
        zs[r*31 + l] = s;
    }
    __syncthreads();
    for (int idx = t; idx < 900; idx += 256){
        int i = idx / 30, j = idx % 30;
        float a = 0.f, ab = 0.f;
        #pragma unroll
        for (int r = 0; r < ZR; r++){
            float zi = zs[r*31 + i], zj = zs[r*31 + j];
            a  += zi*zj;
            ab += fabsf(zi)*fabsf(zj);
        }
        atomicAdd(&g_zTz[idx], a);
        atomicAdd(&g_az[idx], ab);
    }
    for (int idx = t; idx < ZR*HAE; idx += 256){
        int r = idx >> 7, o = idx & 127;
        float s = db1[o];
        #pragma unroll
        for (int l = 0; l < 30; l++) s += zs[r*31 + l]*dw1[o*30 + l];
        g_dh1[(size_t)(b0+r)*HAE + o] = sp_(s);
    }
}

__global__ void __launch_bounds__(256)
hmma_z(const float* __restrict__ ew3, const float* __restrict__ eb3,
       const float* __restrict__ dw1, const float* __restrict__ db1){
    extern __shared__ char dyn[];
    __shared__ float red[256];
    if (blockIdx.x < 480){
        __nv_bfloat16* As = reinterpret_cast<__nv_bfloat16*>(dyn);
        hmma_body(As, As + 128*HS, red, blockIdx.x & 15, blockIdx.x >> 4);
    } else {
        zdec1_body(reinterpret_cast<float*>(dyn), blockIdx.x - 480, ew3, eb3, dw1, db1);
    }
}

// ================= TF32 GEMM (register-prefetch pipelined) ==========
// MODE 1: mse accumulate; MODE 5: sp only; MODE 6: split-K atomicAdd
// MODE 7: enc2 — A-staging applies enc1 epilogue; epilogue h2e f32 + d2b bf16
#define TS 20

__device__ __forceinline__ uint32_t to_tf32(float x){
    uint32_t u;
    asm("cvt.rna.tf32.f32 %0, %1;" : "=r"(u) : "f"(x));
    return u;
}
__device__ __forceinline__ void mma1688_tf32(float* c, const uint32_t* a,
                                             uint32_t b0, uint32_t b1){
    asm volatile(
        "mma.sync.aligned.m16n8k8.row.col.f32.tf32.tf32.f32 "
        "{%0,%1,%2,%3}, {%4,%5,%6,%7}, {%8,%9}, {%0,%1,%2,%3};"
        : "+f"(c[0]), "+f"(c[1]), "+f"(c[2]), "+f"(c[3])
        : "r"(a[0]), "r"(a[1]), "r"(a[2]), "r"(a[3]), "r"(b0), "r"(b1));
}

template<int MODE, int PREC>
__global__ void __launch_bounds__(256)
tf32_gemm(const float* __restrict__ A, const float* __restrict__ Bm,
          int N, int K, int Kc,
          const float* __restrict__ bias, float* __restrict__ out0,
          const float* __restrict__ aux, int s_aux, double* accd,
          const float* __restrict__ pA){
    extern __shared__ float tsm[];
    float* AsH = tsm;
    float* BsH = tsm + 128*TS;
    float* AsL = tsm + 2*128*TS;
    float* BsL = tsm + 3*128*TS;
    __shared__ float red[256];
    const int t = threadIdx.x, wid = t >> 5, lane = t & 31;
    const int g = lane >> 2, ti = lane & 3;
    const int m0 = blockIdx.x * 128, n0 = blockIdx.y * 128;
    const int kBeg = blockIdx.z * Kc, kEnd = min(K, kBeg + Kc);
    const int wm = wid >> 1, wn = wid & 1;
    const int r0 = wm*32, c0 = wn*64;

    // per-thread staging coords (2 slices of the 128x16 tile)
    const int sr0 = t >> 2,        sc0 = (t & 3) * 4;          // slice 0
    const int sr1 = (t+256) >> 2,  sc1 = ((t+256) & 3) * 4;    // slice 1

    float C[2][8][4];
    #pragma unroll
    for (int mi = 0; mi < 2; mi++)
        #pragma unroll
        for (int ni = 0; ni < 8; ni++)
            #pragma unroll
            for (int q = 0; q < 4; q++) C[mi][ni][q] = 0.f;

    // prefetch first tile into registers
    float4 va[2], vb[2];
    {
        va[0] = *reinterpret_cast<const float4*>(&A[(size_t)(m0+sr0)*K + kBeg + sc0]);
        va[1] = *reinterpret_cast<const float4*>(&A[(size_t)(m0+sr1)*K + kBeg + sc1]);
        vb[0] = (n0 + sr0 < N) ? *reinterpret_cast<const float4*>(&Bm[(size_t)(n0+sr0)*K + kBeg + sc0])
                               : make_float4(0.f,0.f,0.f,0.f);
        vb[1] = (n0 + sr1 < N) ? *reinterpret_cast<const float4*>(&Bm[(size_t)(n0+sr1)*K + kBeg + sc1])
                               : make_float4(0.f,0.f,0.f,0.f);
    }

    for (int k0 = kBeg; k0 < kEnd; k0 += 16){
        // stage current registers -> smem
        #pragma unroll
        for (int i = 0; i < 2; i++){
            int row = (i == 0) ? sr0 : sr1;
            int c   = (i == 0) ? sc0 : sc1;
            float av[4] = {va[i].x, va[i].y, va[i].z, va[i].w};
            float bv[4] = {vb[i].x, vb[i].y, vb[i].z, vb[i].w};
            if (MODE == 7){
                #pragma unroll
                for (int q = 0; q < 4; q++){
                    int col = k0 + c + q;
                    float v = av[q] + pA[col];
                    av[q] = sp_(v);
                    g_d1[(size_t)(m0+row)*HAE + col] = sig_(v);
                }
            }
            #pragma unroll
            for (int q = 0; q < 4; q++){
                uint32_t ah = to_tf32(av[q]);
                uint32_t bh = to_tf32(bv[q]);
                AsH[row*TS + c + q] = __uint_as_float(ah);
                BsH[row*TS + c + q] = __uint_as_float(bh);
                if (PREC){
                    AsL[row*TS + c + q] = __uint_as_float(to_tf32(av[q] - __uint_as_float(ah)));
                    BsL[row*TS + c + q] = __uint_as_float(to_tf32(bv[q] - __uint_as_float(bh)));
                }
            }
        }
        __syncthreads();
        // issue next tile's loads (overlap with MMA below)
        if (k0 + 16 < kEnd){
            const int kn = k0 + 16;
            va[0] = *reinterpret_cast<const float4*>(&A[(size_t)(m0+sr0)*K + kn + sc0]);
            va[1] = *reinterpret_cast<const float4*>(&A[(size_t)(m0+sr1)*K + kn + sc1]);
            vb[0] = (n0 + sr0 < N) ? *reinterpret_cast<const float4*>(&Bm[(size_t)(n0+sr0)*K + kn + sc0])
                                   : make_float4(0.f,0.f,0.f,0.f);
            vb[1] = (n0 + sr1 < N) ? *reinterpret_cast<const float4*>(&Bm[(size_t)(n0+sr1)*K + kn + sc1])
                                   : make_float4(0.f,0.f,0.f,0.f);
        }
        #pragma unroll
        for (int kk = 0; kk < 16; kk += 8){
            uint32_t AfH[2][4], AfL[2][4];
            #pragma unroll
            for (int mi = 0; mi < 2; mi++){
                const int ao = (r0 + mi*16 + g)*TS + kk;
                AfH[mi][0] = __float_as_uint(AsH[ao + ti]);
                AfH[mi][1] = __float_as_uint(AsH[ao + 8*TS + ti]);
                AfH[mi][2] = __float_as_uint(AsH[ao + ti + 4]);
                AfH[mi][3] = __float_as_uint(AsH[ao + 8*TS + ti + 4]);
                if (PREC){
                    AfL[mi][0] = __float_as_uint(AsL[ao + ti]);
                    AfL[mi][1] = __float_as_uint(AsL[ao + 8*TS + ti]);
                    AfL[mi][2] = __float_as_uint(AsL[ao + ti + 4]);
                    AfL[mi][3] = __float_as_uint(AsL[ao + 8*TS + ti + 4]);
                }
            }
            #pragma unroll
            for (int ni = 0; ni < 8; ni++){
                const int bo = (c0 + ni*8 + g)*TS + kk;
                uint32_t bH0 = __float_as_uint(BsH[bo + ti]);
                uint32_t bH1 = __float_as_uint(BsH[bo + ti + 4]);
                mma1688_tf32(C[0][ni], AfH[0], bH0, bH1);
                mma1688_tf32(C[1][ni], AfH[1], bH0, bH1);
                if (PREC){
                    uint32_t bL0 = __float_as_uint(BsL[bo + ti]);
                    uint32_t bL1 = __float_as_uint(BsL[bo + ti + 4]);
                    mma1688_tf32(C[0][ni], AfL[0], bH0, bH1);
                    mma1688_tf32(C[1][ni], AfL[1], bH0, bH1);
                    mma1688_tf32(C[0][ni], AfH[0], bL0, bL1);
                    mma1688_tf32(C[1][ni], AfH[1], bL0, bL1);
                }
            }
        }
        __syncthreads();
    }

    if (MODE == 5){
        #pragma unroll
        for (int mi = 0; mi < 2; mi++){
            const int r = m0 + r0 + mi*16 + g;
            #pragma unroll
            for (int ni = 0; ni < 8; ni++){
                const int gn = n0 + c0 + ni*8 + 2*ti;
                if (gn < N){
                    float b0v = bias[gn], b1v = bias[gn+1];
                    size_t oA = (size_t)r*HAE + gn;
                    size_t oB = (size_t)(r+8)*HAE + gn;
                    out0[oA]   = sp_(C[mi][ni][0] + b0v);
                    out0[oA+1] = sp_(C[mi][ni][1] + b1v);
                    out0[oB]   = sp_(C[mi][ni][2] + b0v);
                    out0[oB+1] = sp_(C[mi][ni][3] + b1v);
                }
            }
        }
    } else if (MODE == 7){
        #pragma unroll
        for (int mi = 0; mi < 2; mi++){
            const int r = m0 + r0 + mi*16 + g;
            #pragma unroll
            for (int ni = 0; ni < 8; ni++){
                const int gn = c0 + ni*8 + 2*ti;
                float b0v = bias[gn], b1v = bias[gn+1];
                float v00 = C[mi][ni][0] + b0v, v01 = C[mi][ni][1] + b1v;
                float v10 = C[mi][ni][2] + b0v, v11 = C[mi][ni][3] + b1v;
                size_t oA = (size_t)r*HAE + gn;
                size_t oB = (size_t)(r+8)*HAE + gn;
                out0[oA]   = sp_(v00); out0[oA+1] = sp_(v01);
                out0[oB]   = sp_(v10); out0[oB+1] = sp_(v11);
                *reinterpret_cast<__nv_bfloat162*>(&g_d2b[oA]) =
                    __floats2bfloat162_rn(sig_(v00), sig_(v01));
                *reinterpret_cast<__nv_bfloat162*>(&g_d2b[oB]) =
                    __floats2bfloat162_rn(sig_(v10), sig_(v11));
            }
        }
    } else if (MODE == 1){
        float loc = 0.f;
        #pragma unroll
        for (int mi = 0; mi < 2; mi++){
            const int r = m0 + r0 + mi*16 + g;
            #pragma unroll
            for (int ni = 0; ni < 8; ni++){
                const int gn = n0 + c0 + ni*8 + 2*ti;
                if (gn < N){
                    float b0v = bias[gn], b1v = bias[gn+1];
                    float d0 = aux[(size_t)r*s_aux + gn]       - (C[mi][ni][0] + b0v);
                    float d1 = aux[(size_t)r*s_aux + gn + 1]   - (C[mi][ni][1] + b1v);
                    float d2 = aux[(size_t)(r+8)*s_aux + gn]   - (C[mi][ni][2] + b0v);
                    float d3 = aux[(size_t)(r+8)*s_aux + gn+1] - (C[mi][ni][3] + b1v);
                    loc += d0*d0 + d1*d1 + d2*d2 + d3*d3;
                }
            }
        }
        red[t] = loc; __syncthreads();
        for (int st = 128; st > 0; st >>= 1){ if (t < st) red[t] += red[t+st]; __syncthreads(); }
        if (t == 0) atomicAdd(accd, (double)red[0]);
    } else { // MODE 6
        #pragma unroll
        for (int mi = 0; mi < 2; mi++){
            const int r = m0 + r0 + mi*16 + g;
            #pragma unroll
            for (int ni = 0; ni < 8; ni++){
                const int gn = n0 + c0 + ni*8 + 2*ti;
                if (gn < N){
                    atomicAdd(&out0[(size_t)r*HAE + gn],       C[mi][ni][0]);
                    atomicAdd(&out0[(size_t)r*HAE + gn + 1],   C[mi][ni][1]);
                    atomicAdd(&out0[(size_t)(r+8)*HAE + gn],   C[mi][ni][2]);
                    atomicAdd(&out0[(size_t)(r+8)*HAE + gn+1], C[mi][ni][3]);
                }
            }
        }
    }
}

#define SM1 (2*128*TS*4)
#define SM3 (4*128*TS*4)

// ---------------- setup ----------------
__global__ void setup_k(const float* __restrict__ ew3, const float* __restrict__ ew2,
                        const float* __restrict__ ssc){
    int bid = blockIdx.x, t = threadIdx.x;
    if (bid < 1920){
        int idx = bid*256 + t;
        int bb = idx & 127;
        int n  = idx >> 7;
        int l  = n >> 7;
        int a  = n & 127;
        g_Vb[idx] = __float2bfloat16(ew3[l*HAE + bb] * ew2[bb*HAE + a]);
    } else if (bid < 1984){
        int t2 = (bid - 1920)*256 + t;
        if (t2 < SZv*Hh) g_l2[t2] = 0.5f;
        if (t2 < HAE*HAE) g_G1[t2] = 0.f;
        if (t2 == 0) g_comp = 0.0;
        if (t2 < NTRI){
            int rem = t2, i = 0;
            while (rem >= 32 - i){ rem -= 32 - i; i++; }
            g_iu0[t2] = i; g_iu1[t2] = i + rem;
        }
    } else {
        int gid = (bid - 1984)*256 + t;
        int w = gid >> 5, lane = gid & 31;
        if (w >= Dd*Hh*SZv) return;
        int i = w / (Hh*SZv);
        int rem = w % (Hh*SZv);
        int h = rem / SZv;
        int s = rem % SZv;
        const float* row = &ssc[(((size_t)(i*Hh+h)*SZv)+s)*SZv];
        float a = 0.f;
        for (int k = lane; k < SZv; k += 32) a += row[k];
        #pragma unroll
        for (int o = 16; o > 0; o >>= 1) a += __shfl_down_sync(0xffffffffu, a, o);
        if (lane == 0) g_scalarT[(i*SZv+s)*Hh + h] = a;
    }
}

__global__ void cvt_G1(){
    int t = blockIdx.x*256 + threadIdx.x;
    if (t < HAE*HAE) g_G1b[t] = __float2bfloat16(g_G1[t]);
}

// ---------------- raw / groupnorm (+ zero + out-dot) --------
__global__ void __launch_bounds__(256)
build_raw_fused(const float* __restrict__ x, const float* __restrict__ ln_g,
                const float* __restrict__ ln_b, int do_out){
    __shared__ float nx[32];
    __shared__ float rw[SZv];
    __shared__ float sc[SZv*2];
    __shared__ float redA[256], redB[256];
    int b = blockIdx.x, t = threadIdx.x;
    int gid = b*256 + t;
    if (gid < Bb*HAE) g_accE[gid] = 0.f;
    if (gid < Lv*Lv){ g_zTz[gid] = 0.f; g_az[gid] = 0.f; }
    if (gid == Bb*HAE){ g_mse = 0.0; g_jsum = 0.0; }

    float s0 = 0.f, s1 = 0.f;
    if (do_out){
        for (int i = t; i < SZv*2; i += 256) sc[i] = g_scaled[i];
        __syncthreads();
        const float* rwg = &g_raw[(size_t)b*SZv];
        for (int i = t; i < SZv; i += 256){
            float v = rwg[i];
            s0 += v*sc[i*2];
            s1 += v*sc[i*2+1];
        }
        s0 = blk_reduce(s0, redA, t);
        s1 = blk_reduce(s1, redA, t);
    }
    if (t < NIi) nx[t] = x[b*NIi + t];
    else if (t == NIi)   nx[t] = s0;
    else if (t == NIi+1) nx[t] = s1;
    __syncthreads();
    float s = 0.f, ss = 0.f;
    for (int idx = t; idx < SZv; idx += 256){
        float v;
        if (idx < NTRI){
            int i = g_iu0[idx], j = g_iu1[idx];
            v = (i == j) ? nx[i] : nx[i] + nx[j];
        } else if (idx < 2*NTRI){
            int k = idx - NTRI;
            v = nx[g_iu0[k]] * nx[g_iu1[k]];
        } else if (idx < 2*NTRI + 32){
            v = sinf(nx[idx - 2*NTRI]);
        } else {
            v = cosf(nx[idx - 2*NTRI - 32]);
        }
        rw[idx] = v; s += v; ss += v*v;
    }
    redA[t] = s; redB[t] = ss; __syncthreads();
    for (int st = 128; st > 0; st >>= 1){
        if (t < st){ redA[t] += redA[t+st]; redB[t] += redB[t+st]; }
        __syncthreads();
    }
    float mean = redA[0] / SZv;
    float var  = redB[0] / SZv - mean*mean;
    float rstd = rsqrtf(var + 1e-5f);
    for (int idx = t; idx < SZv; idx += 256){
        float v = rw[idx];
        g_raw[(size_t)b*SZv + idx] = v;
        g_xn [(size_t)b*SZv + idx] = (v - mean)*rstd*ln_g[idx] + ln_b[idx];
    }
}

// ---------------- selection: A-chain + B dot ------
__global__ void __launch_bounds__(256)
sel_AB(const float* __restrict__ qw, const float* __restrict__ qb,
       const float* __restrict__ sq,
       const float* __restrict__ sl1, const float* __restrict__ sg1,
       const float* __restrict__ sb1,
       const float* __restrict__ sl2, int iter){
    __shared__ float gsa[900], lsa[900];
    __shared__ float sel[2][30], h1s[2][64];
    __shared__ float sc8[8];
    __shared__ float h1f[128];
    int t = threadIdx.x;
    qw  += iter*900;  qb  += iter*30;   sq  += iter*60;
    sl1 += iter*2*64*30; sg1 += iter*128; sb1 += iter*128;
    for (int i = t; i < 900; i += 256) gsa[i] = g_zTz[i] / fmaxf(g_az[i], 1e-5f);
    __syncthreads();
    for (int idx = t; idx < 900; idx += 256){
        int i = idx / 30, j = idx % 30;
        float s = qb[j];
        #pragma unroll
        for (int k = 0; k < 30; k++) s += gsa[i*30+k]*qw[j*30+k];
        lsa[idx] = s;
    }
    __syncthreads();
    if (t < 60){
        int h = t / 30, i = t % 30;
        float s = 0.f;
        #pragma unroll
        for (int j = 0; j < 30; j++) s += lsa[i*30+j]*sq[h*30+j];
        sel[h][i] = s;
    }
    __syncthreads();
    if (t < 128){
        int h = t >> 6, o = t & 63;
        float s = 0.f;
        #pragma unroll
        for (int l = 0; l < 30; l++) s += sl1[(h*64+o)*30+l]*sel[h][l];
        h1s[h][o] = s;
    }
    __syncthreads();
    if (t < 2){
        float m = 0.f;
        for (int o = 0; o < 64; o++) m += h1s[t][o];
        m *= (1.f/64.f);
        float v = 0.f;
        for (int o = 0; o < 64; o++){ float d = h1s[t][o]-m; v += d*d; }
        v *= (1.f/64.f);
        sc8[t*2] = m; sc8[t*2+1] = rsqrtf(v + 1e-5f);
    }
    __syncthreads();
    if (t < 128){
        int h = t >> 6, o = t & 63;
        h1f[t] = sp_((h1s[h][o]-sc8[h*2])*sc8[h*2+1]*sg1[h*64+o] + sb1[h*64+o]);
    }
    __syncthreads();
    int w = blockIdx.x*8 + (t >> 5);
    int lane = t & 31;
    if (w >= Hh*SZv) return;
    int h = w / SZv, s = w % SZv;
    const float* wp = &sl2[((size_t)iter*Hh*SZv + w)*64];
    float a = wp[lane]*h1f[h*64+lane] + wp[lane+32]*h1f[h*64+lane+32];
    #pragma unroll
    for (int o = 16; o > 0; o >>= 1) a += __shfl_down_sync(0xffffffffu, a, o);
    if (lane == 0) g_buf[h*SZv + s] = a;
}

// ---------------- phase C ----------------
__global__ void __launch_bounds__(256)
sel_C(const float* __restrict__ sg2, const float* __restrict__ sb2,
      const float* __restrict__ son, int iter){
    __shared__ float buf[2][SZv];
    __shared__ float red[256];
    int t = threadIdx.x;
    sg2 += iter*2*SZv; sb2 += iter*2*SZv;
    son += iter*2*2*SZv;
    for (int i = t; i < 2*SZv; i += 256) buf[i/SZv][i%SZv] = g_buf[i];
    __syncthreads();
    for (int h = 0; h < 2; h++){
        float s = 0.f, ss = 0.f;
        for (int i = t; i < SZv; i += 256){ float v = buf[h][i]; s += v; ss += v*v; }
        s  = blk_reduce(s, red, t);
        ss = blk_reduce(ss, red, t);
        float mean = s*(1.f/SZv);
        float var  = ss*(1.f/SZv) - mean*mean;
        float rstd = rsqrtf(var + 1e-5f);
        float mx = -1e30f;
        for (int i = t; i < SZv; i += 256){
            float v = (buf[h][i]-mean)*rstd*sg2[h*SZv+i] + sb2[h*SZv+i];
            buf[h][i] = v;
            mx = fmaxf(mx, v);
        }
        mx = blk_reduce_max(mx, red, t);
        float se = 0.f;
        for (int i = t; i < SZv; i += 256){
            float e = expf(buf[h][i]-mx);
            buf[h][i] = e;
            se += e;
        }
        se = blk_reduce(se, red, t);
        float inv = 1.f/se;
        for (int i = t; i < SZv; i += 256) buf[h][i] *= inv;
        __syncthreads();
    }
    float d0 = 0.f, d1 = 0.f;
    for (int s = t; s < SZv; s += 256){
        float il = g_l2[s*2]*g_l2[s*2+1];
        d0 += son[s]*il + son[SZv+s]*buf[0][s];
        d1 += son[2*SZv+s]*il + son[2*SZv+SZv+s]*buf[1][s];
    }
    d0 = blk_reduce(d0, red, t);
    d1 = blk_reduce(d1, red, t);
    float on0 = sig_(d0), on1 = sig_(d1);
    float e00 = 0.f, e01 = 0.f, e10 = 0.f, e11 = 0.f;
    for (int s = t; s < SZv; s += 256){
        float o0 = on0*buf[0][s], o1 = on1*buf[1][s];
        float sc0 = o0*g_scalarT[(iter*SZv+s)*2+0];
        float sc1 = o1*g_scalarT[(iter*SZv+s)*2+1];
        if (fabsf(sc0) <= 1e-14f) sc0 = 1e-14f;
        if (fabsf(sc1) <= 1e-14f) sc1 = 1e-14f;
        g_scaled[s*2]   = sc0;
        g_scaled[s*2+1] = sc1;
        float l20 = fmaxf(o0, 1e-14f), l21 = fmaxf(o1, 1e-14f);
        g_l2[s*2] = l20; g_l2[s*2+1] = l21;
        float lg0 = logf(l20 + 1e-5f), lg1 = logf(l21 + 1e-5f);
        e00 += l20*lg0; e01 += l20*lg1;
        e10 += l21*lg0; e11 += l21*lg1;
    }
    e00 = blk_reduce(e00, red, t);
    e01 = blk_reduce(e01, red, t);
    e10 = blk_reduce(e10, red, t);
    e11 = blk_reduce(e11, red, t);
    if (t == 0){
        float g00 = -e00, g01 = -e01, g10 = -e10, g11 = -e11;
        float g = 0.01f*0.5f*(g00+g11) - 0.25f*(g01+g10);
        double cst = g_mse/((double)Bb*SZv) + g_jsum/((double)Lv*(double)Bb*(double)SZv);
        g_comp += (double)g + cst;
    }
}

// ---------------- final ----------------
__global__ void __launch_bounds__(256)
finalize_dot(float* __restrict__ out){
    __shared__ float sc[SZv];
    int t = threadIdx.x;
    for (int i = t; i < SZv; i += 256) sc[i] = g_scaled[i*2] + g_scaled[i*2+1];
    __syncthreads();
    int warp = t >> 5, lane = t & 31;
    int b = blockIdx.x*8 + warp;
    const float* rw = &g_raw[(size_t)b*SZv];
    float s = 0.f;
    for (int i = lane; i < SZv; i += 32) s += rw[i]*sc[i];
    #pragma unroll
    for (int o = 16; o > 0; o >>= 1) s += __shfl_down_sync(0xffffffffu, s, o);
    if (lane == 0) out[b] = s;
    if (blockIdx.x == 0 && t == 0) out[Bb] = (float)g_comp;
}

// ---------------- host ----------------
extern "C" void kernel_launch(void* const* d_in, const int* in_sizes, int n_in,
                              void* d_out, int out_size) {
    const float* x    = (const float*)d_in[0];
    const float* ln_g = (const float*)d_in[1];
    const float* ln_b = (const float*)d_in[2];
    const float* ew1  = (const float*)d_in[3];
    const float* eb1  = (const float*)d_in[4];
    const float* ew2  = (const float*)d_in[5];
    const float* eb2  = (const float*)d_in[6];
    const float* ew3  = (const float*)d_in[7];
    const float* eb3  = (const float*)d_in[8];
    const float* dw1  = (const float*)d_in[9];
    const float* db1  = (const float*)d_in[10];
    const float* dw2  = (const float*)d_in[11];
    const float* db2  = (const float*)d_in[12];
    const float* dw3  = (const float*)d_in[13];
    const float* db3  = (const float*)d_in[14];
    const float* qw   = (const float*)d_in[15];
    const float* qb   = (const float*)d_in[16];
    const float* sq   = (const float*)d_in[17];
    const float* sl1  = (const float*)d_in[18];
    const float* sg1  = (const float*)d_in[19];
    const float* sb1  = (const float*)d_in[20];
    const float* sl2  = (const float*)d_in[21];
    const float* sg2  = (const float*)d_in[22];
    const float* sb2  = (const float*)d_in[23];
    const float* ssc  = (const float*)d_in[24];
    const float* son  = (const float*)d_in[25];
    float* out = (float*)d_out;

    float *pXn, *pH2, *pDh1, *pDh2, *pG1, *pAccE;
    double *pMse;
    cudaGetSymbolAddress((void**)&pXn,  g_xn);
    cudaGetSymbolAddress((void**)&pH2,  g_h2e);
    cudaGetSymbolAddress((void**)&pDh1, g_dh1);
    cudaGetSymbolAddress((void**)&pDh2, g_dh2);
    cudaGetSymbolAddress((void**)&pG1,  g_G1);
    cudaGetSymbolAddress((void**)&pAccE,g_accE);
    cudaGetSymbolAddress((void**)&pMse, g_mse);

    cudaFuncSetAttribute(hmma_z, cudaFuncAttributeMaxDynamicSharedMemorySize, HMMA_SMEM);

    setup_k<<<2544,256>>>(ew3, ew2, ssc);
    tf32_gemm<6,0><<<dim3(1,1,35),256,SM1>>>(ew1, ew1, HAE, SZv, 32,
        nullptr, pG1, nullptr, 0, nullptr, nullptr);
    cvt_G1<<<64,256>>>();

    for (int iter = 0; iter < Dd; iter++){
        build_raw_fused<<<Bb,256>>>(x, ln_g, ln_b, iter > 0 ? 1 : 0);
        tf32_gemm<6,1><<<dim3(16,1,7),256,SM3>>>(pXn, ew1, HAE, SZv, 160,
            nullptr, pAccE, nullptr, 0, nullptr, nullptr);
        tf32_gemm<7,1><<<dim3(16,1,1),256,SM3>>>(pAccE, ew2, HAE, HAE, HAE,
            eb2, pH2, nullptr, 0, nullptr, eb1);
        hmma_z<<<608, 256, HMMA_SMEM>>>(ew3, eb3, dw1, db1);
        tf32_gemm<5,1><<<dim3(16,1,1),256,SM3>>>(pDh1, dw2, HAE, HAE, HAE,
            db2, pDh2, nullptr, 0, nullptr, nullptr);
        tf32_gemm<1,1><<<dim3(16,9,1),256,SM3>>>(pDh2, dw3, SZv, HAE, HAE,
            db3, nullptr, pXn, SZv, pMse, nullptr);
        sel_AB<<<(Hh*SZv+7)/8,256>>>(qw, qb, sq, sl1, sg1, sb1, sl2, iter);
        sel_C<<<1,256>>>(sg2, sb2, son, iter);
    }
    finalize_dot<<<Bb/8,256>>>(out);
}

// round 17
// speedup vs baseline: 1.4653x; 1.1615x over previous
#include <cuda_runtime.h>
#include <cuda_bf16.h>
#include <math.h>
#include <stdint.h>

#define Bb   2048
#define NIi  30
#define Hh   2
#define Dd   2
#define HAE  128
#define SZv  1120
#define Lv   30
#define NTRI 528
#define NV   (Lv*HAE)   /* 3840 */

// ---------------- device scratch ----------------
__device__ float g_raw[Bb*SZv];
__device__ float g_xn [Bb*SZv];
__device__ float g_d1[Bb*HAE];
__device__ float g_h2e[Bb*HAE];
__device__ float g_dh1[Bb*HAE], g_dh2[Bb*HAE];
__device__ float g_accE[Bb*HAE];
__device__ float g_G1[HAE*HAE];
__device__ __nv_bfloat16 g_G1b[HAE*HAE];
__device__ __nv_bfloat16 g_Vb[NV*HAE];
__device__ __nv_bfloat16 g_d2b[Bb*HAE];
__device__ float g_scalarT[Dd*SZv*Hh];
__device__ float g_zTz[Lv*Lv], g_az[Lv*Lv];
__device__ float g_l2[SZv*Hh];
__device__ float g_scaled[SZv*Hh];
__device__ float g_buf[Hh*SZv];
__device__ double g_mse, g_jsum, g_comp;
__device__ int g_iu0[NTRI], g_iu1[NTRI];

__device__ __forceinline__ float sp_(float x){ return fmaxf(x,0.f) + log1pf(__expf(-fabsf(x))); }
__device__ __forceinline__ float sig_(float x){ return 1.f/(1.f+__expf(-x)); }

__device__ __forceinline__ float blk_reduce(float v, float* red, int t){
    red[t]=v; __syncthreads();
    for(int st=128;st>0;st>>=1){ if(t<st) red[t]+=red[t+st]; __syncthreads(); }
    float r=red[0]; __syncthreads();
    return r;
}
__device__ __forceinline__ float blk_reduce_max(float v, float* red, int t){
    red[t]=v; __syncthreads();
    for(int st=128;st>0;st>>=1){ if(t<st) red[t]=fmaxf(red[t],red[t+st]); __syncthreads(); }
    float r=red[0]; __syncthreads();
    return r;
}

// ================= HMMA helpers ==========
#define HS 136
#define HMMA_SMEM (2*128*HS*2)
#define ZR 16

__device__ __forceinline__ void mma16816(float* c, const uint32_t* a,
                                         uint32_t b0, uint32_t b1){
    asm volatile(
        "mma.sync.aligned.m16n8k16.row.col.f32.bf16.bf16.f32 "
        "{%0,%1,%2,%3}, {%4,%5,%6,%7}, {%8,%9}, {%0,%1,%2,%3};"
        : "+f"(c[0]), "+f"(c[1]), "+f"(c[2]), "+f"(c[3])
        : "r"(a[0]), "r"(a[1]), "r"(a[2]), "r"(a[3]), "r"(b0), "r"(b1));
}
__device__ __forceinline__ void ldsm_x4(uint32_t* r, uint32_t addr){
    asm volatile("ldmatrix.sync.aligned.m8n8.x4.shared.b16 {%0,%1,%2,%3}, [%4];"
        : "=r"(r[0]), "=r"(r[1]), "=r"(r[2]), "=r"(r[3]) : "r"(addr));
}
__device__ __forceinline__ void ldsm_x2(uint32_t& r0, uint32_t& r1, uint32_t addr){
    asm volatile("ldmatrix.sync.aligned.m8n8.x2.shared.b16 {%0,%1}, [%2];"
        : "=r"(r0), "=r"(r1) : "r"(addr));
}

// ---- TM+JQ body ----
__device__ void hmma_body(__nv_bfloat16* As, __nv_bfloat16* Bs, float* red,
                          int bx, int by){
    const int t = threadIdx.x, wid = t >> 5, lane = t & 31;
    const int g = lane >> 2, ti = lane & 3;
    const int m0 = bx * 128;

    const __nv_bfloat16* Ag = g_d2b + (size_t)m0*HAE;
    const __nv_bfloat16* Bg = g_Vb + (size_t)by*128*HAE;

    for (int i = t; i < 2048; i += 256){
        int row = i >> 4, col = (i & 15) * 8;
        *reinterpret_cast<uint4*>(&As[row*HS + col]) =
            *reinterpret_cast<const uint4*>(&Ag[(size_t)row*HAE + col]);
        *reinterpret_cast<uint4*>(&Bs[row*HS + col]) =
            *reinterpret_cast<const uint4*>(&Bg[(size_t)row*HAE + col]);
    }
    __syncthreads();

    const int wm = wid >> 1, wn = wid & 1;
    const int r0 = wm*32, c0 = wn*64;
    float C[2][8][4];
    #pragma unroll
    for (int mi = 0; mi < 2; mi++)
        #pragma unroll
        for (int ni = 0; ni < 8; ni++)
            #pragma unroll
            for (int q = 0; q < 4; q++) C[mi][ni][q] = 0.f;

    const uint32_t asu = (uint32_t)__cvta_generic_to_shared(As);
    const uint32_t bsu = (uint32_t)__cvta_generic_to_shared(Bs);
    const uint32_t aBase = asu + ((uint32_t)((r0 + (lane & 15))*HS + ((lane >> 4) << 3)) << 1);
    const uint32_t bBase = bsu + ((uint32_t)((c0 + (lane & 7))*HS + ((lane & 8) ? 8 : 0)) << 1);

    #pragma unroll
    for (int kk = 0; kk < 8; kk++){
        uint32_t Af[2][4];
        ldsm_x4(Af[0], aBase + kk*32);
        ldsm_x4(Af[1], aBase + 16*HS*2 + kk*32);
        #pragma unroll
        for (int ni = 0; ni < 8; ni++){
            uint32_t b0, b1;
            ldsm_x2(b0, b1, bBase + ni*(8*HS*2) + kk*32);
            mma16816(C[0][ni], Af[0], b0, b1);
            mma16816(C[1][ni], Af[1], b0, b1);
        }
    }
    __syncthreads();

    #pragma unroll
    for (int mi = 0; mi < 2; mi++){
        const int rl = r0 + mi*16 + g;
        const int r  = m0 + rl;
        #pragma unroll
        for (int ni = 0; ni < 8; ni++){
            const int a = c0 + ni*8 + ti*2;
            float2 dA = *reinterpret_cast<const float2*>(&g_d1[(size_t)r*HAE + a]);
            float2 dB = *reinterpret_cast<const float2*>(&g_d1[(size_t)(r+8)*HAE + a]);
            *reinterpret_cast<__nv_bfloat162*>(&As[rl*HS + a]) =
                __floats2bfloat162_rn(C[mi][ni][0]*dA.x, C[mi][ni][1]*dA.y);
            *reinterpret_cast<__nv_bfloat162*>(&As[(rl+8)*HS + a]) =
                __floats2bfloat162_rn(C[mi][ni][2]*dB.x, C[mi][ni][3]*dB.y);
        }
    }
    for (int i = t; i < 2048; i += 256){
        int row = i >> 4, col = (i & 15) * 8;
        *reinterpret_cast<uint4*>(&Bs[row*HS + col]) =
            *reinterpret_cast<const uint4*>(&g_G1b[(size_t)row*HAE + col]);
    }
    __syncthreads();

    #pragma unroll
    for (int mi = 0; mi < 2; mi++)
        #pragma unroll
        for (int ni = 0; ni < 8; ni++)
            #pragma unroll
            for (int q = 0; q < 4; q++) C[mi][ni][q] = 0.f;
    #pragma unroll
    for (int kk = 0; kk < 8; kk++){
        uint32_t Af[2][4];
        ldsm_x4(Af[0], aBase + kk*32);
        ldsm_x4(Af[1], aBase + 16*HS*2 + kk*32);
        #pragma unroll
        for (int ni = 0; ni < 8; ni++){
            uint32_t b0, b1;
            ldsm_x2(b0, b1, bBase + ni*(8*HS*2) + kk*32);
            mma16816(C[0][ni], Af[0], b0, b1);
            mma16816(C[1][ni], Af[1], b0, b1);
        }
    }

    float loc = 0.f;
    #pragma unroll
    for (int mi = 0; mi < 2; mi++){
        const int rl = r0 + mi*16 + g;
        #pragma unroll
        for (int ni = 0; ni < 8; ni++){
            const int a = c0 + ni*8 + ti*2;
            __nv_bfloat162 mA = *reinterpret_cast<const __nv_bfloat162*>(&As[rl*HS + a]);
            __nv_bfloat162 mB = *reinterpret_cast<const __nv_bfloat162*>(&As[(rl+8)*HS + a]);
            loc += C[mi][ni][0]*__bfloat162float(mA.x)
                 + C[mi][ni][1]*__bfloat162float(mA.y)
                 + C[mi][ni][2]*__bfloat162float(mB.x)
                 + C[mi][ni][3]*__bfloat162float(mB.y);
        }
    }
    red[t] = loc; __syncthreads();
    for (int st = 128; st > 0; st >>= 1){ if (t < st) red[t] += red[t+st]; __syncthreads(); }
    if (t == 0) atomicAdd(&g_jsum, (double)red[0]);
}

// ---- z + zstats + dec1 body ----
__device__ void zdec1_body(float* sm, int zb,
                           const float* __restrict__ ew3, const float* __restrict__ eb3,
                           const float* __restrict__ dw1, const float* __restrict__ db1){
    float* hs = sm;
    float* w3 = hs + ZR*129;
    float* zs = w3 + 30*129;
    int t = threadIdx.x;
    int b0 = zb * ZR;
    for (int i = t; i < ZR*HAE; i += 256) hs[(i>>7)*129 + (i&127)] = g_h2e[(size_t)b0*HAE + i];
    for (int i = t; i < 30*HAE; i += 256) w3[(i>>7)*129 + (i&127)] = ew3[i];
    __syncthreads();
    for (int idx = t; idx < ZR*30; idx += 256){
        int r = idx / 30, l = idx % 30;
        float s = eb3[l];
        #pragma unroll 8
        for (int k = 0; k < HAE; k++) s += hs[r*129 + k]*w3[l*129 + k];
        zs[r*31 + l] = s;
    }
    __syncthreads();
    for (int idx = t; idx < 900; idx += 256){
        int i = idx / 30, j = idx % 30;
        float a = 0.f, ab = 0.f;
        #pragma unroll
        for (int r = 0; r < ZR; r++){
            float zi = zs[r*31 + i], zj = zs[r*31 + j];
            a  += zi*zj;
            ab += fabsf(zi)*fabsf(zj);
        }
        atomicAdd(&g_zTz[idx], a);
        atomicAdd(&g_az[idx], ab);
    }
    for (int idx = t; idx < ZR*HAE; idx += 256){
        int r = idx >> 7, o = idx & 127;
        float s = db1[o];
        #pragma unroll
        for (int l = 0; l < 30; l++) s += zs[r*31 + l]*dw1[o*30 + l];
        g_dh1[(size_t)(b0+r)*HAE + o] = sp_(s);
    }
}

__global__ void __launch_bounds__(256)
hmma_z(const float* __restrict__ ew3, const float* __restrict__ eb3,
       const float* __restrict__ dw1, const float* __restrict__ db1){
    extern __shared__ char dyn[];
    __shared__ float red[256];
    if (blockIdx.x < 480){
        __nv_bfloat16* As = reinterpret_cast<__nv_bfloat16*>(dyn);
        hmma_body(As, As + 128*HS, red, blockIdx.x & 15, blockIdx.x >> 4);
    } else {
        zdec1_body(reinterpret_cast<float*>(dyn), blockIdx.x - 480, ew3, eb3, dw1, db1);
    }
}

// ================= TF32 GEMM body (register-prefetch pipelined) ==========
#define TS 20

__device__ __forceinline__ uint32_t to_tf32(float x){
    uint32_t u;
    asm("cvt.rna.tf32.f32 %0, %1;" : "=r"(u) : "f"(x));
    return u;
}
__device__ __forceinline__ void mma1688_tf32(float* c, const uint32_t* a,
                                             uint32_t b0, uint32_t b1){
    asm volatile(
        "mma.sync.aligned.m16n8k8.row.col.f32.tf32.tf32.f32 "
        "{%0,%1,%2,%3}, {%4,%5,%6,%7}, {%8,%9}, {%0,%1,%2,%3};"
        : "+f"(c[0]), "+f"(c[1]), "+f"(c[2]), "+f"(c[3])
        : "r"(a[0]), "r"(a[1]), "r"(a[2]), "r"(a[3]), "r"(b0), "r"(b1));
}

// MODE 1: mse accumulate; MODE 5: sp only; MODE 6: split-K atomicAdd
// MODE 7: enc2 (enc1 epi at staging; epilogue h2e f32 + d2b bf16)
template<int MODE, int PREC>
__device__ void tf32_body(float* tsm, float* red, int bx, int by, int bz,
          const float* __restrict__ A, const float* __restrict__ Bm,
          int N, int K, int Kc,
          const float* __restrict__ bias, float* __restrict__ out0,
          const float* __restrict__ aux, int s_aux, double* accd,
          const float* __restrict__ pA){
    float* AsH = tsm;
    float* BsH = tsm + 128*TS;
    float* AsL = tsm + 2*128*TS;
    float* BsL = tsm + 3*128*TS;
    const int t = threadIdx.x, wid = t >> 5, lane = t & 31;
    const int g = lane >> 2, ti = lane & 3;
    const int m0 = bx * 128, n0 = by * 128;
    const int kBeg = bz * Kc, kEnd = min(K, kBeg + Kc);
    const int wm = wid >> 1, wn = wid & 1;
    const int r0 = wm*32, c0 = wn*64;

    const int sr0 = t >> 2,        sc0 = (t & 3) * 4;
    const int sr1 = (t+256) >> 2,  sc1 = ((t+256) & 3) * 4;

    float C[2][8][4];
    #pragma unroll
    for (int mi = 0; mi < 2; mi++)
        #pragma unroll
        for (int ni = 0; ni < 8; ni++)
            #pragma unroll
            for (int q = 0; q < 4; q++) C[mi][ni][q] = 0.f;

    float4 va[2], vb[2];
    va[0] = *reinterpret_cast<const float4*>(&A[(size_t)(m0+sr0)*K + kBeg + sc0]);
    va[1] = *reinterpret_cast<const float4*>(&A[(size_t)(m0+sr1)*K + kBeg + sc1]);
    vb[0] = (n0 + sr0 < N) ? *reinterpret_cast<const float4*>(&Bm[(size_t)(n0+sr0)*K + kBeg + sc0])
                           : make_float4(0.f,0.f,0.f,0.f);
    vb[1] = (n0 + sr1 < N) ? *reinterpret_cast<const float4*>(&Bm[(size_t)(n0+sr1)*K + kBeg + sc1])
                           : make_float4(0.f,0.f,0.f,0.f);

    for (int k0 = kBeg; k0 < kEnd; k0 += 16){
        #pragma unroll
        for (int i = 0; i < 2; i++){
            int row = (i == 0) ? sr0 : sr1;
            int c   = (i == 0) ? sc0 : sc1;
            float av[4] = {va[i].x, va[i].y, va[i].z, va[i].w};
            float bv[4] = {vb[i].x, vb[i].y, vb[i].z, vb[i].w};
            if (MODE == 7){
                #pragma unroll
                for (int q = 0; q < 4; q++){
                    int col = k0 + c + q;
                    float v = av[q] + pA[col];
                    av[q] = sp_(v);
                    g_d1[(size_t)(m0+row)*HAE + col] = sig_(v);
                }
            }
            #pragma unroll
            for (int q = 0; q < 4; q++){
                uint32_t ah = to_tf32(av[q]);
                uint32_t bh = to_tf32(bv[q]);
                AsH[row*TS + c + q] = __uint_as_float(ah);
                BsH[row*TS + c + q] = __uint_as_float(bh);
                if (PREC){
                    AsL[row*TS + c + q] = __uint_as_float(to_tf32(av[q] - __uint_as_float(ah)));
                    BsL[row*TS + c + q] = __uint_as_float(to_tf32(bv[q] - __uint_as_float(bh)));
                }
            }
        }
        __syncthreads();
        if (k0 + 16 < kEnd){
            const int kn = k0 + 16;
            va[0] = *reinterpret_cast<const float4*>(&A[(size_t)(m0+sr0)*K + kn + sc0]);
            va[1] = *reinterpret_cast<const float4*>(&A[(size_t)(m0+sr1)*K + kn + sc1]);
            vb[0] = (n0 + sr0 < N) ? *reinterpret_cast<const float4*>(&Bm[(size_t)(n0+sr0)*K + kn + sc0])
                                   : make_float4(0.f,0.f,0.f,0.f);
            vb[1] = (n0 + sr1 < N) ? *reinterpret_cast<const float4*>(&Bm[(size_t)(n0+sr1)*K + kn + sc1])
                                   : make_float4(0.f,0.f,0.f,0.f);
        }
        #pragma unroll
        for (int kk = 0; kk < 16; kk += 8){
            uint32_t AfH[2][4], AfL[2][4];
            #pragma unroll
            for (int mi = 0; mi < 2; mi++){
                const int ao = (r0 + mi*16 + g)*TS + kk;
                AfH[mi][0] = __float_as_uint(AsH[ao + ti]);
                AfH[mi][1] = __float_as_uint(AsH[ao + 8*TS + ti]);
                AfH[mi][2] = __float_as_uint(AsH[ao + ti + 4]);
                AfH[mi][3] = __float_as_uint(AsH[ao + 8*TS + ti + 4]);
                if (PREC){
                    AfL[mi][0] = __float_as_uint(AsL[ao + ti]);
                    AfL[mi][1] = __float_as_uint(AsL[ao + 8*TS + ti]);
                    AfL[mi][2] = __float_as_uint(AsL[ao + ti + 4]);
                    AfL[mi][3] = __float_as_uint(AsL[ao + 8*TS + ti + 4]);
                }
            }
            #pragma unroll
            for (int ni = 0; ni < 8; ni++){
                const int bo = (c0 + ni*8 + g)*TS + kk;
                uint32_t bH0 = __float_as_uint(BsH[bo + ti]);
                uint32_t bH1 = __float_as_uint(BsH[bo + ti + 4]);
                mma1688_tf32(C[0][ni], AfH[0], bH0, bH1);
                mma1688_tf32(C[1][ni], AfH[1], bH0, bH1);
                if (PREC){
                    uint32_t bL0 = __float_as_uint(BsL[bo + ti]);
                    uint32_t bL1 = __float_as_uint(BsL[bo + ti + 4]);
                    mma1688_tf32(C[0][ni], AfL[0], bH0, bH1);
                    mma1688_tf32(C[1][ni], AfL[1], bH0, bH1);
                    mma1688_tf32(C[0][ni], AfH[0], bL0, bL1);
                    mma1688_tf32(C[1][ni], AfH[1], bL0, bL1);
                }
            }
        }
        __syncthreads();
    }

    if (MODE == 5){
        #pragma unroll
        for (int mi = 0; mi < 2; mi++){
            const int r = m0 + r0 + mi*16 + g;
            #pragma unroll
            for (int ni = 0; ni < 8; ni++){
                const int gn = n0 + c0 + ni*8 + 2*ti;
                if (gn < N){
                    float b0v = bias[gn], b1v = bias[gn+1];
                    size_t oA = (size_t)r*HAE + gn;
                    size_t oB = (size_t)(r+8)*HAE + gn;
                    out0[oA]   = sp_(C[mi][ni][0] + b0v);
                    out0[oA+1] = sp_(C[mi][ni][1] + b1v);
                    out0[oB]   = sp_(C[mi][ni][2] + b0v);
                    out0[oB+1] = sp_(C[mi][ni][3] + b1v);
                }
            }
        }
    } else if (MODE == 7){
        #pragma unroll
        for (int mi = 0; mi < 2; mi++){
            const int r = m0 + r0 + mi*16 + g;
            #pragma unroll
            for (int ni = 0; ni < 8; ni++){
                const int gn = c0 + ni*8 + 2*ti;
                float b0v = bias[gn], b1v = bias[gn+1];
                float v00 = C[mi][ni][0] + b0v, v01 = C[mi][ni][1] + b1v;
                float v10 = C[mi][ni][2] + b0v, v11 = C[mi][ni][3] + b1v;
                size_t oA = (size_t)r*HAE + gn;
                size_t oB = (size_t)(r+8)*HAE + gn;
                out0[oA]   = sp_(v00); out0[oA+1] = sp_(v01);
                out0[oB]   = sp_(v10); out0[oB+1] = sp_(v11);
                *reinterpret_cast<__nv_bfloat162*>(&g_d2b[oA]) =
                    __floats2bfloat162_rn(sig_(v00), sig_(v01));
                *reinterpret_cast<__nv_bfloat162*>(&g_d2b[oB]) =
                    __floats2bfloat162_rn(sig_(v10), sig_(v11));
            }
        }
    } else if (MODE == 1){
        float loc = 0.f;
        #pragma unroll
        for (int mi = 0; mi < 2; mi++){
            const int r = m0 + r0 + mi*16 + g;
            #pragma unroll
            for (int ni = 0; ni < 8; ni++){
                const int gn = n0 + c0 + ni*8 + 2*ti;
                if (gn < N){
                    float b0v = bias[gn], b1v = bias[gn+1];
                    float d0 = aux[(size_t)r*s_aux + gn]       - (C[mi][ni][0] + b0v);
                    float d1 = aux[(size_t)r*s_aux + gn + 1]   - (C[mi][ni][1] + b1v);
                    float d2 = aux[(size_t)(r+8)*s_aux + gn]   - (C[mi][ni][2] + b0v);
                    float d3 = aux[(size_t)(r+8)*s_aux + gn+1] - (C[mi][ni][3] + b1v);
                    loc += d0*d0 + d1*d1 + d2*d2 + d3*d3;
                }
            }
        }
        red[t] = loc; __syncthreads();
        for (int st = 128; st > 0; st >>= 1){ if (t < st) red[t] += red[t+st]; __syncthreads(); }
        if (t == 0) atomicAdd(accd, (double)red[0]);
    } else { // MODE 6
        #pragma unroll
        for (int mi = 0; mi < 2; mi++){
            const int r = m0 + r0 + mi*16 + g;
            #pragma unroll
            for (int ni = 0; ni < 8; ni++){
                const int gn = n0 + c0 + ni*8 + 2*ti;
                if (gn < N){
                    atomicAdd(&out0[(size_t)r*HAE + gn],       C[mi][ni][0]);
                    atomicAdd(&out0[(size_t)r*HAE + gn + 1],   C[mi][ni][1]);
                    atomicAdd(&out0[(size_t)(r+8)*HAE + gn],   C[mi][ni][2]);
                    atomicAdd(&out0[(size_t)(r+8)*HAE + gn+1], C[mi][ni][3]);
                }
            }
        }
    }
}

template<int MODE, int PREC>
__global__ void __launch_bounds__(256)
tf32_gemm(const float* __restrict__ A, const float* __restrict__ Bm,
          int N, int K, int Kc,
          const float* __restrict__ bias, float* __restrict__ out0,
          const float* __restrict__ aux, int s_aux, double* accd,
          const float* __restrict__ pA){
    extern __shared__ float tsm[];
    __shared__ float red[256];
    tf32_body<MODE,PREC>(tsm, red, blockIdx.x, blockIdx.y, blockIdx.z,
                         A, Bm, N, K, Kc, bias, out0, aux, s_aux, accd, pA);
}

#define SM1 (2*128*TS*4)
#define SM3 (4*128*TS*4)

// ---------------- selection bodies ----------------
__device__ void selAB_body(int sbx,
       const float* __restrict__ qw, const float* __restrict__ qb,
       const float* __restrict__ sq,
       const float* __restrict__ sl1, const float* __restrict__ sg1,
       const float* __restrict__ sb1,
       const float* __restrict__ sl2, int iter){
    __shared__ float gsa[900], lsa[900];
    __shared__ float sel[2][30], h1s[2][64];
    __shared__ float sc8[8];
    __shared__ float h1f[128];
    int t = threadIdx.x;
    qw  += iter*900;  qb  += iter*30;   sq  += iter*60;
    sl1 += iter*2*64*30; sg1 += iter*128; sb1 += iter*128;
    for (int i = t; i < 900; i += 256) gsa[i] = g_zTz[i] / fmaxf(g_az[i], 1e-5f);
    __syncthreads();
    for (int idx = t; idx < 900; idx += 256){
        int i = idx / 30, j = idx % 30;
        float s = qb[j];
        #pragma unroll
        for (int k = 0; k < 30; k++) s += gsa[i*30+k]*qw[j*30+k];
        lsa[idx] = s;
    }
    __syncthreads();
    if (t < 60){
        int h = t / 30, i = t % 30;
        float s = 0.f;
        #pragma unroll
        for (int j = 0; j < 30; j++) s += lsa[i*30+j]*sq[h*30+j];
        sel[h][i] = s;
    }
    __syncthreads();
    if (t < 128){
        int h = t >> 6, o = t & 63;
        float s = 0.f;
        #pragma unroll
        for (int l = 0; l < 30; l++) s += sl1[(h*64+o)*30+l]*sel[h][l];
        h1s[h][o] = s;
    }
    __syncthreads();
    if (t < 2){
        float m = 0.f;
        for (int o = 0; o < 64; o++) m += h1s[t][o];
        m *= (1.f/64.f);
        float v = 0.f;
        for (int o = 0; o < 64; o++){ float d = h1s[t][o]-m; v += d*d; }
        v *= (1.f/64.f);
        sc8[t*2] = m; sc8[t*2+1] = rsqrtf(v + 1e-5f);
    }
    __syncthreads();
    if (t < 128){
        int h = t >> 6, o = t & 63;
        h1f[t] = sp_((h1s[h][o]-sc8[h*2])*sc8[h*2+1]*sg1[h*64+o] + sb1[h*64+o]);
    }
    __syncthreads();
    int w = sbx*8 + (t >> 5);
    int lane = t & 31;
    if (w >= Hh*SZv) return;
    int h = w / SZv, s = w % SZv;
    const float* wp = &sl2[((size_t)iter*Hh*SZv + w)*64];
    float a = wp[lane]*h1f[h*64+lane] + wp[lane+32]*h1f[h*64+lane+32];
    #pragma unroll
    for (int o = 16; o > 0; o >>= 1) a += __shfl_down_sync(0xffffffffu, a, o);
    if (lane == 0) g_buf[h*SZv + s] = a;
}

__device__ void selC_body(const float* __restrict__ sg2, const float* __restrict__ sb2,
      const float* __restrict__ son, int iter){
    __shared__ float buf[2][SZv];
    __shared__ float redc[256];
    int t = threadIdx.x;
    sg2 += iter*2*SZv; sb2 += iter*2*SZv;
    son += iter*2*2*SZv;
    for (int i = t; i < 2*SZv; i += 256) buf[i/SZv][i%SZv] = g_buf[i];
    __syncthreads();
    for (int h = 0; h < 2; h++){
        float s = 0.f, ss = 0.f;
        for (int i = t; i < SZv; i += 256){ float v = buf[h][i]; s += v; ss += v*v; }
        s  = blk_reduce(s, redc, t);
        ss = blk_reduce(ss, redc, t);
        float mean = s*(1.f/SZv);
        float var  = ss*(1.f/SZv) - mean*mean;
        float rstd = rsqrtf(var + 1e-5f);
        float mx = -1e30f;
        for (int i = t; i < SZv; i += 256){
            float v = (buf[h][i]-mean)*rstd*sg2[h*SZv+i] + sb2[h*SZv+i];
            buf[h][i] = v;
            mx = fmaxf(mx, v);
        }
        mx = blk_reduce_max(mx, redc, t);
        float se = 0.f;
        for (int i = t; i < SZv; i += 256){
            float e = expf(buf[h][i]-mx);
            buf[h][i] = e;
            se += e;
        }
        se = blk_reduce(se, redc, t);
        float inv = 1.f/se;
        for (int i = t; i < SZv; i += 256) buf[h][i] *= inv;
        __syncthreads();
    }
    float d0 = 0.f, d1 = 0.f;
    for (int s = t; s < SZv; s += 256){
        float il = g_l2[s*2]*g_l2[s*2+1];
        d0 += son[s]*il + son[SZv+s]*buf[0][s];
        d1 += son[2*SZv+s]*il + son[2*SZv+SZv+s]*buf[1][s];
    }
    d0 = blk_reduce(d0, redc, t);
    d1 = blk_reduce(d1, redc, t);
    float on0 = sig_(d0), on1 = sig_(d1);
    float e00 = 0.f, e01 = 0.f, e10 = 0.f, e11 = 0.f;
    for (int s = t; s < SZv; s += 256){
        float o0 = on0*buf[0][s], o1 = on1*buf[1][s];
        float sc0 = o0*g_scalarT[(iter*SZv+s)*2+0];
        float sc1 = o1*g_scalarT[(iter*SZv+s)*2+1];
        if (fabsf(sc0) <= 1e-14f) sc0 = 1e-14f;
        if (fabsf(sc1) <= 1e-14f) sc1 = 1e-14f;
        g_scaled[s*2]   = sc0;
        g_scaled[s*2+1] = sc1;
        float l20 = fmaxf(o0, 1e-14f), l21 = fmaxf(o1, 1e-14f);
        g_l2[s*2] = l20; g_l2[s*2+1] = l21;
        float lg0 = logf(l20 + 1e-5f), lg1 = logf(l21 + 1e-5f);
        e00 += l20*lg0; e01 += l20*lg1;
        e10 += l21*lg0; e11 += l21*lg1;
    }
    e00 = blk_reduce(e00, redc, t);
    e01 = blk_reduce(e01, redc, t);
    e10 = blk_reduce(e10, redc, t);
    e11 = blk_reduce(e11, redc, t);
    if (t == 0){
        float g00 = -e00, g01 = -e01, g10 = -e10, g11 = -e11;
        float g = 0.01f*0.5f*(g00+g11) - 0.25f*(g01+g10);
        g_comp += (double)g;
    }
}

// ---- merged: dec2 (16 blocks) || sel_AB (280 blocks) ----
__global__ void __launch_bounds__(256)
dec2_selAB(const float* __restrict__ dw2, const float* __restrict__ db2,
           const float* __restrict__ qw, const float* __restrict__ qb,
           const float* __restrict__ sq,
           const float* __restrict__ sl1, const float* __restrict__ sg1,
           const float* __restrict__ sb1,
           const float* __restrict__ sl2, int iter){
    extern __shared__ float tsm[];
    __shared__ float red[256];
    if (blockIdx.x < 16){
        tf32_body<5,1>(tsm, red, blockIdx.x, 0, 0,
                       g_dh1, dw2, HAE, HAE, HAE, db2, g_dh2,
                       nullptr, 0, nullptr, nullptr);
    } else {
        selAB_body(blockIdx.x - 16, qw, qb, sq, sl1, sg1, sb1, sl2, iter);
    }
}

// ---- merged: dec3/mse (144 blocks) || sel_C (1 block) ----
__global__ void __launch_bounds__(256)
dec3_selC(const float* __restrict__ dw3, const float* __restrict__ db3,
          const float* __restrict__ sg2, const float* __restrict__ sb2,
          const float* __restrict__ son, int iter, double* accd){
    extern __shared__ float tsm[];
    __shared__ float red[256];
    if (blockIdx.x < 144){
        tf32_body<1,1>(tsm, red, blockIdx.x & 15, blockIdx.x >> 4, 0,
                       g_dh2, dw3, SZv, HAE, HAE, db3, nullptr,
                       g_xn, SZv, accd, nullptr);
    } else {
        selC_body(sg2, sb2, son, iter);
    }
}

// ---------------- setup ----------------
__global__ void setup_k(const float* __restrict__ ew3, const float* __restrict__ ew2,
                        const float* __restrict__ ssc){
    int bid = blockIdx.x, t = threadIdx.x;
    if (bid < 1920){
        int idx = bid*256 + t;
        int bb = idx & 127;
        int n  = idx >> 7;
        int l  = n >> 7;
        int a  = n & 127;
        g_Vb[idx] = __float2bfloat16(ew3[l*HAE + bb] * ew2[bb*HAE + a]);
    } else if (bid < 1984){
        int t2 = (bid - 1920)*256 + t;
        if (t2 < SZv*Hh) g_l2[t2] = 0.5f;
        if (t2 < HAE*HAE) g_G1[t2] = 0.f;
        if (t2 == 0) g_comp = 0.0;
        if (t2 == 1){ g_mse = 0.0; g_jsum = 0.0; }
        if (t2 < NTRI){
            int rem = t2, i = 0;
            while (rem >= 32 - i){ rem -= 32 - i; i++; }
            g_iu0[t2] = i; g_iu1[t2] = i + rem;
        }
    } else {
        int gid = (bid - 1984)*256 + t;
        int w = gid >> 5, lane = gid & 31;
        if (w >= Dd*Hh*SZv) return;
        int i = w / (Hh*SZv);
        int rem = w % (Hh*SZv);
        int h = rem / SZv;
        int s = rem % SZv;
        const float* row = &ssc[(((size_t)(i*Hh+h)*SZv)+s)*SZv];
        float a = 0.f;
        for (int k = lane; k < SZv; k += 32) a += row[k];
        #pragma unroll
        for (int o = 16; o > 0; o >>= 1) a += __shfl_down_sync(0xffffffffu, a, o);
        if (lane == 0) g_scalarT[(i*SZv+s)*Hh + h] = a;
    }
}

__global__ void cvt_G1(){
    int t = blockIdx.x*256 + threadIdx.x;
    if (t < HAE*HAE) g_G1b[t] = __float2bfloat16(g_G1[t]);
}

// ---------------- raw / groupnorm (+ zero + out-dot) --------
__global__ void __launch_bounds__(256)
build_raw_fused(const float* __restrict__ x, const float* __restrict__ ln_g,
                const float* __restrict__ ln_b, int do_out){
    __shared__ float nx[32];
    __shared__ float rw[SZv];
    __shared__ float sc[SZv*2];
    __shared__ float redA[256], redB[256];
    int b = blockIdx.x, t = threadIdx.x;
    int gid = b*256 + t;
    if (gid < Bb*HAE) g_accE[gid] = 0.f;
    if (gid < Lv*Lv){ g_zTz[gid] = 0.f; g_az[gid] = 0.f; }

    float s0 = 0.f, s1 = 0.f;
    if (do_out){
        for (int i = t; i < SZv*2; i += 256) sc[i] = g_scaled[i];
        __syncthreads();
        const float* rwg = &g_raw[(size_t)b*SZv];
        for (int i = t; i < SZv; i += 256){
            float v = rwg[i];
            s0 += v*sc[i*2];
            s1 += v*sc[i*2+1];
        }
        s0 = blk_reduce(s0, redA, t);
        s1 = blk_reduce(s1, redA, t);
    }
    if (t < NIi) nx[t] = x[b*NIi + t];
    else if (t == NIi)   nx[t] = s0;
    else if (t == NIi+1) nx[t] = s1;
    __syncthreads();
    float s = 0.f, ss = 0.f;
    for (int idx = t; idx < SZv; idx += 256){
        float v;
        if (idx < NTRI){
            int i = g_iu0[idx], j = g_iu1[idx];
            v = (i == j) ? nx[i] : nx[i] + nx[j];
        } else if (idx < 2*NTRI){
            int k = idx - NTRI;
            v = nx[g_iu0[k]] * nx[g_iu1[k]];
        } else if (idx < 2*NTRI + 32){
            v = sinf(nx[idx - 2*NTRI]);
        } else {
            v = cosf(nx[idx - 2*NTRI - 32]);
        }
        rw[idx] = v; s += v; ss += v*v;
    }
    redA[t] = s; redB[t] = ss; __syncthreads();
    for (int st = 128; st > 0; st >>= 1){
        if (t < st){ redA[t] += redA[t+st]; redB[t] += redB[t+st]; }
        __syncthreads();
    }
    float mean = redA[0] / SZv;
    float var  = redB[0] / SZv - mean*mean;
    float rstd = rsqrtf(var + 1e-5f);
    for (int idx = t; idx < SZv; idx += 256){
        float v = rw[idx];
        g_raw[(size_t)b*SZv + idx] = v;
        g_xn [(size_t)b*SZv + idx] = (v - mean)*rstd*ln_g[idx] + ln_b[idx];
    }
}

// ---------------- final ----------------
__global__ void __launch_bounds__(256)
finalize_dot(float* __restrict__ out){
    __shared__ float sc[SZv];
    int t = threadIdx.x;
    for (int i = t; i < SZv; i += 256) sc[i] = g_scaled[i*2] + g_scaled[i*2+1];
    __syncthreads();
    int warp = t >> 5, lane = t & 31;
    int b = blockIdx.x*8 + warp;
    const float* rw = &g_raw[(size_t)b*SZv];
    float s = 0.f;
    for (int i = lane; i < SZv; i += 32) s += rw[i]*sc[i];
    #pragma unroll
    for (int o = 16; o > 0; o >>= 1) s += __shfl_down_sync(0xffffffffu, s, o);
    if (lane == 0) out[b] = s;
    if (blockIdx.x == 0 && t == 0){
        double cst = g_mse/((double)Bb*(double)SZv)
                   + g_jsum/((double)Lv*(double)Bb*(double)SZv);
        out[Bb] = (float)(g_comp + cst);
    }
}

// ---------------- host ----------------
extern "C" void kernel_launch(void* const* d_in, const int* in_sizes, int n_in,
                              void* d_out, int out_size) {
    const float* x    = (const float*)d_in[0];
    const float* ln_g = (const float*)d_in[1];
    const float* ln_b = (const float*)d_in[2];
    const float* ew1  = (const float*)d_in[3];
    const float* eb1  = (const float*)d_in[4];
    const float* ew2  = (const float*)d_in[5];
    const float* eb2  = (const float*)d_in[6];
    const float* ew3  = (const float*)d_in[7];
    const float* eb3  = (const float*)d_in[8];
    const float* dw1  = (const float*)d_in[9];
    const float* db1  = (const float*)d_in[10];
    const float* dw2  = (const float*)d_in[11];
    const float* db2  = (const float*)d_in[12];
    const float* dw3  = (const float*)d_in[13];
    const float* db3  = (const float*)d_in[14];
    const float* qw   = (const float*)d_in[15];
    const float* qb   = (const float*)d_in[16];
    const float* sq   = (const float*)d_in[17];
    const float* sl1  = (const float*)d_in[18];
    const float* sg1  = (const float*)d_in[19];
    const float* sb1  = (const float*)d_in[20];
    const float* sl2  = (const float*)d_in[21];
    const float* sg2  = (const float*)d_in[22];
    const float* sb2  = (const float*)d_in[23];
    const float* ssc  = (const float*)d_in[24];
    const float* son  = (const float*)d_in[25];
    float* out = (float*)d_out;

    float *pXn, *pH2, *pG1, *pAccE;
    double *pMse;
    cudaGetSymbolAddress((void**)&pXn,  g_xn);
    cudaGetSymbolAddress((void**)&pH2,  g_h2e);
    cudaGetSymbolAddress((void**)&pG1,  g_G1);
    cudaGetSymbolAddress((void**)&pAccE,g_accE);
    cudaGetSymbolAddress((void**)&pMse, g_mse);

    cudaFuncSetAttribute(hmma_z, cudaFuncAttributeMaxDynamicSharedMemorySize, HMMA_SMEM);
    cudaFuncSetAttribute(dec2_selAB, cudaFuncAttributeMaxDynamicSharedMemorySize, SM3);
    cudaFuncSetAttribute(dec3_selC, cudaFuncAttributeMaxDynamicSharedMemorySize, SM3);

    setup_k<<<2544,256>>>(ew3, ew2, ssc);
    tf32_gemm<6,0><<<dim3(1,1,35),256,SM1>>>(ew1, ew1, HAE, SZv, 32,
        nullptr, pG1, nullptr, 0, nullptr, nullptr);
    cvt_G1<<<64,256>>>();

    for (int iter = 0; iter < Dd; iter++){
        build_raw_fused<<<Bb,256>>>(x, ln_g, ln_b, iter > 0 ? 1 : 0);
        // enc1: xn @ ew1^T -> accE (split-K atomics)
        tf32_gemm<6,1><<<dim3(16,1,7),256,SM3>>>(pXn, ew1, HAE, SZv, 160,
            nullptr, pAccE, nullptr, 0, nullptr, nullptr);
        // enc2 (MODE 7): A-staging applies enc1 epi; epilogue h2e + d2b
        tf32_gemm<7,1><<<dim3(16,1,1),256,SM3>>>(pAccE, ew2, HAE, HAE, HAE,
            eb2, pH2, nullptr, 0, nullptr, eb1);
        // merged: TM+JQ (480 blocks) || z+zstats+dec1 (128 blocks)
        hmma_z<<<608, 256, HMMA_SMEM>>>(ew3, eb3, dw1, db1);
        // merged: dec2 (16) || sel_AB (280)
        dec2_selAB<<<296, 256, SM3>>>(dw2, db2, qw, qb, sq, sl1, sg1, sb1, sl2, iter);
        // merged: dec3/mse (144) || sel_C (1)
        dec3_selC<<<145, 256, SM3>>>(dw3, db3, sg2, sb2, son, iter, pMse);
    }
    finalize_dot<<<Bb/8,256>>>(out);
}